// round 4
// baseline (speedup 1.0000x reference)
#include <cuda_runtime.h>
#include <cuda_bf16.h>
#include <math.h>

// ---------------- problem constants ----------------
#define T_   2048
#define D_   1024
#define NH   16
#define NKV  4
#define HD_  64
#define F_   2048
#define NE   8
#define NL   2
#define NV   32000
#define CH   512
#define NCK  4            // T_/CH

#define OUT_TASK   (T_*(size_t)NV)     // 65,536,000
#define OUT_EVAL   (OUT_TASK + 16)
#define OUT_AUX    (OUT_EVAL + 8)

// ---------------- scratch (device globals; no allocation) ----------------
__device__ float g_h   [(size_t)T_*D_];
__device__ float g_xn  [(size_t)T_*D_];
__device__ float g_q   [(size_t)T_*NH*HD_];
__device__ float g_k   [(size_t)T_*NKV*HD_];
__device__ float g_v   [(size_t)T_*NKV*HD_];
__device__ float g_sc  [(size_t)NCK*NH*CH*CH];      // 67 MB scores
__device__ float g_attn[(size_t)T_*D_];
__device__ float g_probs[(size_t)T_*NE];
__device__ int   g_ti  [T_*2];
__device__ float g_tw  [T_*2];
__device__ int   g_cnt [NE];
__device__ int   g_rows[NE*T_];
__device__ int   g_slot[T_*2];
__device__ float g_hb  [(size_t)NE*T_*F_];          // 128 MB MoE hidden
__device__ float g_yb  [(size_t)NE*T_*D_];          // 64 MB MoE expert out
__device__ float g_aux [1];
__device__ float g_xm  [D_];

// ---------------- helpers ----------------
__device__ __forceinline__ void fma4x4(float (&acc)[4][4], float4 a, float4 b) {
    acc[0][0] += a.x*b.x; acc[0][1] += a.x*b.y; acc[0][2] += a.x*b.z; acc[0][3] += a.x*b.w;
    acc[1][0] += a.y*b.x; acc[1][1] += a.y*b.y; acc[1][2] += a.y*b.z; acc[1][3] += a.y*b.w;
    acc[2][0] += a.z*b.x; acc[2][1] += a.z*b.y; acc[2][2] += a.z*b.z; acc[2][3] += a.z*b.w;
    acc[3][0] += a.w*b.x; acc[3][1] += a.w*b.y; acc[3][2] += a.w*b.z; acc[3][3] += a.w*b.w;
}
__device__ __forceinline__ void storeT(float (&S)[16][64], int acol, int arow, float4 v) {
    S[acol+0][arow] = v.x; S[acol+1][arow] = v.y; S[acol+2][arow] = v.z; S[acol+3][arow] = v.w;
}

// ---------------- tiny kernels ----------------
__global__ void k_zero_aux() { if (threadIdx.x == 0) g_aux[0] = 0.f; }
__global__ void k_zero_cnt() { if (threadIdx.x < NE) g_cnt[threadIdx.x] = 0; }

__global__ void k_embed(const int* __restrict__ ids, const float* __restrict__ ew) {
    int t = blockIdx.x;
    size_t r = (size_t)ids[t] * D_;
    for (int d = threadIdx.x; d < D_; d += blockDim.x)
        g_h[(size_t)t*D_ + d] = ew[r + d];
}

__global__ void k_rms(const float* __restrict__ x, const float* __restrict__ w,
                      float* __restrict__ out) {
    int t = blockIdx.x, tid = threadIdx.x;
    __shared__ float sh[256];
    const float* xr = x + (size_t)t*D_;
    float s = 0.f;
    for (int d = tid; d < D_; d += 256) { float v = xr[d]; s += v*v; }
    sh[tid] = s; __syncthreads();
    for (int o = 128; o > 0; o >>= 1) { if (tid < o) sh[tid] += sh[tid+o]; __syncthreads(); }
    float scale = rsqrtf(sh[0] / (float)D_ + 1e-6f);
    float* orow = out + (size_t)t*D_;
    for (int d = tid; d < D_; d += 256) orow[d] = w[d] * xr[d] * scale;
}

// ---------------- generic 64x64x16 SGEMM (NN), mode 0: C=AB, 1: C+=AB ----------------
__global__ void k_sgemm(const float* __restrict__ A, const float* __restrict__ B,
                        float* __restrict__ C, int M, int N, int K,
                        int lda, int ldb, int ldc, int mode) {
    __shared__ __align__(16) float As[16][64];
    __shared__ __align__(16) float Bs[16][64];
    int bn = blockIdx.x * 64, bm = blockIdx.y * 64;
    int tid = threadIdx.x, tx = tid & 15, ty = tid >> 4;
    int arow = tid >> 2, acol = (tid & 3) * 4;
    int brow = tid >> 4, bcol = (tid & 15) * 4;
    float acc[4][4] = {};
    int gr = bm + arow;
    for (int k0 = 0; k0 < K; k0 += 16) {
        float4 av = make_float4(0.f,0.f,0.f,0.f);
        if (gr < M) av = *(const float4*)(A + (size_t)gr*lda + k0 + acol);
        storeT(As, acol, arow, av);
        *(float4*)&Bs[brow][bcol] = *(const float4*)(B + (size_t)(k0+brow)*ldb + bn + bcol);
        __syncthreads();
        #pragma unroll
        for (int k = 0; k < 16; k++) {
            float4 a = *(float4*)&As[k][ty*4];
            float4 b = *(float4*)&Bs[k][tx*4];
            fma4x4(acc, a, b);
        }
        __syncthreads();
    }
    #pragma unroll
    for (int i = 0; i < 4; i++) {
        int r = bm + ty*4 + i;
        if (r >= M) continue;
        #pragma unroll
        for (int j = 0; j < 4; j++) {
            int c = bn + tx*4 + j;
            if (c >= N) continue;
            size_t idx = (size_t)r*ldc + c;
            if (mode) C[idx] += acc[i][j]; else C[idx] = acc[i][j];
        }
    }
}

// ---------------- RoPE on q (16 heads) and k (4 kv heads), per chunk position ----------------
__global__ void k_rope() {
    int t = blockIdx.x, tid = threadIdx.x;
    float p = (float)(t & (CH-1));
    if (tid < NH*32) {
        int h = tid >> 5, i = tid & 31;
        float ang = p * powf(1000000.0f, -(float)i/32.0f);
        float c = cosf(ang), s = sinf(ang);
        float* q = g_q + (size_t)t*D_ + h*64 + 2*i;
        float x1 = q[0], x2 = q[1];
        q[0] = x1*c - x2*s; q[1] = x1*s + x2*c;
    }
    if (tid < NKV*32) {
        int h = tid >> 5, i = tid & 31;
        float ang = p * powf(1000000.0f, -(float)i/32.0f);
        float c = cosf(ang), s = sinf(ang);
        float* kk = g_k + (size_t)t*(NKV*HD_) + h*64 + 2*i;
        float x1 = kk[0], x2 = kk[1];
        kk[0] = x1*c - x2*s; kk[1] = x1*s + x2*c;
    }
}

// ---------------- scores: S = scale * Q Kt, causal-masked; per (chunk,head) ----------------
__global__ void k_scores() {
    int b = blockIdx.z, chunk = b >> 4, head = b & 15, kvh = head >> 2;
    int qt = blockIdx.y, kt = blockIdx.x;
    const float* Q  = g_q + (size_t)chunk*CH*D_ + head*64;
    const float* Kp = g_k + (size_t)chunk*CH*(NKV*HD_) + kvh*64;
    __shared__ __align__(16) float As[16][64];
    __shared__ __align__(16) float Bs[16][64];
    int tid = threadIdx.x, tx = tid & 15, ty = tid >> 4;
    int arow = tid >> 2, acol = (tid & 3) * 4;
    float acc[4][4] = {};
    for (int k0 = 0; k0 < 64; k0 += 16) {
        float4 av = *(const float4*)(Q  + (size_t)(qt*64+arow)*D_         + k0 + acol);
        float4 bv = *(const float4*)(Kp + (size_t)(kt*64+arow)*(NKV*HD_) + k0 + acol);
        storeT(As, acol, arow, av);
        storeT(Bs, acol, arow, bv);
        __syncthreads();
        #pragma unroll
        for (int k = 0; k < 16; k++) {
            float4 a = *(float4*)&As[k][ty*4];
            float4 bb = *(float4*)&Bs[k][tx*4];
            fma4x4(acc, a, bb);
        }
        __syncthreads();
    }
    float* S = g_sc + (size_t)b*CH*CH;
    #pragma unroll
    for (int i = 0; i < 4; i++) {
        int qg = qt*64 + ty*4 + i;
        #pragma unroll
        for (int j = 0; j < 4; j++) {
            int kg = kt*64 + tx*4 + j;
            float v = acc[i][j] * 0.125f;
            if (kg > qg) v = -1e30f;
            S[(size_t)qg*CH + kg] = v;
        }
    }
}

// ---------------- row softmax over 512 ----------------
__global__ void k_softmax() {
    size_t row = blockIdx.x;
    int tid = threadIdx.x;
    float* r = g_sc + row*CH;
    __shared__ float sh[256];
    float v0 = r[tid], v1 = r[tid+256];
    sh[tid] = fmaxf(v0, v1); __syncthreads();
    for (int o = 128; o > 0; o >>= 1) { if (tid < o) sh[tid] = fmaxf(sh[tid], sh[tid+o]); __syncthreads(); }
    float m = sh[0]; __syncthreads();
    float e0 = expf(v0 - m), e1 = expf(v1 - m);
    sh[tid] = e0 + e1; __syncthreads();
    for (int o = 128; o > 0; o >>= 1) { if (tid < o) sh[tid] += sh[tid+o]; __syncthreads(); }
    float inv = 1.f / sh[0];
    r[tid] = e0*inv; r[tid+256] = e1*inv;
}

// ---------------- O = P V  per (chunk,head) ----------------
__global__ void k_av() {
    int b = blockIdx.z, chunk = b >> 4, head = b & 15, kvh = head >> 2;
    const float* A = g_sc + (size_t)b*CH*CH;                         // lda = 512
    const float* B = g_v + (size_t)chunk*CH*(NKV*HD_) + kvh*64;      // ldb = 256
    float* C = g_attn + (size_t)chunk*CH*D_ + head*64;               // ldc = 1024
    int bm = blockIdx.y * 64;
    __shared__ __align__(16) float As[16][64];
    __shared__ __align__(16) float Bs[16][64];
    int tid = threadIdx.x, tx = tid & 15, ty = tid >> 4;
    int arow = tid >> 2, acol = (tid & 3) * 4;
    int brow = tid >> 4, bcol = (tid & 15) * 4;
    float acc[4][4] = {};
    for (int k0 = 0; k0 < CH; k0 += 16) {
        float4 av = *(const float4*)(A + (size_t)(bm+arow)*CH + k0 + acol);
        storeT(As, acol, arow, av);
        *(float4*)&Bs[brow][bcol] = *(const float4*)(B + (size_t)(k0+brow)*(NKV*HD_) + bcol);
        __syncthreads();
        #pragma unroll
        for (int k = 0; k < 16; k++) {
            float4 a = *(float4*)&As[k][ty*4];
            float4 bb = *(float4*)&Bs[k][tx*4];
            fma4x4(acc, a, bb);
        }
        __syncthreads();
    }
    #pragma unroll
    for (int i = 0; i < 4; i++)
        #pragma unroll
        for (int j = 0; j < 4; j++)
            C[(size_t)(bm + ty*4 + i)*D_ + tx*4 + j] = acc[i][j];
}

// ---------------- router: softmax over 8 experts, top-2 (warp per token) ----------------
__global__ void k_router(const float* __restrict__ rw) {
    int tid = threadIdx.x, lane = tid & 31, w = tid >> 5;
    int t = blockIdx.x*8 + w;
    const float* xr = g_xn + (size_t)t*D_;
    float acc[NE] = {};
    for (int dd = 0; dd < 32; dd++) {
        int d = dd*32 + lane;
        float x = xr[d];
        const float* rr = rw + (size_t)d*NE;
        #pragma unroll
        for (int e = 0; e < NE; e++) acc[e] += x * rr[e];
    }
    #pragma unroll
    for (int e = 0; e < NE; e++)
        for (int o = 16; o > 0; o >>= 1) acc[e] += __shfl_down_sync(0xffffffffu, acc[e], o);
    if (lane == 0) {
        float m = acc[0];
        #pragma unroll
        for (int e = 1; e < NE; e++) m = fmaxf(m, acc[e]);
        float p[NE], s = 0.f;
        #pragma unroll
        for (int e = 0; e < NE; e++) { p[e] = expf(acc[e]-m); s += p[e]; }
        float inv = 1.f/s;
        #pragma unroll
        for (int e = 0; e < NE; e++) { p[e] *= inv; g_probs[(size_t)t*NE + e] = p[e]; }
        int i0 = 0;
        #pragma unroll
        for (int e = 1; e < NE; e++) if (p[e] > p[i0]) i0 = e;
        int i1 = (i0 == 0) ? 1 : 0;
        #pragma unroll
        for (int e = 0; e < NE; e++) if (e != i0 && p[e] > p[i1]) i1 = e;
        float ws = p[i0] + p[i1];
        g_ti[2*t] = i0; g_ti[2*t+1] = i1;
        g_tw[2*t] = p[i0]/ws; g_tw[2*t+1] = p[i1]/ws;
    }
}

// ---------------- deterministic aux accumulation (single block) ----------------
__global__ void k_aux() {
    int tid = threadIdx.x;
    __shared__ float sh[256];
    __shared__ float totp[NE], totc[NE];
    float ps[NE] = {}, cs[NE] = {};
    for (int t = tid; t < T_; t += 256) {
        cs[g_ti[2*t]] += 1.f;
        #pragma unroll
        for (int e = 0; e < NE; e++) ps[e] += g_probs[(size_t)t*NE + e];
    }
    for (int e = 0; e < NE; e++) {
        sh[tid] = ps[e]; __syncthreads();
        for (int o = 128; o > 0; o >>= 1) { if (tid < o) sh[tid] += sh[tid+o]; __syncthreads(); }
        if (tid == 0) totp[e] = sh[0];
        __syncthreads();
        sh[tid] = cs[e]; __syncthreads();
        for (int o = 128; o > 0; o >>= 1) { if (tid < o) sh[tid] += sh[tid+o]; __syncthreads(); }
        if (tid == 0) totc[e] = sh[0];
        __syncthreads();
    }
    if (tid == 0) {
        float a = 0.f;
        for (int e = 0; e < NE; e++) a += (totc[e]/(float)T_) * (totp[e]/(float)T_);
        g_aux[0] += (float)NE * a;
    }
}

__global__ void k_bucket() {
    int t = blockIdx.x*256 + threadIdx.x;
    if (t >= T_) return;
    for (int j = 0; j < 2; j++) {
        int e = g_ti[2*t + j];
        int pos = atomicAdd(&g_cnt[e], 1);
        g_rows[e*T_ + pos] = t;
        g_slot[2*t + j] = e*T_ + pos;
    }
}

// ---------------- MoE up: H = silu(Xg W1) * (Xg W3), gathered rows ----------------
__global__ void k_moe_up(const float* __restrict__ W1, const float* __restrict__ W3) {
    int e = blockIdx.y >> 5, rt = blockIdx.y & 31;
    int count = g_cnt[e];
    if (rt*64 >= count) return;
    const float* B1 = W1 + (size_t)e*D_*F_;
    const float* B3 = W3 + (size_t)e*D_*F_;
    int bn = blockIdx.x * 64;
    __shared__ __align__(16) float As[16][64];
    __shared__ __align__(16) float Bs1[16][64];
    __shared__ __align__(16) float Bs3[16][64];
    int tid = threadIdx.x, tx = tid & 15, ty = tid >> 4;
    int arow = tid >> 2, acol = (tid & 3) * 4;
    int brow = tid >> 4, bcol = (tid & 15) * 4;
    int gr = rt*64 + arow;
    int tok = (gr < count) ? g_rows[e*T_ + gr] : -1;
    float a1[4][4] = {}, a3[4][4] = {};
    for (int k0 = 0; k0 < D_; k0 += 16) {
        float4 av = make_float4(0.f,0.f,0.f,0.f);
        if (tok >= 0) av = *(const float4*)(g_xn + (size_t)tok*D_ + k0 + acol);
        storeT(As, acol, arow, av);
        size_t bidx = (size_t)(k0+brow)*F_ + bn + bcol;
        *(float4*)&Bs1[brow][bcol] = *(const float4*)(B1 + bidx);
        *(float4*)&Bs3[brow][bcol] = *(const float4*)(B3 + bidx);
        __syncthreads();
        #pragma unroll
        for (int k = 0; k < 16; k++) {
            float4 a  = *(float4*)&As[k][ty*4];
            float4 b1 = *(float4*)&Bs1[k][tx*4];
            float4 b3 = *(float4*)&Bs3[k][tx*4];
            fma4x4(a1, a, b1);
            fma4x4(a3, a, b3);
        }
        __syncthreads();
    }
    #pragma unroll
    for (int i = 0; i < 4; i++) {
        int r = rt*64 + ty*4 + i;
        if (r >= count) continue;
        #pragma unroll
        for (int j = 0; j < 4; j++) {
            int c = bn + tx*4 + j;
            float u = a1[i][j];
            float hv = (u / (1.f + expf(-u))) * a3[i][j];
            g_hb[((size_t)e*T_ + r)*F_ + c] = hv;
        }
    }
}

// ---------------- MoE down: Y = H W2 ----------------
__global__ void k_moe_dn(const float* __restrict__ W2) {
    int e = blockIdx.y >> 5, rt = blockIdx.y & 31;
    int count = g_cnt[e];
    if (rt*64 >= count) return;
    const float* B = W2 + (size_t)e*F_*D_;
    int bn = blockIdx.x * 64;
    __shared__ __align__(16) float As[16][64];
    __shared__ __align__(16) float Bs[16][64];
    int tid = threadIdx.x, tx = tid & 15, ty = tid >> 4;
    int arow = tid >> 2, acol = (tid & 3) * 4;
    int brow = tid >> 4, bcol = (tid & 15) * 4;
    int gr = rt*64 + arow;
    const float* Ar = g_hb + ((size_t)e*T_ + gr)*F_;
    bool valid = (gr < count);
    float acc[4][4] = {};
    for (int k0 = 0; k0 < F_; k0 += 16) {
        float4 av = make_float4(0.f,0.f,0.f,0.f);
        if (valid) av = *(const float4*)(Ar + k0 + acol);
        storeT(As, acol, arow, av);
        *(float4*)&Bs[brow][bcol] = *(const float4*)(B + (size_t)(k0+brow)*D_ + bn + bcol);
        __syncthreads();
        #pragma unroll
        for (int k = 0; k < 16; k++) {
            float4 a = *(float4*)&As[k][ty*4];
            float4 bb = *(float4*)&Bs[k][tx*4];
            fma4x4(acc, a, bb);
        }
        __syncthreads();
    }
    #pragma unroll
    for (int i = 0; i < 4; i++) {
        int r = rt*64 + ty*4 + i;
        if (r >= count) continue;
        #pragma unroll
        for (int j = 0; j < 4; j++)
            g_yb[((size_t)e*T_ + r)*D_ + bn + tx*4 + j] = acc[i][j];
    }
}

// ---------------- combine: h += w0*Y[slot0] + w1*Y[slot1] (deterministic) ----------------
__global__ void k_combine() {
    int t = blockIdx.x, tid = threadIdx.x;
    int s0 = g_slot[2*t], s1 = g_slot[2*t+1];
    float w0 = g_tw[2*t], w1 = g_tw[2*t+1];
    const float* y0 = g_yb + (size_t)s0*D_;
    const float* y1 = g_yb + (size_t)s1*D_;
    float* hr = g_h + (size_t)t*D_;
    for (int d = tid; d < D_; d += 256)
        hr[d] += w0*y0[d] + w1*y1[d];
}

// ---------------- final small heads ----------------
__global__ void k_task(const float* __restrict__ tw, const float* __restrict__ tb,
                       float* __restrict__ out) {
    int c = blockIdx.x, tid = threadIdx.x;
    __shared__ float sh[256];
    float s = 0.f;
    for (int d = tid; d < D_; d += 256) s += g_xn[d] * tw[(size_t)d*16 + c];
    sh[tid] = s; __syncthreads();
    for (int o = 128; o > 0; o >>= 1) { if (tid < o) sh[tid] += sh[tid+o]; __syncthreads(); }
    if (tid == 0) out[OUT_TASK + c] = sh[0] + tb[c];
}
__global__ void k_mean() {
    int d = blockIdx.x*256 + threadIdx.x;
    float s = 0.f;
    for (int t = 0; t < T_; t++) s += g_xn[(size_t)t*D_ + d];
    g_xm[d] = s / (float)T_;
}
__global__ void k_eval(const float* __restrict__ ew, const float* __restrict__ eb,
                       float* __restrict__ out) {
    int c = blockIdx.x, tid = threadIdx.x;
    __shared__ float sh[256];
    float s = 0.f;
    for (int d = tid; d < D_; d += 256) s += g_xm[d] * ew[(size_t)d*8 + c];
    sh[tid] = s; __syncthreads();
    for (int o = 128; o > 0; o >>= 1) { if (tid < o) sh[tid] += sh[tid+o]; __syncthreads(); }
    if (tid == 0) out[OUT_EVAL + c] = sh[0] + eb[c];
}
__global__ void k_auxw(float* __restrict__ out) { out[OUT_AUX] = g_aux[0]; }

// ---------------- launch ----------------
extern "C" void kernel_launch(void* const* d_in, const int* in_sizes, int n_in,
                              void* d_out, int out_size) {
    const int*   ids     = (const int*)  d_in[0];
    const float* embed_W = (const float*)d_in[1];
    const float* n1      = (const float*)d_in[2];
    const float* n2      = (const float*)d_in[3];
    const float* wq      = (const float*)d_in[4];
    const float* wk      = (const float*)d_in[5];
    const float* wv      = (const float*)d_in[6];
    const float* wo      = (const float*)d_in[7];
    const float* rw      = (const float*)d_in[8];
    const float* w1      = (const float*)d_in[9];
    const float* w3      = (const float*)d_in[10];
    const float* w2      = (const float*)d_in[11];
    const float* normf   = (const float*)d_in[12];
    const float* lm      = (const float*)d_in[13];
    const float* tw      = (const float*)d_in[14];
    const float* tb      = (const float*)d_in[15];
    const float* ew      = (const float*)d_in[16];
    const float* eb      = (const float*)d_in[17];
    float* out = (float*)d_out;

    float *p_h, *p_xn, *p_q, *p_k, *p_v, *p_attn;
    cudaGetSymbolAddress((void**)&p_h,    g_h);
    cudaGetSymbolAddress((void**)&p_xn,   g_xn);
    cudaGetSymbolAddress((void**)&p_q,    g_q);
    cudaGetSymbolAddress((void**)&p_k,    g_k);
    cudaGetSymbolAddress((void**)&p_v,    g_v);
    cudaGetSymbolAddress((void**)&p_attn, g_attn);

    k_zero_aux<<<1, 32>>>();
    k_embed<<<T_, 256>>>(ids, embed_W);

    for (int l = 0; l < NL; l++) {
        // ---- attention block ----
        k_rms<<<T_, 256>>>(p_h, n1 + (size_t)l*D_, p_xn);
        k_sgemm<<<dim3(D_/64, T_/64), 256>>>(p_xn, wq + (size_t)l*D_*D_,  p_q, T_, D_,  D_, D_, D_,  D_,  0);
        k_sgemm<<<dim3(256/64, T_/64), 256>>>(p_xn, wk + (size_t)l*D_*256, p_k, T_, 256, D_, D_, 256, 256, 0);
        k_sgemm<<<dim3(256/64, T_/64), 256>>>(p_xn, wv + (size_t)l*D_*256, p_v, T_, 256, D_, D_, 256, 256, 0);
        k_rope<<<T_, 512>>>();
        k_scores<<<dim3(8, 8, NCK*NH), 256>>>();
        k_softmax<<<NCK*NH*CH, 256>>>();
        k_av<<<dim3(1, 8, NCK*NH), 256>>>();
        k_sgemm<<<dim3(D_/64, T_/64), 256>>>(p_attn, wo + (size_t)l*D_*D_, p_h, T_, D_, D_, D_, D_, D_, 1);

        // ---- MoE block ----
        k_rms<<<T_, 256>>>(p_h, n2 + (size_t)l*D_, p_xn);
        k_router<<<T_/8, 256>>>(rw + (size_t)l*D_*NE);
        k_aux<<<1, 256>>>();
        k_zero_cnt<<<1, 32>>>();
        k_bucket<<<T_/256, 256>>>();
        k_moe_up<<<dim3(F_/64, NE*32), 256>>>(w1 + (size_t)l*NE*D_*F_, w3 + (size_t)l*NE*D_*F_);
        k_moe_dn<<<dim3(D_/64, NE*32), 256>>>(w2 + (size_t)l*NE*F_*D_);
        k_combine<<<T_, 256>>>();
    }

    // ---- final norm + heads ----
    k_rms<<<T_, 256>>>(p_h, normf, p_xn);
    k_sgemm<<<dim3(NV/64, T_/64), 256>>>(p_xn, lm, out, T_, NV, D_, D_, NV, NV, 0);
    k_task<<<16, 256>>>(tw, tb, out);
    k_mean<<<D_/256, 256>>>();
    k_eval<<<8, 256>>>(ew, eb, out);
    k_auxw<<<1, 1>>>(out);
}

// round 5
// speedup vs baseline: 1.0002x; 1.0002x over previous
#include <cuda_runtime.h>
#include <cuda_bf16.h>
#include <math.h>

// ---------------- problem constants ----------------
#define T_   2048
#define D_   1024
#define NH   16
#define NKV  4
#define HD_  64
#define F_   2048
#define NE   8
#define NL   2
#define NV   32000
#define CH   512
#define NCK  4            // T_/CH

#define OUT_TASK   (T_*(size_t)NV)     // 65,536,000
#define OUT_EVAL   (OUT_TASK + 16)
#define OUT_AUX    (OUT_EVAL + 8)

// ---------------- scratch (device globals; no allocation) ----------------
__device__ float g_h   [(size_t)T_*D_];
__device__ float g_xn  [(size_t)T_*D_];
__device__ float g_q   [(size_t)T_*NH*HD_];
__device__ float g_k   [(size_t)T_*NKV*HD_];
__device__ float g_v   [(size_t)T_*NKV*HD_];
__device__ float g_sc  [(size_t)NCK*NH*CH*CH];      // 67 MB scores
__device__ float g_attn[(size_t)T_*D_];
__device__ float g_probs[(size_t)T_*NE];
__device__ int   g_ti  [T_*2];
__device__ float g_tw  [T_*2];
__device__ int   g_cnt [NE];
__device__ int   g_rows[NE*T_];
__device__ int   g_slot[T_*2];
__device__ float g_hb  [(size_t)NE*T_*F_];          // 128 MB MoE hidden
__device__ float g_yb  [(size_t)NE*T_*D_];          // 64 MB MoE expert out
__device__ float g_aux [1];
__device__ float g_xm  [D_];

// ---------------- helpers ----------------
__device__ __forceinline__ void fma4x4(float (&acc)[4][4], float4 a, float4 b) {
    acc[0][0] += a.x*b.x; acc[0][1] += a.x*b.y; acc[0][2] += a.x*b.z; acc[0][3] += a.x*b.w;
    acc[1][0] += a.y*b.x; acc[1][1] += a.y*b.y; acc[1][2] += a.y*b.z; acc[1][3] += a.y*b.w;
    acc[2][0] += a.z*b.x; acc[2][1] += a.z*b.y; acc[2][2] += a.z*b.z; acc[2][3] += a.z*b.w;
    acc[3][0] += a.w*b.x; acc[3][1] += a.w*b.y; acc[3][2] += a.w*b.z; acc[3][3] += a.w*b.w;
}
__device__ __forceinline__ void storeT(float (&S)[16][64], int acol, int arow, float4 v) {
    S[acol+0][arow] = v.x; S[acol+1][arow] = v.y; S[acol+2][arow] = v.z; S[acol+3][arow] = v.w;
}

// ---------------- tiny kernels ----------------
__global__ void k_zero_aux() { if (threadIdx.x == 0) g_aux[0] = 0.f; }
__global__ void k_zero_cnt() { if (threadIdx.x < NE) g_cnt[threadIdx.x] = 0; }

__global__ void k_embed(const int* __restrict__ ids, const float* __restrict__ ew) {
    int t = blockIdx.x;
    size_t r = (size_t)ids[t] * D_;
    for (int d = threadIdx.x; d < D_; d += blockDim.x)
        g_h[(size_t)t*D_ + d] = ew[r + d];
}

__global__ void k_rms(const float* __restrict__ x, const float* __restrict__ w,
                      float* __restrict__ out) {
    int t = blockIdx.x, tid = threadIdx.x;
    __shared__ float sh[256];
    const float* xr = x + (size_t)t*D_;
    float s = 0.f;
    for (int d = tid; d < D_; d += 256) { float v = xr[d]; s += v*v; }
    sh[tid] = s; __syncthreads();
    for (int o = 128; o > 0; o >>= 1) { if (tid < o) sh[tid] += sh[tid+o]; __syncthreads(); }
    float scale = rsqrtf(sh[0] / (float)D_ + 1e-6f);
    float* orow = out + (size_t)t*D_;
    for (int d = tid; d < D_; d += 256) orow[d] = w[d] * xr[d] * scale;
}

// ---------------- generic 64x64x16 SGEMM (NN), mode 0: C=AB, 1: C+=AB ----------------
__global__ void k_sgemm(const float* __restrict__ A, const float* __restrict__ B,
                        float* __restrict__ C, int M, int N, int K,
                        int lda, int ldb, int ldc, int mode) {
    __shared__ __align__(16) float As[16][64];
    __shared__ __align__(16) float Bs[16][64];
    int bn = blockIdx.x * 64, bm = blockIdx.y * 64;
    int tid = threadIdx.x, tx = tid & 15, ty = tid >> 4;
    int arow = tid >> 2, acol = (tid & 3) * 4;
    int brow = tid >> 4, bcol = (tid & 15) * 4;
    float acc[4][4] = {};
    int gr = bm + arow;
    for (int k0 = 0; k0 < K; k0 += 16) {
        float4 av = make_float4(0.f,0.f,0.f,0.f);
        if (gr < M) av = *(const float4*)(A + (size_t)gr*lda + k0 + acol);
        storeT(As, acol, arow, av);
        *(float4*)&Bs[brow][bcol] = *(const float4*)(B + (size_t)(k0+brow)*ldb + bn + bcol);
        __syncthreads();
        #pragma unroll
        for (int k = 0; k < 16; k++) {
            float4 a = *(float4*)&As[k][ty*4];
            float4 b = *(float4*)&Bs[k][tx*4];
            fma4x4(acc, a, b);
        }
        __syncthreads();
    }
    #pragma unroll
    for (int i = 0; i < 4; i++) {
        int r = bm + ty*4 + i;
        if (r >= M) continue;
        #pragma unroll
        for (int j = 0; j < 4; j++) {
            int c = bn + tx*4 + j;
            if (c >= N) continue;
            size_t idx = (size_t)r*ldc + c;
            if (mode) C[idx] += acc[i][j]; else C[idx] = acc[i][j];
        }
    }
}

// ---------------- RoPE on q (16 heads) and k (4 kv heads), per chunk position ----------------
__global__ void k_rope() {
    int t = blockIdx.x, tid = threadIdx.x;
    float p = (float)(t & (CH-1));
    if (tid < NH*32) {
        int h = tid >> 5, i = tid & 31;
        float ang = p * powf(1000000.0f, -(float)i/32.0f);
        float c = cosf(ang), s = sinf(ang);
        float* q = g_q + (size_t)t*D_ + h*64 + 2*i;
        float x1 = q[0], x2 = q[1];
        q[0] = x1*c - x2*s; q[1] = x1*s + x2*c;
    }
    if (tid < NKV*32) {
        int h = tid >> 5, i = tid & 31;
        float ang = p * powf(1000000.0f, -(float)i/32.0f);
        float c = cosf(ang), s = sinf(ang);
        float* kk = g_k + (size_t)t*(NKV*HD_) + h*64 + 2*i;
        float x1 = kk[0], x2 = kk[1];
        kk[0] = x1*c - x2*s; kk[1] = x1*s + x2*c;
    }
}

// ---------------- scores: S = scale * Q Kt, causal-masked; per (chunk,head) ----------------
__global__ void k_scores() {
    int b = blockIdx.z, chunk = b >> 4, head = b & 15, kvh = head >> 2;
    int qt = blockIdx.y, kt = blockIdx.x;
    const float* Q  = g_q + (size_t)chunk*CH*D_ + head*64;
    const float* Kp = g_k + (size_t)chunk*CH*(NKV*HD_) + kvh*64;
    __shared__ __align__(16) float As[16][64];
    __shared__ __align__(16) float Bs[16][64];
    int tid = threadIdx.x, tx = tid & 15, ty = tid >> 4;
    int arow = tid >> 2, acol = (tid & 3) * 4;
    float acc[4][4] = {};
    for (int k0 = 0; k0 < 64; k0 += 16) {
        float4 av = *(const float4*)(Q  + (size_t)(qt*64+arow)*D_         + k0 + acol);
        float4 bv = *(const float4*)(Kp + (size_t)(kt*64+arow)*(NKV*HD_) + k0 + acol);
        storeT(As, acol, arow, av);
        storeT(Bs, acol, arow, bv);
        __syncthreads();
        #pragma unroll
        for (int k = 0; k < 16; k++) {
            float4 a = *(float4*)&As[k][ty*4];
            float4 bb = *(float4*)&Bs[k][tx*4];
            fma4x4(acc, a, bb);
        }
        __syncthreads();
    }
    float* S = g_sc + (size_t)b*CH*CH;
    #pragma unroll
    for (int i = 0; i < 4; i++) {
        int qg = qt*64 + ty*4 + i;
        #pragma unroll
        for (int j = 0; j < 4; j++) {
            int kg = kt*64 + tx*4 + j;
            float v = acc[i][j] * 0.125f;
            if (kg > qg) v = -1e30f;
            S[(size_t)qg*CH + kg] = v;
        }
    }
}

// ---------------- row softmax over 512 ----------------
__global__ void k_softmax() {
    size_t row = blockIdx.x;
    int tid = threadIdx.x;
    float* r = g_sc + row*CH;
    __shared__ float sh[256];
    float v0 = r[tid], v1 = r[tid+256];
    sh[tid] = fmaxf(v0, v1); __syncthreads();
    for (int o = 128; o > 0; o >>= 1) { if (tid < o) sh[tid] = fmaxf(sh[tid], sh[tid+o]); __syncthreads(); }
    float m = sh[0]; __syncthreads();
    float e0 = expf(v0 - m), e1 = expf(v1 - m);
    sh[tid] = e0 + e1; __syncthreads();
    for (int o = 128; o > 0; o >>= 1) { if (tid < o) sh[tid] += sh[tid+o]; __syncthreads(); }
    float inv = 1.f / sh[0];
    r[tid] = e0*inv; r[tid+256] = e1*inv;
}

// ---------------- O = P V  per (chunk,head) ----------------
__global__ void k_av() {
    int b = blockIdx.z, chunk = b >> 4, head = b & 15, kvh = head >> 2;
    const float* A = g_sc + (size_t)b*CH*CH;                         // lda = 512
    const float* B = g_v + (size_t)chunk*CH*(NKV*HD_) + kvh*64;      // ldb = 256
    float* C = g_attn + (size_t)chunk*CH*D_ + head*64;               // ldc = 1024
    int bm = blockIdx.y * 64;
    __shared__ __align__(16) float As[16][64];
    __shared__ __align__(16) float Bs[16][64];
    int tid = threadIdx.x, tx = tid & 15, ty = tid >> 4;
    int arow = tid >> 2, acol = (tid & 3) * 4;
    int brow = tid >> 4, bcol = (tid & 15) * 4;
    float acc[4][4] = {};
    for (int k0 = 0; k0 < CH; k0 += 16) {
        float4 av = *(const float4*)(A + (size_t)(bm+arow)*CH + k0 + acol);
        storeT(As, acol, arow, av);
        *(float4*)&Bs[brow][bcol] = *(const float4*)(B + (size_t)(k0+brow)*(NKV*HD_) + bcol);
        __syncthreads();
        #pragma unroll
        for (int k = 0; k < 16; k++) {
            float4 a = *(float4*)&As[k][ty*4];
            float4 bb = *(float4*)&Bs[k][tx*4];
            fma4x4(acc, a, bb);
        }
        __syncthreads();
    }
    #pragma unroll
    for (int i = 0; i < 4; i++)
        #pragma unroll
        for (int j = 0; j < 4; j++)
            C[(size_t)(bm + ty*4 + i)*D_ + tx*4 + j] = acc[i][j];
}

// ---------------- router: softmax over 8 experts, top-2 (warp per token) ----------------
__global__ void k_router(const float* __restrict__ rw) {
    int tid = threadIdx.x, lane = tid & 31, w = tid >> 5;
    int t = blockIdx.x*8 + w;
    const float* xr = g_xn + (size_t)t*D_;
    float acc[NE] = {};
    for (int dd = 0; dd < 32; dd++) {
        int d = dd*32 + lane;
        float x = xr[d];
        const float* rr = rw + (size_t)d*NE;
        #pragma unroll
        for (int e = 0; e < NE; e++) acc[e] += x * rr[e];
    }
    #pragma unroll
    for (int e = 0; e < NE; e++)
        for (int o = 16; o > 0; o >>= 1) acc[e] += __shfl_down_sync(0xffffffffu, acc[e], o);
    if (lane == 0) {
        float m = acc[0];
        #pragma unroll
        for (int e = 1; e < NE; e++) m = fmaxf(m, acc[e]);
        float p[NE], s = 0.f;
        #pragma unroll
        for (int e = 0; e < NE; e++) { p[e] = expf(acc[e]-m); s += p[e]; }
        float inv = 1.f/s;
        #pragma unroll
        for (int e = 0; e < NE; e++) { p[e] *= inv; g_probs[(size_t)t*NE + e] = p[e]; }
        int i0 = 0;
        #pragma unroll
        for (int e = 1; e < NE; e++) if (p[e] > p[i0]) i0 = e;
        int i1 = (i0 == 0) ? 1 : 0;
        #pragma unroll
        for (int e = 0; e < NE; e++) if (e != i0 && p[e] > p[i1]) i1 = e;
        float ws = p[i0] + p[i1];
        g_ti[2*t] = i0; g_ti[2*t+1] = i1;
        g_tw[2*t] = p[i0]/ws; g_tw[2*t+1] = p[i1]/ws;
    }
}

// ---------------- deterministic aux accumulation (single block) ----------------
__global__ void k_aux() {
    int tid = threadIdx.x;
    __shared__ float sh[256];
    __shared__ float totp[NE], totc[NE];
    float ps[NE] = {}, cs[NE] = {};
    for (int t = tid; t < T_; t += 256) {
        cs[g_ti[2*t]] += 1.f;
        #pragma unroll
        for (int e = 0; e < NE; e++) ps[e] += g_probs[(size_t)t*NE + e];
    }
    for (int e = 0; e < NE; e++) {
        sh[tid] = ps[e]; __syncthreads();
        for (int o = 128; o > 0; o >>= 1) { if (tid < o) sh[tid] += sh[tid+o]; __syncthreads(); }
        if (tid == 0) totp[e] = sh[0];
        __syncthreads();
        sh[tid] = cs[e]; __syncthreads();
        for (int o = 128; o > 0; o >>= 1) { if (tid < o) sh[tid] += sh[tid+o]; __syncthreads(); }
        if (tid == 0) totc[e] = sh[0];
        __syncthreads();
    }
    if (tid == 0) {
        float a = 0.f;
        for (int e = 0; e < NE; e++) a += (totc[e]/(float)T_) * (totp[e]/(float)T_);
        g_aux[0] += (float)NE * a;
    }
}

__global__ void k_bucket() {
    int t = blockIdx.x*256 + threadIdx.x;
    if (t >= T_) return;
    for (int j = 0; j < 2; j++) {
        int e = g_ti[2*t + j];
        int pos = atomicAdd(&g_cnt[e], 1);
        g_rows[e*T_ + pos] = t;
        g_slot[2*t + j] = e*T_ + pos;
    }
}

// ---------------- MoE up: H = silu(Xg W1) * (Xg W3), gathered rows ----------------
__global__ void k_moe_up(const float* __restrict__ W1, const float* __restrict__ W3) {
    int e = blockIdx.y >> 5, rt = blockIdx.y & 31;
    int count = g_cnt[e];
    if (rt*64 >= count) return;
    const float* B1 = W1 + (size_t)e*D_*F_;
    const float* B3 = W3 + (size_t)e*D_*F_;
    int bn = blockIdx.x * 64;
    __shared__ __align__(16) float As[16][64];
    __shared__ __align__(16) float Bs1[16][64];
    __shared__ __align__(16) float Bs3[16][64];
    int tid = threadIdx.x, tx = tid & 15, ty = tid >> 4;
    int arow = tid >> 2, acol = (tid & 3) * 4;
    int brow = tid >> 4, bcol = (tid & 15) * 4;
    int gr = rt*64 + arow;
    int tok = (gr < count) ? g_rows[e*T_ + gr] : -1;
    float a1[4][4] = {}, a3[4][4] = {};
    for (int k0 = 0; k0 < D_; k0 += 16) {
        float4 av = make_float4(0.f,0.f,0.f,0.f);
        if (tok >= 0) av = *(const float4*)(g_xn + (size_t)tok*D_ + k0 + acol);
        storeT(As, acol, arow, av);
        size_t bidx = (size_t)(k0+brow)*F_ + bn + bcol;
        *(float4*)&Bs1[brow][bcol] = *(const float4*)(B1 + bidx);
        *(float4*)&Bs3[brow][bcol] = *(const float4*)(B3 + bidx);
        __syncthreads();
        #pragma unroll
        for (int k = 0; k < 16; k++) {
            float4 a  = *(float4*)&As[k][ty*4];
            float4 b1 = *(float4*)&Bs1[k][tx*4];
            float4 b3 = *(float4*)&Bs3[k][tx*4];
            fma4x4(a1, a, b1);
            fma4x4(a3, a, b3);
        }
        __syncthreads();
    }
    #pragma unroll
    for (int i = 0; i < 4; i++) {
        int r = rt*64 + ty*4 + i;
        if (r >= count) continue;
        #pragma unroll
        for (int j = 0; j < 4; j++) {
            int c = bn + tx*4 + j;
            float u = a1[i][j];
            float hv = (u / (1.f + expf(-u))) * a3[i][j];
            g_hb[((size_t)e*T_ + r)*F_ + c] = hv;
        }
    }
}

// ---------------- MoE down: Y = H W2 ----------------
__global__ void k_moe_dn(const float* __restrict__ W2) {
    int e = blockIdx.y >> 5, rt = blockIdx.y & 31;
    int count = g_cnt[e];
    if (rt*64 >= count) return;
    const float* B = W2 + (size_t)e*F_*D_;
    int bn = blockIdx.x * 64;
    __shared__ __align__(16) float As[16][64];
    __shared__ __align__(16) float Bs[16][64];
    int tid = threadIdx.x, tx = tid & 15, ty = tid >> 4;
    int arow = tid >> 2, acol = (tid & 3) * 4;
    int brow = tid >> 4, bcol = (tid & 15) * 4;
    int gr = rt*64 + arow;
    const float* Ar = g_hb + ((size_t)e*T_ + gr)*F_;
    bool valid = (gr < count);
    float acc[4][4] = {};
    for (int k0 = 0; k0 < F_; k0 += 16) {
        float4 av = make_float4(0.f,0.f,0.f,0.f);
        if (valid) av = *(const float4*)(Ar + k0 + acol);
        storeT(As, acol, arow, av);
        *(float4*)&Bs[brow][bcol] = *(const float4*)(B + (size_t)(k0+brow)*D_ + bn + bcol);
        __syncthreads();
        #pragma unroll
        for (int k = 0; k < 16; k++) {
            float4 a = *(float4*)&As[k][ty*4];
            float4 bb = *(float4*)&Bs[k][tx*4];
            fma4x4(acc, a, bb);
        }
        __syncthreads();
    }
    #pragma unroll
    for (int i = 0; i < 4; i++) {
        int r = rt*64 + ty*4 + i;
        if (r >= count) continue;
        #pragma unroll
        for (int j = 0; j < 4; j++)
            g_yb[((size_t)e*T_ + r)*D_ + bn + tx*4 + j] = acc[i][j];
    }
}

// ---------------- combine: h += w0*Y[slot0] + w1*Y[slot1] (deterministic) ----------------
__global__ void k_combine() {
    int t = blockIdx.x, tid = threadIdx.x;
    int s0 = g_slot[2*t], s1 = g_slot[2*t+1];
    float w0 = g_tw[2*t], w1 = g_tw[2*t+1];
    const float* y0 = g_yb + (size_t)s0*D_;
    const float* y1 = g_yb + (size_t)s1*D_;
    float* hr = g_h + (size_t)t*D_;
    for (int d = tid; d < D_; d += 256)
        hr[d] += w0*y0[d] + w1*y1[d];
}

// ---------------- final small heads ----------------
__global__ void k_task(const float* __restrict__ tw, const float* __restrict__ tb,
                       float* __restrict__ out) {
    int c = blockIdx.x, tid = threadIdx.x;
    __shared__ float sh[256];
    float s = 0.f;
    for (int d = tid; d < D_; d += 256) s += g_xn[d] * tw[(size_t)d*16 + c];
    sh[tid] = s; __syncthreads();
    for (int o = 128; o > 0; o >>= 1) { if (tid < o) sh[tid] += sh[tid+o]; __syncthreads(); }
    if (tid == 0) out[OUT_TASK + c] = sh[0] + tb[c];
}
__global__ void k_mean() {
    int d = blockIdx.x*256 + threadIdx.x;
    float s = 0.f;
    for (int t = 0; t < T_; t++) s += g_xn[(size_t)t*D_ + d];
    g_xm[d] = s / (float)T_;
}
__global__ void k_eval(const float* __restrict__ ew, const float* __restrict__ eb,
                       float* __restrict__ out) {
    int c = blockIdx.x, tid = threadIdx.x;
    __shared__ float sh[256];
    float s = 0.f;
    for (int d = tid; d < D_; d += 256) s += g_xm[d] * ew[(size_t)d*8 + c];
    sh[tid] = s; __syncthreads();
    for (int o = 128; o > 0; o >>= 1) { if (tid < o) sh[tid] += sh[tid+o]; __syncthreads(); }
    if (tid == 0) out[OUT_EVAL + c] = sh[0] + eb[c];
}
__global__ void k_auxw(float* __restrict__ out) { out[OUT_AUX] = g_aux[0]; }

// ---------------- launch ----------------
extern "C" void kernel_launch(void* const* d_in, const int* in_sizes, int n_in,
                              void* d_out, int out_size) {
    const int*   ids     = (const int*)  d_in[0];
    const float* embed_W = (const float*)d_in[1];
    const float* n1      = (const float*)d_in[2];
    const float* n2      = (const float*)d_in[3];
    const float* wq      = (const float*)d_in[4];
    const float* wk      = (const float*)d_in[5];
    const float* wv      = (const float*)d_in[6];
    const float* wo      = (const float*)d_in[7];
    const float* rw      = (const float*)d_in[8];
    const float* w1      = (const float*)d_in[9];
    const float* w3      = (const float*)d_in[10];
    const float* w2      = (const float*)d_in[11];
    const float* normf   = (const float*)d_in[12];
    const float* lm      = (const float*)d_in[13];
    const float* tw      = (const float*)d_in[14];
    const float* tb      = (const float*)d_in[15];
    const float* ew      = (const float*)d_in[16];
    const float* eb      = (const float*)d_in[17];
    float* out = (float*)d_out;

    float *p_h, *p_xn, *p_q, *p_k, *p_v, *p_attn;
    cudaGetSymbolAddress((void**)&p_h,    g_h);
    cudaGetSymbolAddress((void**)&p_xn,   g_xn);
    cudaGetSymbolAddress((void**)&p_q,    g_q);
    cudaGetSymbolAddress((void**)&p_k,    g_k);
    cudaGetSymbolAddress((void**)&p_v,    g_v);
    cudaGetSymbolAddress((void**)&p_attn, g_attn);

    k_zero_aux<<<1, 32>>>();
    k_embed<<<T_, 256>>>(ids, embed_W);

    for (int l = 0; l < NL; l++) {
        // ---- attention block ----
        k_rms<<<T_, 256>>>(p_h, n1 + (size_t)l*D_, p_xn);
        k_sgemm<<<dim3(D_/64, T_/64), 256>>>(p_xn, wq + (size_t)l*D_*D_,  p_q, T_, D_,  D_, D_, D_,  D_,  0);
        k_sgemm<<<dim3(256/64, T_/64), 256>>>(p_xn, wk + (size_t)l*D_*256, p_k, T_, 256, D_, D_, 256, 256, 0);
        k_sgemm<<<dim3(256/64, T_/64), 256>>>(p_xn, wv + (size_t)l*D_*256, p_v, T_, 256, D_, D_, 256, 256, 0);
        k_rope<<<T_, 512>>>();
        k_scores<<<dim3(8, 8, NCK*NH), 256>>>();
        k_softmax<<<NCK*NH*CH, 256>>>();
        k_av<<<dim3(1, 8, NCK*NH), 256>>>();
        k_sgemm<<<dim3(D_/64, T_/64), 256>>>(p_attn, wo + (size_t)l*D_*D_, p_h, T_, D_, D_, D_, D_, D_, 1);

        // ---- MoE block ----
        k_rms<<<T_, 256>>>(p_h, n2 + (size_t)l*D_, p_xn);
        k_router<<<T_/8, 256>>>(rw + (size_t)l*D_*NE);
        k_aux<<<1, 256>>>();
        k_zero_cnt<<<1, 32>>>();
        k_bucket<<<T_/256, 256>>>();
        k_moe_up<<<dim3(F_/64, NE*32), 256>>>(w1 + (size_t)l*NE*D_*F_, w3 + (size_t)l*NE*D_*F_);
        k_moe_dn<<<dim3(D_/64, NE*32), 256>>>(w2 + (size_t)l*NE*F_*D_);
        k_combine<<<T_, 256>>>();
    }

    // ---- final norm + heads ----
    k_rms<<<T_, 256>>>(p_h, normf, p_xn);
    k_sgemm<<<dim3(NV/64, T_/64), 256>>>(p_xn, lm, out, T_, NV, D_, D_, NV, NV, 0);
    k_task<<<16, 256>>>(tw, tb, out);
    k_mean<<<D_/256, 256>>>();
    k_eval<<<8, 256>>>(ew, eb, out);
    k_auxw<<<1, 1>>>(out);
}

// round 6
// speedup vs baseline: 1.0010x; 1.0008x over previous
#include <cuda_runtime.h>
#include <cuda_bf16.h>
#include <math.h>

// ---------------- problem constants ----------------
#define T_   2048
#define D_   1024
#define NH   16
#define NKV  4
#define HD_  64
#define F_   2048
#define NE   8
#define NL   2
#define NV   32000
#define CH   512
#define NCK  4            // T_/CH

#define OUT_TASK   (T_*(size_t)NV)     // 65,536,000
#define OUT_EVAL   (OUT_TASK + 16)
#define OUT_AUX    (OUT_EVAL + 8)

// ---------------- scratch (device globals; no allocation) ----------------
__device__ float g_h   [(size_t)T_*D_];
__device__ float g_xn  [(size_t)T_*D_];
__device__ float g_q   [(size_t)T_*NH*HD_];
__device__ float g_k   [(size_t)T_*NKV*HD_];
__device__ float g_v   [(size_t)T_*NKV*HD_];
__device__ float g_sc  [(size_t)NCK*NH*CH*CH];      // 67 MB scores
__device__ float g_attn[(size_t)T_*D_];
__device__ float g_probs[(size_t)T_*NE];
__device__ int   g_ti  [T_*2];
__device__ float g_tw  [T_*2];
__device__ int   g_cnt [NE];
__device__ int   g_rows[NE*T_];
__device__ int   g_slot[T_*2];
__device__ float g_hb  [(size_t)NE*T_*F_];          // 128 MB MoE hidden
__device__ float g_yb  [(size_t)NE*T_*D_];          // 64 MB MoE expert out
__device__ float g_aux [1];
__device__ float g_xm  [D_];

// ---------------- helpers ----------------
__device__ __forceinline__ void fma4x4(float (&acc)[4][4], float4 a, float4 b) {
    acc[0][0] += a.x*b.x; acc[0][1] += a.x*b.y; acc[0][2] += a.x*b.z; acc[0][3] += a.x*b.w;
    acc[1][0] += a.y*b.x; acc[1][1] += a.y*b.y; acc[1][2] += a.y*b.z; acc[1][3] += a.y*b.w;
    acc[2][0] += a.z*b.x; acc[2][1] += a.z*b.y; acc[2][2] += a.z*b.z; acc[2][3] += a.z*b.w;
    acc[3][0] += a.w*b.x; acc[3][1] += a.w*b.y; acc[3][2] += a.w*b.z; acc[3][3] += a.w*b.w;
}
__device__ __forceinline__ void storeT(float (&S)[16][64], int acol, int arow, float4 v) {
    S[acol+0][arow] = v.x; S[acol+1][arow] = v.y; S[acol+2][arow] = v.z; S[acol+3][arow] = v.w;
}

// ---------------- tiny kernels ----------------
__global__ void k_zero_aux() { if (threadIdx.x == 0) g_aux[0] = 0.f; }
__global__ void k_zero_cnt() { if (threadIdx.x < NE) g_cnt[threadIdx.x] = 0; }

__global__ void k_embed(const int* __restrict__ ids, const float* __restrict__ ew) {
    int t = blockIdx.x;
    size_t r = (size_t)ids[t] * D_;
    for (int d = threadIdx.x; d < D_; d += blockDim.x)
        g_h[(size_t)t*D_ + d] = ew[r + d];
}

__global__ void k_rms(const float* __restrict__ x, const float* __restrict__ w,
                      float* __restrict__ out) {
    int t = blockIdx.x, tid = threadIdx.x;
    __shared__ float sh[256];
    const float* xr = x + (size_t)t*D_;
    float s = 0.f;
    for (int d = tid; d < D_; d += 256) { float v = xr[d]; s += v*v; }
    sh[tid] = s; __syncthreads();
    for (int o = 128; o > 0; o >>= 1) { if (tid < o) sh[tid] += sh[tid+o]; __syncthreads(); }
    float scale = rsqrtf(sh[0] / (float)D_ + 1e-6f);
    float* orow = out + (size_t)t*D_;
    for (int d = tid; d < D_; d += 256) orow[d] = w[d] * xr[d] * scale;
}

// ---------------- generic 64x64x16 SGEMM (NN), mode 0: C=AB, 1: C+=AB ----------------
__global__ void k_sgemm(const float* __restrict__ A, const float* __restrict__ B,
                        float* __restrict__ C, int M, int N, int K,
                        int lda, int ldb, int ldc, int mode) {
    __shared__ __align__(16) float As[16][64];
    __shared__ __align__(16) float Bs[16][64];
    int bn = blockIdx.x * 64, bm = blockIdx.y * 64;
    int tid = threadIdx.x, tx = tid & 15, ty = tid >> 4;
    int arow = tid >> 2, acol = (tid & 3) * 4;
    int brow = tid >> 4, bcol = (tid & 15) * 4;
    float acc[4][4] = {};
    int gr = bm + arow;
    for (int k0 = 0; k0 < K; k0 += 16) {
        float4 av = make_float4(0.f,0.f,0.f,0.f);
        if (gr < M) av = *(const float4*)(A + (size_t)gr*lda + k0 + acol);
        storeT(As, acol, arow, av);
        *(float4*)&Bs[brow][bcol] = *(const float4*)(B + (size_t)(k0+brow)*ldb + bn + bcol);
        __syncthreads();
        #pragma unroll
        for (int k = 0; k < 16; k++) {
            float4 a = *(float4*)&As[k][ty*4];
            float4 b = *(float4*)&Bs[k][tx*4];
            fma4x4(acc, a, b);
        }
        __syncthreads();
    }
    #pragma unroll
    for (int i = 0; i < 4; i++) {
        int r = bm + ty*4 + i;
        if (r >= M) continue;
        #pragma unroll
        for (int j = 0; j < 4; j++) {
            int c = bn + tx*4 + j;
            if (c >= N) continue;
            size_t idx = (size_t)r*ldc + c;
            if (mode) C[idx] += acc[i][j]; else C[idx] = acc[i][j];
        }
    }
}

// ---------------- RoPE on q (16 heads) and k (4 kv heads), per chunk position ----------------
__global__ void k_rope() {
    int t = blockIdx.x, tid = threadIdx.x;
    float p = (float)(t & (CH-1));
    if (tid < NH*32) {
        int h = tid >> 5, i = tid & 31;
        float ang = p * powf(1000000.0f, -(float)i/32.0f);
        float c = cosf(ang), s = sinf(ang);
        float* q = g_q + (size_t)t*D_ + h*64 + 2*i;
        float x1 = q[0], x2 = q[1];
        q[0] = x1*c - x2*s; q[1] = x1*s + x2*c;
    }
    if (tid < NKV*32) {
        int h = tid >> 5, i = tid & 31;
        float ang = p * powf(1000000.0f, -(float)i/32.0f);
        float c = cosf(ang), s = sinf(ang);
        float* kk = g_k + (size_t)t*(NKV*HD_) + h*64 + 2*i;
        float x1 = kk[0], x2 = kk[1];
        kk[0] = x1*c - x2*s; kk[1] = x1*s + x2*c;
    }
}

// ---------------- scores: S = scale * Q Kt, causal-masked; per (chunk,head) ----------------
__global__ void k_scores() {
    int b = blockIdx.z, chunk = b >> 4, head = b & 15, kvh = head >> 2;
    int qt = blockIdx.y, kt = blockIdx.x;
    const float* Q  = g_q + (size_t)chunk*CH*D_ + head*64;
    const float* Kp = g_k + (size_t)chunk*CH*(NKV*HD_) + kvh*64;
    __shared__ __align__(16) float As[16][64];
    __shared__ __align__(16) float Bs[16][64];
    int tid = threadIdx.x, tx = tid & 15, ty = tid >> 4;
    int arow = tid >> 2, acol = (tid & 3) * 4;
    float acc[4][4] = {};
    for (int k0 = 0; k0 < 64; k0 += 16) {
        float4 av = *(const float4*)(Q  + (size_t)(qt*64+arow)*D_         + k0 + acol);
        float4 bv = *(const float4*)(Kp + (size_t)(kt*64+arow)*(NKV*HD_) + k0 + acol);
        storeT(As, acol, arow, av);
        storeT(Bs, acol, arow, bv);
        __syncthreads();
        #pragma unroll
        for (int k = 0; k < 16; k++) {
            float4 a = *(float4*)&As[k][ty*4];
            float4 bb = *(float4*)&Bs[k][tx*4];
            fma4x4(acc, a, bb);
        }
        __syncthreads();
    }
    float* S = g_sc + (size_t)b*CH*CH;
    #pragma unroll
    for (int i = 0; i < 4; i++) {
        int qg = qt*64 + ty*4 + i;
        #pragma unroll
        for (int j = 0; j < 4; j++) {
            int kg = kt*64 + tx*4 + j;
            float v = acc[i][j] * 0.125f;
            if (kg > qg) v = -1e30f;
            S[(size_t)qg*CH + kg] = v;
        }
    }
}

// ---------------- row softmax over 512 ----------------
__global__ void k_softmax() {
    size_t row = blockIdx.x;
    int tid = threadIdx.x;
    float* r = g_sc + row*CH;
    __shared__ float sh[256];
    float v0 = r[tid], v1 = r[tid+256];
    sh[tid] = fmaxf(v0, v1); __syncthreads();
    for (int o = 128; o > 0; o >>= 1) { if (tid < o) sh[tid] = fmaxf(sh[tid], sh[tid+o]); __syncthreads(); }
    float m = sh[0]; __syncthreads();
    float e0 = expf(v0 - m), e1 = expf(v1 - m);
    sh[tid] = e0 + e1; __syncthreads();
    for (int o = 128; o > 0; o >>= 1) { if (tid < o) sh[tid] += sh[tid+o]; __syncthreads(); }
    float inv = 1.f / sh[0];
    r[tid] = e0*inv; r[tid+256] = e1*inv;
}

// ---------------- O = P V  per (chunk,head) ----------------
__global__ void k_av() {
    int b = blockIdx.z, chunk = b >> 4, head = b & 15, kvh = head >> 2;
    const float* A = g_sc + (size_t)b*CH*CH;                         // lda = 512
    const float* B = g_v + (size_t)chunk*CH*(NKV*HD_) + kvh*64;      // ldb = 256
    float* C = g_attn + (size_t)chunk*CH*D_ + head*64;               // ldc = 1024
    int bm = blockIdx.y * 64;
    __shared__ __align__(16) float As[16][64];
    __shared__ __align__(16) float Bs[16][64];
    int tid = threadIdx.x, tx = tid & 15, ty = tid >> 4;
    int arow = tid >> 2, acol = (tid & 3) * 4;
    int brow = tid >> 4, bcol = (tid & 15) * 4;
    float acc[4][4] = {};
    for (int k0 = 0; k0 < CH; k0 += 16) {
        float4 av = *(const float4*)(A + (size_t)(bm+arow)*CH + k0 + acol);
        storeT(As, acol, arow, av);
        *(float4*)&Bs[brow][bcol] = *(const float4*)(B + (size_t)(k0+brow)*(NKV*HD_) + bcol);
        __syncthreads();
        #pragma unroll
        for (int k = 0; k < 16; k++) {
            float4 a = *(float4*)&As[k][ty*4];
            float4 bb = *(float4*)&Bs[k][tx*4];
            fma4x4(acc, a, bb);
        }
        __syncthreads();
    }
    #pragma unroll
    for (int i = 0; i < 4; i++)
        #pragma unroll
        for (int j = 0; j < 4; j++)
            C[(size_t)(bm + ty*4 + i)*D_ + tx*4 + j] = acc[i][j];
}

// ---------------- router: softmax over 8 experts, top-2 (warp per token) ----------------
__global__ void k_router(const float* __restrict__ rw) {
    int tid = threadIdx.x, lane = tid & 31, w = tid >> 5;
    int t = blockIdx.x*8 + w;
    const float* xr = g_xn + (size_t)t*D_;
    float acc[NE] = {};
    for (int dd = 0; dd < 32; dd++) {
        int d = dd*32 + lane;
        float x = xr[d];
        const float* rr = rw + (size_t)d*NE;
        #pragma unroll
        for (int e = 0; e < NE; e++) acc[e] += x * rr[e];
    }
    #pragma unroll
    for (int e = 0; e < NE; e++)
        for (int o = 16; o > 0; o >>= 1) acc[e] += __shfl_down_sync(0xffffffffu, acc[e], o);
    if (lane == 0) {
        float m = acc[0];
        #pragma unroll
        for (int e = 1; e < NE; e++) m = fmaxf(m, acc[e]);
        float p[NE], s = 0.f;
        #pragma unroll
        for (int e = 0; e < NE; e++) { p[e] = expf(acc[e]-m); s += p[e]; }
        float inv = 1.f/s;
        #pragma unroll
        for (int e = 0; e < NE; e++) { p[e] *= inv; g_probs[(size_t)t*NE + e] = p[e]; }
        int i0 = 0;
        #pragma unroll
        for (int e = 1; e < NE; e++) if (p[e] > p[i0]) i0 = e;
        int i1 = (i0 == 0) ? 1 : 0;
        #pragma unroll
        for (int e = 0; e < NE; e++) if (e != i0 && p[e] > p[i1]) i1 = e;
        float ws = p[i0] + p[i1];
        g_ti[2*t] = i0; g_ti[2*t+1] = i1;
        g_tw[2*t] = p[i0]/ws; g_tw[2*t+1] = p[i1]/ws;
    }
}

// ---------------- deterministic aux accumulation (single block) ----------------
__global__ void k_aux() {
    int tid = threadIdx.x;
    __shared__ float sh[256];
    __shared__ float totp[NE], totc[NE];
    float ps[NE] = {}, cs[NE] = {};
    for (int t = tid; t < T_; t += 256) {
        cs[g_ti[2*t]] += 1.f;
        #pragma unroll
        for (int e = 0; e < NE; e++) ps[e] += g_probs[(size_t)t*NE + e];
    }
    for (int e = 0; e < NE; e++) {
        sh[tid] = ps[e]; __syncthreads();
        for (int o = 128; o > 0; o >>= 1) { if (tid < o) sh[tid] += sh[tid+o]; __syncthreads(); }
        if (tid == 0) totp[e] = sh[0];
        __syncthreads();
        sh[tid] = cs[e]; __syncthreads();
        for (int o = 128; o > 0; o >>= 1) { if (tid < o) sh[tid] += sh[tid+o]; __syncthreads(); }
        if (tid == 0) totc[e] = sh[0];
        __syncthreads();
    }
    if (tid == 0) {
        float a = 0.f;
        for (int e = 0; e < NE; e++) a += (totc[e]/(float)T_) * (totp[e]/(float)T_);
        g_aux[0] += (float)NE * a;
    }
}

__global__ void k_bucket() {
    int t = blockIdx.x*256 + threadIdx.x;
    if (t >= T_) return;
    for (int j = 0; j < 2; j++) {
        int e = g_ti[2*t + j];
        int pos = atomicAdd(&g_cnt[e], 1);
        g_rows[e*T_ + pos] = t;
        g_slot[2*t + j] = e*T_ + pos;
    }
}

// ---------------- MoE up: H = silu(Xg W1) * (Xg W3), gathered rows ----------------
__global__ void k_moe_up(const float* __restrict__ W1, const float* __restrict__ W3) {
    int e = blockIdx.y >> 5, rt = blockIdx.y & 31;
    int count = g_cnt[e];
    if (rt*64 >= count) return;
    const float* B1 = W1 + (size_t)e*D_*F_;
    const float* B3 = W3 + (size_t)e*D_*F_;
    int bn = blockIdx.x * 64;
    __shared__ __align__(16) float As[16][64];
    __shared__ __align__(16) float Bs1[16][64];
    __shared__ __align__(16) float Bs3[16][64];
    int tid = threadIdx.x, tx = tid & 15, ty = tid >> 4;
    int arow = tid >> 2, acol = (tid & 3) * 4;
    int brow = tid >> 4, bcol = (tid & 15) * 4;
    int gr = rt*64 + arow;
    int tok = (gr < count) ? g_rows[e*T_ + gr] : -1;
    float a1[4][4] = {}, a3[4][4] = {};
    for (int k0 = 0; k0 < D_; k0 += 16) {
        float4 av = make_float4(0.f,0.f,0.f,0.f);
        if (tok >= 0) av = *(const float4*)(g_xn + (size_t)tok*D_ + k0 + acol);
        storeT(As, acol, arow, av);
        size_t bidx = (size_t)(k0+brow)*F_ + bn + bcol;
        *(float4*)&Bs1[brow][bcol] = *(const float4*)(B1 + bidx);
        *(float4*)&Bs3[brow][bcol] = *(const float4*)(B3 + bidx);
        __syncthreads();
        #pragma unroll
        for (int k = 0; k < 16; k++) {
            float4 a  = *(float4*)&As[k][ty*4];
            float4 b1 = *(float4*)&Bs1[k][tx*4];
            float4 b3 = *(float4*)&Bs3[k][tx*4];
            fma4x4(a1, a, b1);
            fma4x4(a3, a, b3);
        }
        __syncthreads();
    }
    #pragma unroll
    for (int i = 0; i < 4; i++) {
        int r = rt*64 + ty*4 + i;
        if (r >= count) continue;
        #pragma unroll
        for (int j = 0; j < 4; j++) {
            int c = bn + tx*4 + j;
            float u = a1[i][j];
            float hv = (u / (1.f + expf(-u))) * a3[i][j];
            g_hb[((size_t)e*T_ + r)*F_ + c] = hv;
        }
    }
}

// ---------------- MoE down: Y = H W2 ----------------
__global__ void k_moe_dn(const float* __restrict__ W2) {
    int e = blockIdx.y >> 5, rt = blockIdx.y & 31;
    int count = g_cnt[e];
    if (rt*64 >= count) return;
    const float* B = W2 + (size_t)e*F_*D_;
    int bn = blockIdx.x * 64;
    __shared__ __align__(16) float As[16][64];
    __shared__ __align__(16) float Bs[16][64];
    int tid = threadIdx.x, tx = tid & 15, ty = tid >> 4;
    int arow = tid >> 2, acol = (tid & 3) * 4;
    int brow = tid >> 4, bcol = (tid & 15) * 4;
    int gr = rt*64 + arow;
    const float* Ar = g_hb + ((size_t)e*T_ + gr)*F_;
    bool valid = (gr < count);
    float acc[4][4] = {};
    for (int k0 = 0; k0 < F_; k0 += 16) {
        float4 av = make_float4(0.f,0.f,0.f,0.f);
        if (valid) av = *(const float4*)(Ar + k0 + acol);
        storeT(As, acol, arow, av);
        *(float4*)&Bs[brow][bcol] = *(const float4*)(B + (size_t)(k0+brow)*D_ + bn + bcol);
        __syncthreads();
        #pragma unroll
        for (int k = 0; k < 16; k++) {
            float4 a = *(float4*)&As[k][ty*4];
            float4 bb = *(float4*)&Bs[k][tx*4];
            fma4x4(acc, a, bb);
        }
        __syncthreads();
    }
    #pragma unroll
    for (int i = 0; i < 4; i++) {
        int r = rt*64 + ty*4 + i;
        if (r >= count) continue;
        #pragma unroll
        for (int j = 0; j < 4; j++)
            g_yb[((size_t)e*T_ + r)*D_ + bn + tx*4 + j] = acc[i][j];
    }
}

// ---------------- combine: h += w0*Y[slot0] + w1*Y[slot1] (deterministic) ----------------
__global__ void k_combine() {
    int t = blockIdx.x, tid = threadIdx.x;
    int s0 = g_slot[2*t], s1 = g_slot[2*t+1];
    float w0 = g_tw[2*t], w1 = g_tw[2*t+1];
    const float* y0 = g_yb + (size_t)s0*D_;
    const float* y1 = g_yb + (size_t)s1*D_;
    float* hr = g_h + (size_t)t*D_;
    for (int d = tid; d < D_; d += 256)
        hr[d] += w0*y0[d] + w1*y1[d];
}

// ---------------- final small heads ----------------
__global__ void k_task(const float* __restrict__ tw, const float* __restrict__ tb,
                       float* __restrict__ out) {
    int c = blockIdx.x, tid = threadIdx.x;
    __shared__ float sh[256];
    float s = 0.f;
    for (int d = tid; d < D_; d += 256) s += g_xn[d] * tw[(size_t)d*16 + c];
    sh[tid] = s; __syncthreads();
    for (int o = 128; o > 0; o >>= 1) { if (tid < o) sh[tid] += sh[tid+o]; __syncthreads(); }
    if (tid == 0) out[OUT_TASK + c] = sh[0] + tb[c];
}
__global__ void k_mean() {
    int d = blockIdx.x*256 + threadIdx.x;
    float s = 0.f;
    for (int t = 0; t < T_; t++) s += g_xn[(size_t)t*D_ + d];
    g_xm[d] = s / (float)T_;
}
__global__ void k_eval(const float* __restrict__ ew, const float* __restrict__ eb,
                       float* __restrict__ out) {
    int c = blockIdx.x, tid = threadIdx.x;
    __shared__ float sh[256];
    float s = 0.f;
    for (int d = tid; d < D_; d += 256) s += g_xm[d] * ew[(size_t)d*8 + c];
    sh[tid] = s; __syncthreads();
    for (int o = 128; o > 0; o >>= 1) { if (tid < o) sh[tid] += sh[tid+o]; __syncthreads(); }
    if (tid == 0) out[OUT_EVAL + c] = sh[0] + eb[c];
}
__global__ void k_auxw(float* __restrict__ out) { out[OUT_AUX] = g_aux[0]; }

// ---------------- launch ----------------
extern "C" void kernel_launch(void* const* d_in, const int* in_sizes, int n_in,
                              void* d_out, int out_size) {
    const int*   ids     = (const int*)  d_in[0];
    const float* embed_W = (const float*)d_in[1];
    const float* n1      = (const float*)d_in[2];
    const float* n2      = (const float*)d_in[3];
    const float* wq      = (const float*)d_in[4];
    const float* wk      = (const float*)d_in[5];
    const float* wv      = (const float*)d_in[6];
    const float* wo      = (const float*)d_in[7];
    const float* rw      = (const float*)d_in[8];
    const float* w1      = (const float*)d_in[9];
    const float* w3      = (const float*)d_in[10];
    const float* w2      = (const float*)d_in[11];
    const float* normf   = (const float*)d_in[12];
    const float* lm      = (const float*)d_in[13];
    const float* tw      = (const float*)d_in[14];
    const float* tb      = (const float*)d_in[15];
    const float* ew      = (const float*)d_in[16];
    const float* eb      = (const float*)d_in[17];
    float* out = (float*)d_out;

    float *p_h, *p_xn, *p_q, *p_k, *p_v, *p_attn;
    cudaGetSymbolAddress((void**)&p_h,    g_h);
    cudaGetSymbolAddress((void**)&p_xn,   g_xn);
    cudaGetSymbolAddress((void**)&p_q,    g_q);
    cudaGetSymbolAddress((void**)&p_k,    g_k);
    cudaGetSymbolAddress((void**)&p_v,    g_v);
    cudaGetSymbolAddress((void**)&p_attn, g_attn);

    k_zero_aux<<<1, 32>>>();
    k_embed<<<T_, 256>>>(ids, embed_W);

    for (int l = 0; l < NL; l++) {
        // ---- attention block ----
        k_rms<<<T_, 256>>>(p_h, n1 + (size_t)l*D_, p_xn);
        k_sgemm<<<dim3(D_/64, T_/64), 256>>>(p_xn, wq + (size_t)l*D_*D_,  p_q, T_, D_,  D_, D_, D_,  D_,  0);
        k_sgemm<<<dim3(256/64, T_/64), 256>>>(p_xn, wk + (size_t)l*D_*256, p_k, T_, 256, D_, D_, 256, 256, 0);
        k_sgemm<<<dim3(256/64, T_/64), 256>>>(p_xn, wv + (size_t)l*D_*256, p_v, T_, 256, D_, D_, 256, 256, 0);
        k_rope<<<T_, 512>>>();
        k_scores<<<dim3(8, 8, NCK*NH), 256>>>();
        k_softmax<<<NCK*NH*CH, 256>>>();
        k_av<<<dim3(1, 8, NCK*NH), 256>>>();
        k_sgemm<<<dim3(D_/64, T_/64), 256>>>(p_attn, wo + (size_t)l*D_*D_, p_h, T_, D_, D_, D_, D_, D_, 1);

        // ---- MoE block ----
        k_rms<<<T_, 256>>>(p_h, n2 + (size_t)l*D_, p_xn);
        k_router<<<T_/8, 256>>>(rw + (size_t)l*D_*NE);
        k_aux<<<1, 256>>>();
        k_zero_cnt<<<1, 32>>>();
        k_bucket<<<T_/256, 256>>>();
        k_moe_up<<<dim3(F_/64, NE*32), 256>>>(w1 + (size_t)l*NE*D_*F_, w3 + (size_t)l*NE*D_*F_);
        k_moe_dn<<<dim3(D_/64, NE*32), 256>>>(w2 + (size_t)l*NE*F_*D_);
        k_combine<<<T_, 256>>>();
    }

    // ---- final norm + heads ----
    k_rms<<<T_, 256>>>(p_h, normf, p_xn);
    k_sgemm<<<dim3(NV/64, T_/64), 256>>>(p_xn, lm, out, T_, NV, D_, D_, NV, NV, 0);
    k_task<<<16, 256>>>(tw, tb, out);
    k_mean<<<D_/256, 256>>>();
    k_eval<<<8, 256>>>(ew, eb, out);
    k_auxw<<<1, 1>>>(out);
}

// round 8
// speedup vs baseline: 2.1734x; 2.1712x over previous
#include <cuda_runtime.h>
#include <cuda_bf16.h>
#include <math.h>
#include <stdint.h>

#define T_   2048
#define D_   1024
#define NH   16
#define NKV  4
#define F_   2048
#define NE   8
#define NL   2
#define NV   32000
#define CH   512
#define NCK  4

#define OUT_TASK   (T_*(size_t)NV)
#define OUT_EVAL   (OUT_TASK + 16)
#define OUT_AUX    (OUT_EVAL + 8)

// ---------------- scratch (device globals; no allocation) ----------------
__device__ float g_h   [(size_t)T_*D_];
__device__ float g_xn  [(size_t)T_*D_];
__device__ float g_q   [(size_t)T_*D_];
__device__ float g_k   [(size_t)T_*256];
__device__ float g_v   [(size_t)T_*256];
__device__ float g_sc  [(size_t)NCK*NH*CH*CH];
__device__ float g_attn[(size_t)T_*D_];
__device__ float g_probs[(size_t)T_*NE];
__device__ int   g_ti  [T_*2];
__device__ float g_tw  [T_*2];
__device__ int   g_cnt [NE];
__device__ int   g_rows[NE*T_];
__device__ int   g_slot[T_*2];
__device__ float g_yb  [(size_t)NE*T_*D_];
__device__ float g_aux [1];
__device__ float g_xm  [D_];
__device__ __nv_bfloat16 g_ah [(size_t)T_*D_];
__device__ __nv_bfloat16 g_al [(size_t)T_*D_];
__device__ float g_ub  [(size_t)NE*T_*F_];          // MoE u = X W1 (fp32)
__device__ __nv_bfloat16 g_hbh[(size_t)NE*T_*F_];   // MoE hidden hi
__device__ __nv_bfloat16 g_hbl[(size_t)NE*T_*F_];   // MoE hidden lo

// ---------------- mma helpers ----------------
__device__ __forceinline__ uint32_t smem_u32(const void* p) {
    uint32_t a;
    asm("{ .reg .u64 t; cvta.to.shared.u64 t, %1; cvt.u32.u64 %0, t; }" : "=r"(a) : "l"(p));
    return a;
}
__device__ __forceinline__ void ldsm4(uint32_t (&r)[4], uint32_t a) {
    asm volatile("ldmatrix.sync.aligned.m8n8.x4.shared.b16 {%0,%1,%2,%3}, [%4];"
        : "=r"(r[0]), "=r"(r[1]), "=r"(r[2]), "=r"(r[3]) : "r"(a));
}
__device__ __forceinline__ void ldsm2t(uint32_t (&r)[2], uint32_t a) {
    asm volatile("ldmatrix.sync.aligned.m8n8.x2.trans.shared.b16 {%0,%1}, [%2];"
        : "=r"(r[0]), "=r"(r[1]) : "r"(a));
}
__device__ __forceinline__ void mma16816(float (&d)[4], const uint32_t (&a)[4], const uint32_t (&b)[2]) {
    asm volatile("mma.sync.aligned.m16n8k16.row.col.f32.bf16.bf16.f32 "
        "{%0,%1,%2,%3}, {%4,%5,%6,%7}, {%8,%9}, {%0,%1,%2,%3};"
        : "+f"(d[0]), "+f"(d[1]), "+f"(d[2]), "+f"(d[3])
        : "r"(a[0]), "r"(a[1]), "r"(a[2]), "r"(a[3]), "r"(b[0]), "r"(b[1]));
}

// SMEM layout per buffer (bytes):
//   Ah: 128 rows x 80B   @ 0        (32 bf16 + pad8)
//   Al: same             @ 10240
//   Bh: 32 k-rows x 272B @ 20480    (128 bf16 + pad8)
//   Bl: same             @ 29184
#define OFF_AL 10240
#define OFF_BH 20480
#define OFF_BL 29184
#define BUFSZ  37888
#define SMEM_MMA (2*BUFSZ)

// modes: 0 = C=acc, 1 = C+=acc, 2 = silu(U)*acc -> split bf16 to Hh/Hl
__device__ __forceinline__ void mma_block(
    const __nv_bfloat16* __restrict__ Ah, const __nv_bfloat16* __restrict__ Al,
    const int* __restrict__ rows, int count,
    const float* __restrict__ B, int ldb, int K,
    float* __restrict__ C, int ldc, int mode,
    const float* __restrict__ U, __nv_bfloat16* __restrict__ Hh, __nv_bfloat16* __restrict__ Hl,
    int m0, int n0, char* dsm, uint32_t sb)
{
    const int tid = threadIdx.x, lane = tid & 31, wid = tid >> 5;
    const int wm = (wid & 1) * 64, wn = (wid >> 1) * 32;

    // loader indices
    const int ar = tid >> 1, akc = (tid & 1) * 16;          // A: row, k-half
    const int bkr = tid >> 3, bn16 = (tid & 7) * 16;        // B: k-row, n-offset
    const int gm = m0 + ar;
    const bool av = gm < count;
    const __nv_bfloat16* pAh = Ah;
    const __nv_bfloat16* pAl = Al;
    if (av) {
        size_t rr = (size_t)(rows ? rows[gm] : gm) * K + akc;
        pAh = Ah + rr; pAl = Al + rr;
    }
    const float* pB = B + (size_t)bkr * ldb + n0 + bn16;

    float acc[4][4][4];
    #pragma unroll
    for (int a = 0; a < 4; a++)
        #pragma unroll
        for (int b = 0; b < 4; b++)
            #pragma unroll
            for (int c = 0; c < 4; c++) acc[a][b][c] = 0.f;

    uint4 avh0, avh1, avl0, avl1;
    float4 bf0, bf1, bf2, bf3;

    auto LOADG = [&](int k0) {
        if (av) {
            avh0 = *(const uint4*)(pAh + k0);
            avh1 = *(const uint4*)(pAh + k0 + 8);
            avl0 = *(const uint4*)(pAl + k0);
            avl1 = *(const uint4*)(pAl + k0 + 8);
        } else {
            avh0 = avh1 = avl0 = avl1 = make_uint4(0,0,0,0);
        }
        const float* bp = pB + (size_t)k0 * ldb;
        bf0 = *(const float4*)(bp);
        bf1 = *(const float4*)(bp + 4);
        bf2 = *(const float4*)(bp + 8);
        bf3 = *(const float4*)(bp + 12);
    };

    auto STORES = [&](char* sm) {
        uint32_t ao = (uint32_t)ar * 80 + (uint32_t)akc * 2;
        *(uint2*)(sm + ao)      = make_uint2(avh0.x, avh0.y);
        *(uint2*)(sm + ao + 8)  = make_uint2(avh0.z, avh0.w);
        *(uint2*)(sm + ao + 16) = make_uint2(avh1.x, avh1.y);
        *(uint2*)(sm + ao + 24) = make_uint2(avh1.z, avh1.w);
        char* sl = sm + OFF_AL;
        *(uint2*)(sl + ao)      = make_uint2(avl0.x, avl0.y);
        *(uint2*)(sl + ao + 8)  = make_uint2(avl0.z, avl0.w);
        *(uint2*)(sl + ao + 16) = make_uint2(avl1.x, avl1.y);
        *(uint2*)(sl + ao + 24) = make_uint2(avl1.z, avl1.w);
        float fv[16] = {bf0.x,bf0.y,bf0.z,bf0.w, bf1.x,bf1.y,bf1.z,bf1.w,
                        bf2.x,bf2.y,bf2.z,bf2.w, bf3.x,bf3.y,bf3.z,bf3.w};
        uint32_t hw[8], lw[8];
        #pragma unroll
        for (int j = 0; j < 8; j++) {
            float x0 = fv[2*j], x1 = fv[2*j+1];
            __nv_bfloat162 hh = __floats2bfloat162_rn(x0, x1);
            float r0x = x0 - __low2float(hh);
            float r1x = x1 - __high2float(hh);
            __nv_bfloat162 ll = __floats2bfloat162_rn(r0x, r1x);
            hw[j] = *(uint32_t*)&hh;
            lw[j] = *(uint32_t*)&ll;
        }
        uint32_t bo = (uint32_t)bkr * 272 + (uint32_t)bn16 * 2;
        char* bh = sm + OFF_BH + bo;
        *(uint4*)(bh)      = make_uint4(hw[0], hw[1], hw[2], hw[3]);
        *(uint4*)(bh + 16) = make_uint4(hw[4], hw[5], hw[6], hw[7]);
        char* bl = sm + OFF_BL + bo;
        *(uint4*)(bl)      = make_uint4(lw[0], lw[1], lw[2], lw[3]);
        *(uint4*)(bl + 16) = make_uint4(lw[4], lw[5], lw[6], lw[7]);
    };

    auto COMPUTE = [&](uint32_t bo) {
        uint32_t abase = sb + bo + (uint32_t)(wm + (lane & 15)) * 80 + ((lane >> 4) * 8) * 2;
        uint32_t bbase = sb + bo + OFF_BH
                       + (uint32_t)((lane & 7) + ((lane >> 3) & 1) * 8) * 272
                       + (uint32_t)wn * 2;
        #pragma unroll
        for (int ks = 0; ks < 2; ks++) {
            uint32_t ah4[4][4], al4[4][4], bh2[4][2], bl2[4][2];
            #pragma unroll
            for (int mt = 0; mt < 4; mt++) {
                uint32_t aa = abase + mt * (16 * 80) + ks * 32;
                ldsm4(ah4[mt], aa);
                ldsm4(al4[mt], aa + OFF_AL);
            }
            #pragma unroll
            for (int nt = 0; nt < 4; nt++) {
                uint32_t ba = bbase + ks * (16 * 272) + nt * 16;
                ldsm2t(bh2[nt], ba);
                ldsm2t(bl2[nt], ba + (OFF_BL - OFF_BH));
            }
            #pragma unroll
            for (int mt = 0; mt < 4; mt++)
                #pragma unroll
                for (int nt = 0; nt < 4; nt++) {
                    mma16816(acc[mt][nt], ah4[mt], bh2[nt]);
                    mma16816(acc[mt][nt], ah4[mt], bl2[nt]);
                    mma16816(acc[mt][nt], al4[mt], bh2[nt]);
                }
        }
    };

    LOADG(0);
    STORES(dsm);
    __syncthreads();
    const int NC = K >> 5;
    for (int c = 0; c < NC; c++) {
        if (c + 1 < NC) LOADG((c + 1) << 5);
        COMPUTE((uint32_t)(c & 1) * BUFSZ);
        if (c + 1 < NC) STORES(dsm + ((c + 1) & 1) * BUFSZ);
        __syncthreads();
    }

    // epilogue
    #pragma unroll
    for (int mt = 0; mt < 4; mt++) {
        int r0 = m0 + wm + mt * 16 + (lane >> 2);
        #pragma unroll
        for (int nt = 0; nt < 4; nt++) {
            int cc = n0 + wn + nt * 8 + (lane & 3) * 2;
            float* d = acc[mt][nt];
            #pragma unroll
            for (int hrow = 0; hrow < 2; hrow++) {
                int r = r0 + hrow * 8;
                float d0 = d[hrow*2], d1 = d[hrow*2 + 1];
                if (r >= count) continue;
                if (mode == 0) {
                    *(float2*)(C + (size_t)r * ldc + cc) = make_float2(d0, d1);
                } else if (mode == 1) {
                    float2 p = *(const float2*)(C + (size_t)r * ldc + cc);
                    *(float2*)(C + (size_t)r * ldc + cc) = make_float2(p.x + d0, p.y + d1);
                } else {
                    size_t o = (size_t)r * ldc + cc;
                    float2 u = *(const float2*)(U + o);
                    float h0 = (u.x / (1.f + expf(-u.x))) * d0;
                    float h1 = (u.y / (1.f + expf(-u.y))) * d1;
                    __nv_bfloat162 hh = __floats2bfloat162_rn(h0, h1);
                    __nv_bfloat162 ll = __floats2bfloat162_rn(h0 - __low2float(hh),
                                                              h1 - __high2float(hh));
                    *(__nv_bfloat162*)(Hh + o) = hh;
                    *(__nv_bfloat162*)(Hl + o) = ll;
                }
            }
        }
    }
}

// dense: grid (M/128, N/128)
__global__ __launch_bounds__(256, 1) void k_mma(
    const __nv_bfloat16* __restrict__ Ah, const __nv_bfloat16* __restrict__ Al,
    const float* __restrict__ B, float* __restrict__ C, int K, int ldb, int ldc, int mode)
{
    extern __shared__ __align__(16) char dsm[];
    uint32_t sb = smem_u32(dsm);
    mma_block(Ah, Al, nullptr, 1 << 30, B, ldb, K, C, ldc, mode,
              nullptr, nullptr, nullptr, blockIdx.x * 128, blockIdx.y * 128, dsm, sb);
}

// MoE: grid (16, ntiles, NE); which 0=u (X W1), 1=g (X W3 + fused silu), 2=down
__global__ __launch_bounds__(256, 1) void k_moe_mma(const float* __restrict__ W, int which)
{
    int e = blockIdx.z;
    int count = g_cnt[e];
    int m0 = blockIdx.x * 128;
    if (m0 >= count) return;
    int n0 = blockIdx.y * 128;
    extern __shared__ __align__(16) char dsm[];
    uint32_t sb = smem_u32(dsm);
    if (which == 0) {
        mma_block(g_ah, g_al, g_rows + e * T_, count, W + (size_t)e * D_ * F_, F_, D_,
                  g_ub + (size_t)e * T_ * F_, F_, 0, nullptr, nullptr, nullptr, m0, n0, dsm, sb);
    } else if (which == 1) {
        mma_block(g_ah, g_al, g_rows + e * T_, count, W + (size_t)e * D_ * F_, F_, D_,
                  nullptr, F_, 2, g_ub + (size_t)e * T_ * F_,
                  g_hbh + (size_t)e * T_ * F_, g_hbl + (size_t)e * T_ * F_, m0, n0, dsm, sb);
    } else {
        mma_block(g_hbh + (size_t)e * T_ * F_, g_hbl + (size_t)e * T_ * F_, nullptr, count,
                  W + (size_t)e * F_ * D_, D_, F_, g_yb + (size_t)e * T_ * D_, D_, 0,
                  nullptr, nullptr, nullptr, m0, n0, dsm, sb);
    }
}

// ---- split fp32 -> bf16 hi/lo ----
__global__ void k_split(const float* __restrict__ x,
                        __nv_bfloat16* __restrict__ hh, __nv_bfloat16* __restrict__ ll) {
    int i = blockIdx.x * 256 + threadIdx.x;   // over n/4
    float4 v = ((const float4*)x)[i];
    float xs[4] = {v.x, v.y, v.z, v.w};
    #pragma unroll
    for (int j = 0; j < 4; j += 2) {
        __nv_bfloat162 h2 = __floats2bfloat162_rn(xs[j], xs[j+1]);
        __nv_bfloat162 l2 = __floats2bfloat162_rn(xs[j] - __low2float(h2),
                                                  xs[j+1] - __high2float(h2));
        ((__nv_bfloat162*)hh)[i*2 + j/2] = h2;
        ((__nv_bfloat162*)ll)[i*2 + j/2] = l2;
    }
}

// ---------------- SIMT attention + misc ----------------
__device__ __forceinline__ void fma4x4(float (&acc)[4][4], float4 a, float4 b) {
    acc[0][0] += a.x*b.x; acc[0][1] += a.x*b.y; acc[0][2] += a.x*b.z; acc[0][3] += a.x*b.w;
    acc[1][0] += a.y*b.x; acc[1][1] += a.y*b.y; acc[1][2] += a.y*b.z; acc[1][3] += a.y*b.w;
    acc[2][0] += a.z*b.x; acc[2][1] += a.z*b.y; acc[2][2] += a.z*b.z; acc[2][3] += a.z*b.w;
    acc[3][0] += a.w*b.x; acc[3][1] += a.w*b.y; acc[3][2] += a.w*b.z; acc[3][3] += a.w*b.w;
}
__device__ __forceinline__ void storeT(float (&S)[16][64], int acol, int arow, float4 v) {
    S[acol+0][arow] = v.x; S[acol+1][arow] = v.y; S[acol+2][arow] = v.z; S[acol+3][arow] = v.w;
}
__global__ void k_zero_aux() { if (threadIdx.x == 0) g_aux[0] = 0.f; }
__global__ void k_zero_cnt() { if (threadIdx.x < NE) g_cnt[threadIdx.x] = 0; }
__global__ void k_embed(const int* __restrict__ ids, const float* __restrict__ ew) {
    int t = blockIdx.x;
    size_t r = (size_t)ids[t] * D_;
    for (int d = threadIdx.x; d < D_; d += blockDim.x) g_h[(size_t)t*D_ + d] = ew[r + d];
}
__global__ void k_rms(const float* __restrict__ x, const float* __restrict__ w, float* __restrict__ out) {
    int t = blockIdx.x, tid = threadIdx.x;
    __shared__ float sh[256];
    const float* xr = x + (size_t)t*D_;
    float s = 0.f;
    for (int d = tid; d < D_; d += 256) { float v = xr[d]; s += v*v; }
    sh[tid] = s; __syncthreads();
    for (int o = 128; o > 0; o >>= 1) { if (tid < o) sh[tid] += sh[tid+o]; __syncthreads(); }
    float scale = rsqrtf(sh[0] / (float)D_ + 1e-6f);
    float* orow = out + (size_t)t*D_;
    for (int d = tid; d < D_; d += 256) orow[d] = w[d] * xr[d] * scale;
}
__global__ void k_rope() {
    int t = blockIdx.x, tid = threadIdx.x;
    float p = (float)(t & (CH-1));
    if (tid < NH*32) {
        int h = tid >> 5, i = tid & 31;
        float ang = p * powf(1000000.0f, -(float)i/32.0f);
        float c = cosf(ang), s = sinf(ang);
        float* q = g_q + (size_t)t*D_ + h*64 + 2*i;
        float x1 = q[0], x2 = q[1];
        q[0] = x1*c - x2*s; q[1] = x1*s + x2*c;
    }
    if (tid < NKV*32) {
        int h = tid >> 5, i = tid & 31;
        float ang = p * powf(1000000.0f, -(float)i/32.0f);
        float c = cosf(ang), s = sinf(ang);
        float* kk = g_k + (size_t)t*256 + h*64 + 2*i;
        float x1 = kk[0], x2 = kk[1];
        kk[0] = x1*c - x2*s; kk[1] = x1*s + x2*c;
    }
}
__global__ void k_scores() {
    int b = blockIdx.z, chunk = b >> 4, head = b & 15, kvh = head >> 2;
    int qt = blockIdx.y, kt = blockIdx.x;
    const float* Q  = g_q + (size_t)chunk*CH*D_ + head*64;
    const float* Kp = g_k + (size_t)chunk*CH*256 + kvh*64;
    __shared__ __align__(16) float As[16][64];
    __shared__ __align__(16) float Bs[16][64];
    int tid = threadIdx.x, tx = tid & 15, ty = tid >> 4;
    int arow = tid >> 2, acol = (tid & 3) * 4;
    float acc[4][4] = {};
    for (int k0 = 0; k0 < 64; k0 += 16) {
        float4 av = *(const float4*)(Q  + (size_t)(qt*64+arow)*D_  + k0 + acol);
        float4 bv = *(const float4*)(Kp + (size_t)(kt*64+arow)*256 + k0 + acol);
        storeT(As, acol, arow, av);
        storeT(Bs, acol, arow, bv);
        __syncthreads();
        #pragma unroll
        for (int k = 0; k < 16; k++) fma4x4(acc, *(float4*)&As[k][ty*4], *(float4*)&Bs[k][tx*4]);
        __syncthreads();
    }
    float* S = g_sc + (size_t)b*CH*CH;
    #pragma unroll
    for (int i = 0; i < 4; i++) {
        int qg = qt*64 + ty*4 + i;
        #pragma unroll
        for (int j = 0; j < 4; j++) {
            int kg = kt*64 + tx*4 + j;
            float v = acc[i][j] * 0.125f;
            if (kg > qg) v = -1e30f;
            S[(size_t)qg*CH + kg] = v;
        }
    }
}
__global__ void k_softmax() {
    size_t row = blockIdx.x;
    int tid = threadIdx.x;
    float* r = g_sc + row*CH;
    __shared__ float sh[256];
    float v0 = r[tid], v1 = r[tid+256];
    sh[tid] = fmaxf(v0, v1); __syncthreads();
    for (int o = 128; o > 0; o >>= 1) { if (tid < o) sh[tid] = fmaxf(sh[tid], sh[tid+o]); __syncthreads(); }
    float m = sh[0]; __syncthreads();
    float e0 = expf(v0 - m), e1 = expf(v1 - m);
    sh[tid] = e0 + e1; __syncthreads();
    for (int o = 128; o > 0; o >>= 1) { if (tid < o) sh[tid] += sh[tid+o]; __syncthreads(); }
    float inv = 1.f / sh[0];
    r[tid] = e0*inv; r[tid+256] = e1*inv;
}
__global__ void k_av() {
    int b = blockIdx.z, chunk = b >> 4, head = b & 15, kvh = head >> 2;
    const float* A = g_sc + (size_t)b*CH*CH;
    const float* B = g_v + (size_t)chunk*CH*256 + kvh*64;
    float* C = g_attn + (size_t)chunk*CH*D_ + head*64;
    int bm = blockIdx.y * 64;
    __shared__ __align__(16) float As[16][64];
    __shared__ __align__(16) float Bs[16][64];
    int tid = threadIdx.x, tx = tid & 15, ty = tid >> 4;
    int arow = tid >> 2, acol = (tid & 3) * 4;
    int brow = tid >> 4, bcol = (tid & 15) * 4;
    float acc[4][4] = {};
    for (int k0 = 0; k0 < CH; k0 += 16) {
        storeT(As, acol, arow, *(const float4*)(A + (size_t)(bm+arow)*CH + k0 + acol));
        *(float4*)&Bs[brow][bcol] = *(const float4*)(B + (size_t)(k0+brow)*256 + bcol);
        __syncthreads();
        #pragma unroll
        for (int k = 0; k < 16; k++) fma4x4(acc, *(float4*)&As[k][ty*4], *(float4*)&Bs[k][tx*4]);
        __syncthreads();
    }
    #pragma unroll
    for (int i = 0; i < 4; i++)
        #pragma unroll
        for (int j = 0; j < 4; j++)
            C[(size_t)(bm + ty*4 + i)*D_ + tx*4 + j] = acc[i][j];
}
__global__ void k_router(const float* __restrict__ rw) {
    int tid = threadIdx.x, lane = tid & 31, w = tid >> 5;
    int t = blockIdx.x*8 + w;
    const float* xr = g_xn + (size_t)t*D_;
    float acc[NE] = {};
    for (int dd = 0; dd < 32; dd++) {
        int d = dd*32 + lane;
        float x = xr[d];
        const float* rr = rw + (size_t)d*NE;
        #pragma unroll
        for (int e = 0; e < NE; e++) acc[e] += x * rr[e];
    }
    #pragma unroll
    for (int e = 0; e < NE; e++)
        for (int o = 16; o > 0; o >>= 1) acc[e] += __shfl_down_sync(0xffffffffu, acc[e], o);
    if (lane == 0) {
        float m = acc[0];
        #pragma unroll
        for (int e = 1; e < NE; e++) m = fmaxf(m, acc[e]);
        float p[NE], s = 0.f;
        #pragma unroll
        for (int e = 0; e < NE; e++) { p[e] = expf(acc[e]-m); s += p[e]; }
        float inv = 1.f/s;
        #pragma unroll
        for (int e = 0; e < NE; e++) { p[e] *= inv; g_probs[(size_t)t*NE + e] = p[e]; }
        int i0 = 0;
        #pragma unroll
        for (int e = 1; e < NE; e++) if (p[e] > p[i0]) i0 = e;
        int i1 = (i0 == 0) ? 1 : 0;
        #pragma unroll
        for (int e = 0; e < NE; e++) if (e != i0 && p[e] > p[i1]) i1 = e;
        float ws = p[i0] + p[i1];
        g_ti[2*t] = i0; g_ti[2*t+1] = i1;
        g_tw[2*t] = p[i0]/ws; g_tw[2*t+1] = p[i1]/ws;
    }
}
__global__ void k_aux() {
    int tid = threadIdx.x;
    __shared__ float sh[256];
    __shared__ float totp[NE], totc[NE];
    float ps[NE] = {}, cs[NE] = {};
    for (int t = tid; t < T_; t += 256) {
        cs[g_ti[2*t]] += 1.f;
        #pragma unroll
        for (int e = 0; e < NE; e++) ps[e] += g_probs[(size_t)t*NE + e];
    }
    for (int e = 0; e < NE; e++) {
        sh[tid] = ps[e]; __syncthreads();
        for (int o = 128; o > 0; o >>= 1) { if (tid < o) sh[tid] += sh[tid+o]; __syncthreads(); }
        if (tid == 0) totp[e] = sh[0];
        __syncthreads();
        sh[tid] = cs[e]; __syncthreads();
        for (int o = 128; o > 0; o >>= 1) { if (tid < o) sh[tid] += sh[tid+o]; __syncthreads(); }
        if (tid == 0) totc[e] = sh[0];
        __syncthreads();
    }
    if (tid == 0) {
        float a = 0.f;
        for (int e = 0; e < NE; e++) a += (totc[e]/(float)T_) * (totp[e]/(float)T_);
        g_aux[0] += (float)NE * a;
    }
}
__global__ void k_bucket() {
    int t = blockIdx.x*256 + threadIdx.x;
    if (t >= T_) return;
    for (int j = 0; j < 2; j++) {
        int e = g_ti[2*t + j];
        int pos = atomicAdd(&g_cnt[e], 1);
        g_rows[e*T_ + pos] = t;
        g_slot[2*t + j] = e*T_ + pos;
    }
}
__global__ void k_combine() {
    int t = blockIdx.x, tid = threadIdx.x;
    int s0 = g_slot[2*t], s1 = g_slot[2*t+1];
    float w0 = g_tw[2*t], w1 = g_tw[2*t+1];
    const float* y0 = g_yb + (size_t)s0*D_;
    const float* y1 = g_yb + (size_t)s1*D_;
    float* hr = g_h + (size_t)t*D_;
    for (int d = tid; d < D_; d += 256) hr[d] += w0*y0[d] + w1*y1[d];
}
__global__ void k_task(const float* __restrict__ tw, const float* __restrict__ tb, float* __restrict__ out) {
    int c = blockIdx.x, tid = threadIdx.x;
    __shared__ float sh[256];
    float s = 0.f;
    for (int d = tid; d < D_; d += 256) s += g_xn[d] * tw[(size_t)d*16 + c];
    sh[tid] = s; __syncthreads();
    for (int o = 128; o > 0; o >>= 1) { if (tid < o) sh[tid] += sh[tid+o]; __syncthreads(); }
    if (tid == 0) out[OUT_TASK + c] = sh[0] + tb[c];
}
__global__ void k_mean() {
    int d = blockIdx.x*256 + threadIdx.x;
    float s = 0.f;
    for (int t = 0; t < T_; t++) s += g_xn[(size_t)t*D_ + d];
    g_xm[d] = s / (float)T_;
}
__global__ void k_eval(const float* __restrict__ ew, const float* __restrict__ eb, float* __restrict__ out) {
    int c = blockIdx.x, tid = threadIdx.x;
    __shared__ float sh[256];
    float s = 0.f;
    for (int d = tid; d < D_; d += 256) s += g_xm[d] * ew[(size_t)d*8 + c];
    sh[tid] = s; __syncthreads();
    for (int o = 128; o > 0; o >>= 1) { if (tid < o) sh[tid] += sh[tid+o]; __syncthreads(); }
    if (tid == 0) out[OUT_EVAL + c] = sh[0] + eb[c];
}
__global__ void k_auxw(float* __restrict__ out) { out[OUT_AUX] = g_aux[0]; }

// ---------------- launch ----------------
extern "C" void kernel_launch(void* const* d_in, const int* in_sizes, int n_in,
                              void* d_out, int out_size) {
    const int*   ids     = (const int*)  d_in[0];
    const float* embed_W = (const float*)d_in[1];
    const float* n1      = (const float*)d_in[2];
    const float* n2      = (const float*)d_in[3];
    const float* wq      = (const float*)d_in[4];
    const float* wk      = (const float*)d_in[5];
    const float* wv      = (const float*)d_in[6];
    const float* wo      = (const float*)d_in[7];
    const float* rw      = (const float*)d_in[8];
    const float* w1      = (const float*)d_in[9];
    const float* w3      = (const float*)d_in[10];
    const float* w2      = (const float*)d_in[11];
    const float* normf   = (const float*)d_in[12];
    const float* lm      = (const float*)d_in[13];
    const float* tw      = (const float*)d_in[14];
    const float* tb      = (const float*)d_in[15];
    const float* ew      = (const float*)d_in[16];
    const float* eb      = (const float*)d_in[17];
    float* out = (float*)d_out;

    float *p_h, *p_xn, *p_q, *p_k, *p_v, *p_attn;
    __nv_bfloat16 *p_ah, *p_al;
    cudaGetSymbolAddress((void**)&p_h,    g_h);
    cudaGetSymbolAddress((void**)&p_xn,   g_xn);
    cudaGetSymbolAddress((void**)&p_q,    g_q);
    cudaGetSymbolAddress((void**)&p_k,    g_k);
    cudaGetSymbolAddress((void**)&p_v,    g_v);
    cudaGetSymbolAddress((void**)&p_attn, g_attn);
    cudaGetSymbolAddress((void**)&p_ah,   g_ah);
    cudaGetSymbolAddress((void**)&p_al,   g_al);

    cudaFuncSetAttribute(k_mma,     cudaFuncAttributeMaxDynamicSharedMemorySize, SMEM_MMA);
    cudaFuncSetAttribute(k_moe_mma, cudaFuncAttributeMaxDynamicSharedMemorySize, SMEM_MMA);

    const int NSPLIT = T_*D_/4/256;

    k_zero_aux<<<1, 32>>>();
    k_embed<<<T_, 256>>>(ids, embed_W);

    for (int l = 0; l < NL; l++) {
        // attention
        k_rms<<<T_, 256>>>(p_h, n1 + (size_t)l*D_, p_xn);
        k_split<<<NSPLIT, 256>>>(p_xn, p_ah, p_al);
        k_mma<<<dim3(16, 8), 256, SMEM_MMA>>>(p_ah, p_al, wq + (size_t)l*D_*D_,  p_q, D_, D_,  D_,  0);
        k_mma<<<dim3(16, 2), 256, SMEM_MMA>>>(p_ah, p_al, wk + (size_t)l*D_*256, p_k, D_, 256, 256, 0);
        k_mma<<<dim3(16, 2), 256, SMEM_MMA>>>(p_ah, p_al, wv + (size_t)l*D_*256, p_v, D_, 256, 256, 0);
        k_rope<<<T_, 512>>>();
        k_scores<<<dim3(8, 8, NCK*NH), 256>>>();
        k_softmax<<<NCK*NH*CH, 256>>>();
        k_av<<<dim3(1, 8, NCK*NH), 256>>>();
        k_split<<<NSPLIT, 256>>>(p_attn, p_ah, p_al);
        k_mma<<<dim3(16, 8), 256, SMEM_MMA>>>(p_ah, p_al, wo + (size_t)l*D_*D_, p_h, D_, D_, D_, 1);

        // MoE
        k_rms<<<T_, 256>>>(p_h, n2 + (size_t)l*D_, p_xn);
        k_split<<<NSPLIT, 256>>>(p_xn, p_ah, p_al);
        k_router<<<T_/8, 256>>>(rw + (size_t)l*D_*NE);
        k_aux<<<1, 256>>>();
        k_zero_cnt<<<1, 32>>>();
        k_bucket<<<T_/256, 256>>>();
        k_moe_mma<<<dim3(16, 16, NE), 256, SMEM_MMA>>>(w1 + (size_t)l*NE*D_*F_, 0);
        k_moe_mma<<<dim3(16, 16, NE), 256, SMEM_MMA>>>(w3 + (size_t)l*NE*D_*F_, 1);
        k_moe_mma<<<dim3(16, 8,  NE), 256, SMEM_MMA>>>(w2 + (size_t)l*NE*F_*D_, 2);
        k_combine<<<T_, 256>>>();
    }

    // final norm + heads
    k_rms<<<T_, 256>>>(p_h, normf, p_xn);
    k_split<<<NSPLIT, 256>>>(p_xn, p_ah, p_al);
    k_mma<<<dim3(16, NV/128), 256, SMEM_MMA>>>(p_ah, p_al, lm, out, D_, NV, NV, 0);
    k_task<<<16, 256>>>(tw, tb, out);
    k_mean<<<D_/256, 256>>>();
    k_eval<<<8, 256>>>(ew, eb, out);
    k_auxw<<<1, 1>>>(out);
}

// round 9
// speedup vs baseline: 2.2279x; 1.0251x over previous
#include <cuda_runtime.h>
#include <cuda_bf16.h>
#include <math.h>
#include <stdint.h>

#define T_   2048
#define D_   1024
#define NH   16
#define NKV  4
#define F_   2048
#define NE   8
#define NL   2
#define NV   32000
#define CH   512
#define NCK  4
#define QKV_ 1536

#define OUT_TASK   (T_*(size_t)NV)
#define OUT_EVAL   (OUT_TASK + 16)
#define OUT_AUX    (OUT_EVAL + 8)

typedef __nv_bfloat16 bf16;
typedef __nv_bfloat162 bf162;

// ---------------- scratch (device globals; no allocation) ----------------
__device__ float g_h   [(size_t)T_*D_];
__device__ float g_xn  [(size_t)T_*D_];
__device__ float g_qkv [(size_t)T_*QKV_];
__device__ float g_sc  [(size_t)NCK*NH*CH*CH];
__device__ float g_attn[(size_t)T_*D_];
__device__ float g_probs[(size_t)T_*NE];
__device__ int   g_ti  [T_*2];
__device__ float g_tw  [T_*2];
__device__ int   g_cnt [NE];
__device__ int   g_rows[NE*T_];
__device__ int   g_slot[T_*2];
__device__ float g_yb  [(size_t)NE*T_*D_];
__device__ float g_aux [1];
__device__ float g_xm  [D_];
__device__ float g_mp  [16*D_];
__device__ bf16  g_ah  [(size_t)T_*D_];
__device__ bf16  g_al  [(size_t)T_*D_];
__device__ bf16  g_qkvh[(size_t)T_*QKV_];
__device__ bf16  g_qkvl[(size_t)T_*QKV_];
__device__ float g_ub  [(size_t)NE*T_*F_];
__device__ bf16  g_hbh [(size_t)NE*T_*F_];   // also reused as P-split hi
__device__ bf16  g_hbl [(size_t)NE*T_*F_];   // also reused as P-split lo
// pre-converted weights (hi/lo bf16)
__device__ bf16  c_qkvh[(size_t)NL*D_*QKV_], c_qkvl[(size_t)NL*D_*QKV_];
__device__ bf16  c_woh [(size_t)NL*D_*D_],   c_wol [(size_t)NL*D_*D_];
__device__ bf16  c_w1h [(size_t)NL*NE*D_*F_], c_w1l[(size_t)NL*NE*D_*F_];
__device__ bf16  c_w3h [(size_t)NL*NE*D_*F_], c_w3l[(size_t)NL*NE*D_*F_];
__device__ bf16  c_w2h [(size_t)NL*NE*F_*D_], c_w2l[(size_t)NL*NE*F_*D_];
__device__ bf16  c_lmh [(size_t)D_*NV],      c_lml[(size_t)D_*NV];

// ---------------- asm helpers ----------------
__device__ __forceinline__ uint32_t smem_u32(const void* p) {
    uint32_t a;
    asm("{ .reg .u64 t; cvta.to.shared.u64 t, %1; cvt.u32.u64 %0, t; }" : "=r"(a) : "l"(p));
    return a;
}
__device__ __forceinline__ void cpa(uint32_t d, const void* s) {
    asm volatile("cp.async.cg.shared.global [%0], [%1], 16;" :: "r"(d), "l"(s));
}
__device__ __forceinline__ void cp_commit() { asm volatile("cp.async.commit_group;" ::: "memory"); }
__device__ __forceinline__ void cp_wait1()  { asm volatile("cp.async.wait_group 1;" ::: "memory"); }
__device__ __forceinline__ void cp_wait0()  { asm volatile("cp.async.wait_group 0;" ::: "memory"); }
__device__ __forceinline__ void ldsm4(uint32_t (&r)[4], uint32_t a) {
    asm volatile("ldmatrix.sync.aligned.m8n8.x4.shared.b16 {%0,%1,%2,%3}, [%4];"
        : "=r"(r[0]), "=r"(r[1]), "=r"(r[2]), "=r"(r[3]) : "r"(a));
}
__device__ __forceinline__ void ldsm2t(uint32_t (&r)[2], uint32_t a) {
    asm volatile("ldmatrix.sync.aligned.m8n8.x2.trans.shared.b16 {%0,%1}, [%2];"
        : "=r"(r[0]), "=r"(r[1]) : "r"(a));
}
__device__ __forceinline__ void ldsm2(uint32_t (&r)[2], uint32_t a) {
    asm volatile("ldmatrix.sync.aligned.m8n8.x2.shared.b16 {%0,%1}, [%2];"
        : "=r"(r[0]), "=r"(r[1]) : "r"(a));
}
__device__ __forceinline__ void mma16816(float (&d)[4], const uint32_t (&a)[4], const uint32_t (&b)[2]) {
    asm volatile("mma.sync.aligned.m16n8k16.row.col.f32.bf16.bf16.f32 "
        "{%0,%1,%2,%3}, {%4,%5,%6,%7}, {%8,%9}, {%0,%1,%2,%3};"
        : "+f"(d[0]), "+f"(d[1]), "+f"(d[2]), "+f"(d[3])
        : "r"(a[0]), "r"(a[1]), "r"(a[2]), "r"(a[3]), "r"(b[0]), "r"(b[1]));
}

// SMEM per buffer: Ah 128x80B @0 | Al @10240 | Bh 32x272B @20480 | Bl @29184
#define OFF_AL 10240
#define OFF_BH 20480
#define OFF_BL 29184
#define BUFSZ  37888
#define SMEM_MMA (2*BUFSZ)

// modes: 0 = C=acc, 1 = C+=acc, 2 = silu(U)*acc -> split bf16 to Hh/Hl
__device__ __forceinline__ void mma_block(
    const bf16* __restrict__ Ah, const bf16* __restrict__ Al, int lda,
    const int* __restrict__ rows, int count, int m0,
    const bf16* __restrict__ Bh, const bf16* __restrict__ Bl, int ldb, int n0, int nlim,
    int K, float* __restrict__ C, int ldc, int mode,
    const float* __restrict__ U, bf16* __restrict__ Hh, bf16* __restrict__ Hl,
    char* dsm, uint32_t sb)
{
    const int tid = threadIdx.x, lane = tid & 31, wid = tid >> 5;
    const int wm = (wid & 1) * 64, wn = (wid >> 1) * 32;
    const int ar = tid >> 1, akc = (tid & 1) * 16;
    const int bkr = tid >> 3, bn16 = (tid & 7) * 16;
    const int gm = m0 + ar;
    const bool av = gm < count;
    const bf16 *pAh = nullptr, *pAl = nullptr;
    if (av) {
        size_t rr = (size_t)(rows ? rows[gm] : gm) * lda + akc;
        pAh = Ah + rr; pAl = Al + rr;
    }
    const int bcol = (nlim < 128) ? (bn16 & (nlim - 1)) : bn16;
    const bf16* pBh = Bh + (size_t)bkr * ldb + n0 + bcol;
    const bf16* pBl = Bl + (size_t)bkr * ldb + n0 + bcol;
    const uint32_t ao = (uint32_t)ar * 80 + (uint32_t)akc * 2;
    const uint32_t bo = (uint32_t)OFF_BH + (uint32_t)bkr * 272 + (uint32_t)bn16 * 2;

    if (!av) {
        uint4 z = make_uint4(0,0,0,0);
        #pragma unroll
        for (int s = 0; s < 2; s++) {
            char* bb = dsm + s * BUFSZ;
            *(uint4*)(bb + ao) = z;            *(uint4*)(bb + ao + 16) = z;
            *(uint4*)(bb + OFF_AL + ao) = z;   *(uint4*)(bb + OFF_AL + ao + 16) = z;
        }
    }

    float acc[4][4][4];
    #pragma unroll
    for (int a = 0; a < 4; a++)
        #pragma unroll
        for (int b = 0; b < 4; b++)
            #pragma unroll
            for (int c = 0; c < 4; c++) acc[a][b][c] = 0.f;

    auto ISSUE = [&](int k0, uint32_t sbuf) {
        if (av) {
            cpa(sbuf + ao,               pAh + k0);
            cpa(sbuf + ao + 16,          pAh + k0 + 8);
            cpa(sbuf + OFF_AL + ao,      pAl + k0);
            cpa(sbuf + OFF_AL + ao + 16, pAl + k0 + 8);
        }
        const bf16* b = pBh + (size_t)k0 * ldb;
        cpa(sbuf + bo,      b);
        cpa(sbuf + bo + 16, b + 8);
        b = pBl + (size_t)k0 * ldb;
        cpa(sbuf + (OFF_BL - OFF_BH) + bo,      b);
        cpa(sbuf + (OFF_BL - OFF_BH) + bo + 16, b + 8);
    };

    auto COMPUTE = [&](uint32_t boff) {
        uint32_t abase = sb + boff + (uint32_t)(wm + (lane & 15)) * 80 + ((lane >> 4) * 8) * 2;
        uint32_t bbase = sb + boff + OFF_BH
                       + (uint32_t)((lane & 7) + ((lane >> 3) & 1) * 8) * 272
                       + (uint32_t)wn * 2;
        #pragma unroll
        for (int ks = 0; ks < 2; ks++) {
            uint32_t ah4[4][4], al4[4][4], bh2[4][2], bl2[4][2];
            #pragma unroll
            for (int mt = 0; mt < 4; mt++) {
                uint32_t aa = abase + mt * (16 * 80) + ks * 32;
                ldsm4(ah4[mt], aa);
                ldsm4(al4[mt], aa + OFF_AL);
            }
            #pragma unroll
            for (int nt = 0; nt < 4; nt++) {
                uint32_t ba = bbase + ks * (16 * 272) + nt * 16;
                ldsm2t(bh2[nt], ba);
                ldsm2t(bl2[nt], ba + (OFF_BL - OFF_BH));
            }
            #pragma unroll
            for (int mt = 0; mt < 4; mt++)
                #pragma unroll
                for (int nt = 0; nt < 4; nt++) {
                    mma16816(acc[mt][nt], ah4[mt], bh2[nt]);
                    mma16816(acc[mt][nt], ah4[mt], bl2[nt]);
                    mma16816(acc[mt][nt], al4[mt], bh2[nt]);
                }
        }
    };

    const int NC = K >> 5;
    ISSUE(0, sb); cp_commit();
    for (int c = 0; c < NC; c++) {
        if (c + 1 < NC) { ISSUE((c + 1) << 5, sb + (uint32_t)((c + 1) & 1) * BUFSZ); cp_commit(); cp_wait1(); }
        else cp_wait0();
        __syncthreads();
        COMPUTE((uint32_t)(c & 1) * BUFSZ);
        __syncthreads();
    }

    #pragma unroll
    for (int mt = 0; mt < 4; mt++) {
        int r0 = m0 + wm + mt * 16 + (lane >> 2);
        #pragma unroll
        for (int nt = 0; nt < 4; nt++) {
            int ln = wn + nt * 8 + (lane & 3) * 2;
            if (ln >= nlim) continue;
            int cc = n0 + ln;
            float* d = acc[mt][nt];
            #pragma unroll
            for (int hrow = 0; hrow < 2; hrow++) {
                int r = r0 + hrow * 8;
                if (r >= count) continue;
                float d0 = d[hrow*2], d1 = d[hrow*2 + 1];
                size_t o = (size_t)r * ldc + cc;
                if (mode == 0) {
                    *(float2*)(C + o) = make_float2(d0, d1);
                } else if (mode == 1) {
                    float2 p = *(const float2*)(C + o);
                    *(float2*)(C + o) = make_float2(p.x + d0, p.y + d1);
                } else {
                    float2 u = *(const float2*)(U + o);
                    float h0 = (u.x / (1.f + expf(-u.x))) * d0;
                    float h1 = (u.y / (1.f + expf(-u.y))) * d1;
                    bf162 hh = __floats2bfloat162_rn(h0, h1);
                    bf162 ll = __floats2bfloat162_rn(h0 - __low2float(hh), h1 - __high2float(hh));
                    *(bf162*)(Hh + o) = hh;
                    *(bf162*)(Hl + o) = ll;
                }
            }
        }
    }
}

// dense GEMM: grid (M/128, N/128)
__global__ __launch_bounds__(256, 1) void k_mma(
    const bf16* __restrict__ Ah, const bf16* __restrict__ Al,
    const bf16* __restrict__ Bh, const bf16* __restrict__ Bl,
    float* __restrict__ C, int K, int ldb, int ldc, int mode)
{
    extern __shared__ __align__(16) char dsm[];
    mma_block(Ah, Al, K, nullptr, 1 << 30, blockIdx.x * 128,
              Bh, Bl, ldb, blockIdx.y * 128, 128,
              K, C, ldc, mode, nullptr, nullptr, nullptr, dsm, smem_u32(dsm));
}

// MoE: which 0 = X W1 -> g_ub; 1 = X W3 fused silu -> hidden split; 2 = H W2 -> g_yb
__global__ __launch_bounds__(256, 1) void k_moe_mma(
    const bf16* __restrict__ Wh, const bf16* __restrict__ Wl, int which)
{
    int e = blockIdx.z;
    int count = g_cnt[e];
    int m0 = blockIdx.x * 128;
    if (m0 >= count) return;
    int n0 = blockIdx.y * 128;
    extern __shared__ __align__(16) char dsm[];
    uint32_t sb = smem_u32(dsm);
    if (which == 0) {
        mma_block(g_ah, g_al, D_, g_rows + e * T_, count, m0,
                  Wh + (size_t)e * D_ * F_, Wl + (size_t)e * D_ * F_, F_, n0, 128,
                  D_, g_ub + (size_t)e * T_ * F_, F_, 0, nullptr, nullptr, nullptr, dsm, sb);
    } else if (which == 1) {
        mma_block(g_ah, g_al, D_, g_rows + e * T_, count, m0,
                  Wh + (size_t)e * D_ * F_, Wl + (size_t)e * D_ * F_, F_, n0, 128,
                  D_, nullptr, F_, 2, g_ub + (size_t)e * T_ * F_,
                  g_hbh + (size_t)e * T_ * F_, g_hbl + (size_t)e * T_ * F_, dsm, sb);
    } else {
        mma_block(g_hbh + (size_t)e * T_ * F_, g_hbl + (size_t)e * T_ * F_, F_, nullptr, count, m0,
                  Wh + (size_t)e * F_ * D_, Wl + (size_t)e * F_ * D_, D_, n0, 128,
                  F_, g_yb + (size_t)e * T_ * D_, D_, 0, nullptr, nullptr, nullptr, dsm, sb);
    }
}

// O = P V: grid (4, 1, 64); P split lives in g_hbh/g_hbl
__global__ __launch_bounds__(256, 1) void k_avm()
{
    int b = blockIdx.z, chunk = b >> 4, head = b & 15, kvh = head >> 2;
    extern __shared__ __align__(16) char dsm[];
    mma_block(g_hbh + (size_t)b * CH * CH, g_hbl + (size_t)b * CH * CH, CH, nullptr, CH, blockIdx.x * 128,
              g_qkvh + (size_t)chunk * CH * QKV_ + 1280 + kvh * 64,
              g_qkvl + (size_t)chunk * CH * QKV_ + 1280 + kvh * 64, QKV_, 0, 64,
              CH, g_attn + (size_t)chunk * CH * D_ + head * 64, D_, 0,
              nullptr, nullptr, nullptr, dsm, smem_u32(dsm));
}

// ---------------- scores S = Q K^T (both k-contiguous): grid (4, 4, 64) ----------------
#define QK_AL 10240
#define QK_KH 20480
#define QK_KL 30720
#define QK_BUF 40960
#define SMEM_QK (2*QK_BUF)

__global__ __launch_bounds__(256, 1) void k_qk()
{
    extern __shared__ __align__(16) char dsm[];
    uint32_t sb = smem_u32(dsm);
    int b = blockIdx.z, chunk = b >> 4, head = b & 15, kvh = head >> 2;
    int m0 = blockIdx.x * 128, n0 = blockIdx.y * 128;
    int tid = threadIdx.x, lane = tid & 31, wid = tid >> 5;
    int wm = (wid & 1) * 64, wn = (wid >> 1) * 32;
    int ar = tid >> 1, akc = (tid & 1) * 16;
    const bf16* pQh = g_qkvh + (size_t)(chunk*CH + m0 + ar) * QKV_ + head * 64 + akc;
    const bf16* pQl = g_qkvl + (size_t)(chunk*CH + m0 + ar) * QKV_ + head * 64 + akc;
    const bf16* pKh = g_qkvh + (size_t)(chunk*CH + n0 + ar) * QKV_ + 1024 + kvh * 64 + akc;
    const bf16* pKl = g_qkvl + (size_t)(chunk*CH + n0 + ar) * QKV_ + 1024 + kvh * 64 + akc;
    const uint32_t ao = (uint32_t)ar * 80 + (uint32_t)akc * 2;

    float acc[4][4][4];
    #pragma unroll
    for (int a = 0; a < 4; a++)
        #pragma unroll
        for (int bb = 0; bb < 4; bb++)
            #pragma unroll
            for (int c = 0; c < 4; c++) acc[a][bb][c] = 0.f;

    auto ISSUE = [&](int k0, uint32_t sbuf) {
        cpa(sbuf + ao,               pQh + k0); cpa(sbuf + ao + 16,           pQh + k0 + 8);
        cpa(sbuf + QK_AL + ao,       pQl + k0); cpa(sbuf + QK_AL + ao + 16,   pQl + k0 + 8);
        cpa(sbuf + QK_KH + ao,       pKh + k0); cpa(sbuf + QK_KH + ao + 16,   pKh + k0 + 8);
        cpa(sbuf + QK_KL + ao,       pKl + k0); cpa(sbuf + QK_KL + ao + 16,   pKl + k0 + 8);
    };
    auto COMPUTE = [&](uint32_t boff) {
        uint32_t abase = sb + boff + (uint32_t)(wm + (lane & 15)) * 80 + ((lane >> 4) * 8) * 2;
        #pragma unroll
        for (int ks = 0; ks < 2; ks++) {
            uint32_t ah4[4][4], al4[4][4], bh2[4][2], bl2[4][2];
            #pragma unroll
            for (int mt = 0; mt < 4; mt++) {
                uint32_t aa = abase + mt * (16 * 80) + ks * 32;
                ldsm4(ah4[mt], aa);
                ldsm4(al4[mt], aa + QK_AL);
            }
            #pragma unroll
            for (int nt = 0; nt < 4; nt++) {
                uint32_t ba = sb + boff + QK_KH
                            + (uint32_t)(wn + nt * 8 + (lane & 7)) * 80
                            + ks * 32 + ((lane >> 3) & 1) * 16;
                ldsm2(bh2[nt], ba);
                ldsm2(bl2[nt], ba + (QK_KL - QK_KH));
            }
            #pragma unroll
            for (int mt = 0; mt < 4; mt++)
                #pragma unroll
                for (int nt = 0; nt < 4; nt++) {
                    mma16816(acc[mt][nt], ah4[mt], bh2[nt]);
                    mma16816(acc[mt][nt], ah4[mt], bl2[nt]);
                    mma16816(acc[mt][nt], al4[mt], bh2[nt]);
                }
        }
    };

    ISSUE(0, sb); cp_commit();
    for (int c = 0; c < 2; c++) {
        if (c == 0) { ISSUE(32, sb + BUFSZ > 0 ? sb + QK_BUF : sb); cp_commit(); cp_wait1(); }
        else cp_wait0();
        __syncthreads();
        COMPUTE((uint32_t)c * QK_BUF);
        __syncthreads();
    }

    float* S = g_sc + (size_t)b * CH * CH;
    #pragma unroll
    for (int mt = 0; mt < 4; mt++) {
        int r0 = wm + mt * 16 + (lane >> 2);
        #pragma unroll
        for (int nt = 0; nt < 4; nt++) {
            int c0 = wn + nt * 8 + (lane & 3) * 2;
            float* d = acc[mt][nt];
            #pragma unroll
            for (int hrow = 0; hrow < 2; hrow++) {
                int qg = m0 + r0 + hrow * 8;
                int kg = n0 + c0;
                float v0 = d[hrow*2] * 0.125f, v1 = d[hrow*2 + 1] * 0.125f;
                if (kg > qg)     v0 = -1e30f;
                if (kg + 1 > qg) v1 = -1e30f;
                *(float2*)(S + (size_t)qg * CH + kg) = make_float2(v0, v1);
            }
        }
    }
}

// ---- fp32 -> bf16 hi/lo (linear) ----
__global__ void k_split(const float* __restrict__ x, bf16* __restrict__ hh, bf16* __restrict__ ll) {
    size_t i = (size_t)blockIdx.x * 256 + threadIdx.x;
    float4 v = ((const float4*)x)[i];
    bf162 h0 = __floats2bfloat162_rn(v.x, v.y);
    bf162 l0 = __floats2bfloat162_rn(v.x - __low2float(h0), v.y - __high2float(h0));
    bf162 h1 = __floats2bfloat162_rn(v.z, v.w);
    bf162 l1 = __floats2bfloat162_rn(v.z - __low2float(h1), v.w - __high2float(h1));
    ((bf162*)hh)[i*2]   = h0; ((bf162*)hh)[i*2+1] = h1;
    ((bf162*)ll)[i*2]   = l0; ((bf162*)ll)[i*2+1] = l1;
}
// strided (for packing wq/wk/wv into [K,1536])
__global__ void k_convs(const float* __restrict__ src, bf16* __restrict__ h, bf16* __restrict__ l,
                        int N, int ldd) {
    size_t i = (size_t)blockIdx.x * 256 + threadIdx.x;
    size_t e = i * 4;
    int r = (int)(e / N), c = (int)(e % N);
    float4 v = *(const float4*)(src + e);
    size_t o = (size_t)r * ldd + c;
    bf162 h0 = __floats2bfloat162_rn(v.x, v.y);
    bf162 l0 = __floats2bfloat162_rn(v.x - __low2float(h0), v.y - __high2float(h0));
    bf162 h1 = __floats2bfloat162_rn(v.z, v.w);
    bf162 l1 = __floats2bfloat162_rn(v.z - __low2float(h1), v.w - __high2float(h1));
    *(bf162*)(h+o) = h0; *(bf162*)(h+o+2) = h1;
    *(bf162*)(l+o) = l0; *(bf162*)(l+o+2) = l1;
}

// ---------------- misc kernels ----------------
__global__ void k_zero_aux() { if (threadIdx.x == 0) g_aux[0] = 0.f; }
__global__ void k_zero_cnt() { if (threadIdx.x < NE) g_cnt[threadIdx.x] = 0; }
__global__ void k_embed(const int* __restrict__ ids, const float* __restrict__ ew) {
    int t = blockIdx.x;
    size_t r = (size_t)ids[t] * D_;
    for (int d = threadIdx.x; d < D_; d += blockDim.x) g_h[(size_t)t*D_ + d] = ew[r + d];
}
__global__ void k_rms(const float* __restrict__ x, const float* __restrict__ w, float* __restrict__ out) {
    int t = blockIdx.x, tid = threadIdx.x;
    __shared__ float sh[256];
    const float* xr = x + (size_t)t*D_;
    float s = 0.f;
    for (int d = tid; d < D_; d += 256) { float v = xr[d]; s += v*v; }
    sh[tid] = s; __syncthreads();
    for (int o = 128; o > 0; o >>= 1) { if (tid < o) sh[tid] += sh[tid+o]; __syncthreads(); }
    float scale = rsqrtf(sh[0] / (float)D_ + 1e-6f);
    float* orow = out + (size_t)t*D_;
    for (int d = tid; d < D_; d += 256) orow[d] = w[d] * xr[d] * scale;
}
__global__ void k_rope() {
    int t = blockIdx.x, tid = threadIdx.x;
    float p = (float)(t & (CH-1));
    float* base = g_qkv + (size_t)t*QKV_;
    if (tid < NH*32) {
        int h = tid >> 5, i = tid & 31;
        float ang = p * powf(1000000.0f, -(float)i/32.0f);
        float c = cosf(ang), s = sinf(ang);
        float* q = base + h*64 + 2*i;
        float x1 = q[0], x2 = q[1];
        q[0] = x1*c - x2*s; q[1] = x1*s + x2*c;
    }
    if (tid < NKV*32) {
        int h = tid >> 5, i = tid & 31;
        float ang = p * powf(1000000.0f, -(float)i/32.0f);
        float c = cosf(ang), s = sinf(ang);
        float* kk = base + 1024 + h*64 + 2*i;
        float x1 = kk[0], x2 = kk[1];
        kk[0] = x1*c - x2*s; kk[1] = x1*s + x2*c;
    }
}
__global__ void k_softmax() {
    size_t row = blockIdx.x;
    int tid = threadIdx.x;
    float* r = g_sc + row*CH;
    __shared__ float sh[256];
    float v0 = r[tid], v1 = r[tid+256];
    sh[tid] = fmaxf(v0, v1); __syncthreads();
    for (int o = 128; o > 0; o >>= 1) { if (tid < o) sh[tid] = fmaxf(sh[tid], sh[tid+o]); __syncthreads(); }
    float m = sh[0]; __syncthreads();
    float e0 = expf(v0 - m), e1 = expf(v1 - m);
    sh[tid] = e0 + e1; __syncthreads();
    for (int o = 128; o > 0; o >>= 1) { if (tid < o) sh[tid] += sh[tid+o]; __syncthreads(); }
    float inv = 1.f / sh[0];
    r[tid] = e0*inv; r[tid+256] = e1*inv;
}
__global__ void k_router(const float* __restrict__ rw) {
    int tid = threadIdx.x, lane = tid & 31, w = tid >> 5;
    int t = blockIdx.x*8 + w;
    const float* xr = g_xn + (size_t)t*D_;
    float acc[NE] = {};
    for (int dd = 0; dd < 32; dd++) {
        int d = dd*32 + lane;
        float x = xr[d];
        const float* rr = rw + (size_t)d*NE;
        #pragma unroll
        for (int e = 0; e < NE; e++) acc[e] += x * rr[e];
    }
    #pragma unroll
    for (int e = 0; e < NE; e++)
        for (int o = 16; o > 0; o >>= 1) acc[e] += __shfl_down_sync(0xffffffffu, acc[e], o);
    if (lane == 0) {
        float m = acc[0];
        #pragma unroll
        for (int e = 1; e < NE; e++) m = fmaxf(m, acc[e]);
        float p[NE], s = 0.f;
        #pragma unroll
        for (int e = 0; e < NE; e++) { p[e] = expf(acc[e]-m); s += p[e]; }
        float inv = 1.f/s;
        #pragma unroll
        for (int e = 0; e < NE; e++) { p[e] *= inv; g_probs[(size_t)t*NE + e] = p[e]; }
        int i0 = 0;
        #pragma unroll
        for (int e = 1; e < NE; e++) if (p[e] > p[i0]) i0 = e;
        int i1 = (i0 == 0) ? 1 : 0;
        #pragma unroll
        for (int e = 0; e < NE; e++) if (e != i0 && p[e] > p[i1]) i1 = e;
        float ws = p[i0] + p[i1];
        g_ti[2*t] = i0; g_ti[2*t+1] = i1;
        g_tw[2*t] = p[i0]/ws; g_tw[2*t+1] = p[i1]/ws;
    }
}
__global__ void k_aux() {
    int tid = threadIdx.x;
    __shared__ float sh[256];
    __shared__ float totp[NE], totc[NE];
    float ps[NE] = {}, cs[NE] = {};
    for (int t = tid; t < T_; t += 256) {
        cs[g_ti[2*t]] += 1.f;
        #pragma unroll
        for (int e = 0; e < NE; e++) ps[e] += g_probs[(size_t)t*NE + e];
    }
    for (int e = 0; e < NE; e++) {
        sh[tid] = ps[e]; __syncthreads();
        for (int o = 128; o > 0; o >>= 1) { if (tid < o) sh[tid] += sh[tid+o]; __syncthreads(); }
        if (tid == 0) totp[e] = sh[0];
        __syncthreads();
        sh[tid] = cs[e]; __syncthreads();
        for (int o = 128; o > 0; o >>= 1) { if (tid < o) sh[tid] += sh[tid+o]; __syncthreads(); }
        if (tid == 0) totc[e] = sh[0];
        __syncthreads();
    }
    if (tid == 0) {
        float a = 0.f;
        for (int e = 0; e < NE; e++) a += (totc[e]/(float)T_) * (totp[e]/(float)T_);
        g_aux[0] += (float)NE * a;
    }
}
__global__ void k_bucket() {
    int t = blockIdx.x*256 + threadIdx.x;
    if (t >= T_) return;
    for (int j = 0; j < 2; j++) {
        int e = g_ti[2*t + j];
        int pos = atomicAdd(&g_cnt[e], 1);
        g_rows[e*T_ + pos] = t;
        g_slot[2*t + j] = e*T_ + pos;
    }
}
__global__ void k_combine() {
    int t = blockIdx.x, tid = threadIdx.x;
    int s0 = g_slot[2*t], s1 = g_slot[2*t+1];
    float w0 = g_tw[2*t], w1 = g_tw[2*t+1];
    const float* y0 = g_yb + (size_t)s0*D_;
    const float* y1 = g_yb + (size_t)s1*D_;
    float* hr = g_h + (size_t)t*D_;
    for (int d = tid; d < D_; d += 256) hr[d] += w0*y0[d] + w1*y1[d];
}
__global__ void k_task(const float* __restrict__ tw, const float* __restrict__ tb, float* __restrict__ out) {
    int c = blockIdx.x, tid = threadIdx.x;
    __shared__ float sh[256];
    float s = 0.f;
    for (int d = tid; d < D_; d += 256) s += g_xn[d] * tw[(size_t)d*16 + c];
    sh[tid] = s; __syncthreads();
    for (int o = 128; o > 0; o >>= 1) { if (tid < o) sh[tid] += sh[tid+o]; __syncthreads(); }
    if (tid == 0) out[OUT_TASK + c] = sh[0] + tb[c];
}
__global__ void k_mean1() {
    int b = blockIdx.x, tid = threadIdx.x;
    const float* x = g_xn + (size_t)b*128*D_ + tid*4;
    float4 a = make_float4(0.f,0.f,0.f,0.f);
    for (int r = 0; r < 128; r++) {
        float4 v = *(const float4*)(x + (size_t)r*D_);
        a.x += v.x; a.y += v.y; a.z += v.z; a.w += v.w;
    }
    *(float4*)(g_mp + b*D_ + tid*4) = a;
}
__global__ void k_mean2() {
    int d = blockIdx.x*256 + threadIdx.x;
    float s = 0.f;
    for (int b = 0; b < 16; b++) s += g_mp[b*D_ + d];
    g_xm[d] = s / (float)T_;
}
__global__ void k_eval(const float* __restrict__ ew, const float* __restrict__ eb, float* __restrict__ out) {
    int c = blockIdx.x, tid = threadIdx.x;
    __shared__ float sh[256];
    float s = 0.f;
    for (int d = tid; d < D_; d += 256) s += g_xm[d] * ew[(size_t)d*8 + c];
    sh[tid] = s; __syncthreads();
    for (int o = 128; o > 0; o >>= 1) { if (tid < o) sh[tid] += sh[tid+o]; __syncthreads(); }
    if (tid == 0) out[OUT_EVAL + c] = sh[0] + eb[c];
}
__global__ void k_auxw(float* __restrict__ out) { out[OUT_AUX] = g_aux[0]; }

// ---------------- launch ----------------
extern "C" void kernel_launch(void* const* d_in, const int* in_sizes, int n_in,
                              void* d_out, int out_size) {
    const int*   ids     = (const int*)  d_in[0];
    const float* embed_W = (const float*)d_in[1];
    const float* n1      = (const float*)d_in[2];
    const float* n2      = (const float*)d_in[3];
    const float* wq      = (const float*)d_in[4];
    const float* wk      = (const float*)d_in[5];
    const float* wv      = (const float*)d_in[6];
    const float* wo      = (const float*)d_in[7];
    const float* rw      = (const float*)d_in[8];
    const float* w1      = (const float*)d_in[9];
    const float* w3      = (const float*)d_in[10];
    const float* w2      = (const float*)d_in[11];
    const float* normf   = (const float*)d_in[12];
    const float* lm      = (const float*)d_in[13];
    const float* tw      = (const float*)d_in[14];
    const float* tb      = (const float*)d_in[15];
    const float* ew      = (const float*)d_in[16];
    const float* eb      = (const float*)d_in[17];
    float* out = (float*)d_out;

    float *p_h, *p_xn, *p_qkv, *p_attn, *p_sc;
    bf16 *p_ah, *p_al, *p_qkvh, *p_qkvl, *p_hbh, *p_hbl;
    bf16 *p_cqh, *p_cql, *p_cwoh, *p_cwol, *p_c1h, *p_c1l, *p_c3h, *p_c3l, *p_c2h, *p_c2l, *p_clh, *p_cll;
    cudaGetSymbolAddress((void**)&p_h,    g_h);
    cudaGetSymbolAddress((void**)&p_xn,   g_xn);
    cudaGetSymbolAddress((void**)&p_qkv,  g_qkv);
    cudaGetSymbolAddress((void**)&p_attn, g_attn);
    cudaGetSymbolAddress((void**)&p_sc,   g_sc);
    cudaGetSymbolAddress((void**)&p_ah,   g_ah);
    cudaGetSymbolAddress((void**)&p_al,   g_al);
    cudaGetSymbolAddress((void**)&p_qkvh, g_qkvh);
    cudaGetSymbolAddress((void**)&p_qkvl, g_qkvl);
    cudaGetSymbolAddress((void**)&p_hbh,  g_hbh);
    cudaGetSymbolAddress((void**)&p_hbl,  g_hbl);
    cudaGetSymbolAddress((void**)&p_cqh,  c_qkvh);
    cudaGetSymbolAddress((void**)&p_cql,  c_qkvl);
    cudaGetSymbolAddress((void**)&p_cwoh, c_woh);
    cudaGetSymbolAddress((void**)&p_cwol, c_wol);
    cudaGetSymbolAddress((void**)&p_c1h,  c_w1h);
    cudaGetSymbolAddress((void**)&p_c1l,  c_w1l);
    cudaGetSymbolAddress((void**)&p_c3h,  c_w3h);
    cudaGetSymbolAddress((void**)&p_c3l,  c_w3l);
    cudaGetSymbolAddress((void**)&p_c2h,  c_w2h);
    cudaGetSymbolAddress((void**)&p_c2l,  c_w2l);
    cudaGetSymbolAddress((void**)&p_clh,  c_lmh);
    cudaGetSymbolAddress((void**)&p_cll,  c_lml);

    cudaFuncSetAttribute(k_mma,     cudaFuncAttributeMaxDynamicSharedMemorySize, SMEM_MMA);
    cudaFuncSetAttribute(k_moe_mma, cudaFuncAttributeMaxDynamicSharedMemorySize, SMEM_MMA);
    cudaFuncSetAttribute(k_avm,     cudaFuncAttributeMaxDynamicSharedMemorySize, SMEM_MMA);
    cudaFuncSetAttribute(k_qk,      cudaFuncAttributeMaxDynamicSharedMemorySize, SMEM_QK);

    // ---- weight conversion (once per call) ----
    for (int l = 0; l < NL; l++) {
        k_convs<<<1024, 256>>>(wq + (size_t)l*D_*1024, p_cqh + (size_t)l*D_*QKV_,        p_cql + (size_t)l*D_*QKV_,        1024, QKV_);
        k_convs<<<256,  256>>>(wk + (size_t)l*D_*256,  p_cqh + (size_t)l*D_*QKV_ + 1024, p_cql + (size_t)l*D_*QKV_ + 1024, 256,  QKV_);
        k_convs<<<256,  256>>>(wv + (size_t)l*D_*256,  p_cqh + (size_t)l*D_*QKV_ + 1280, p_cql + (size_t)l*D_*QKV_ + 1280, 256,  QKV_);
    }
    k_split<<<2048,  256>>>(wo, p_cwoh, p_cwol);
    k_split<<<32768, 256>>>(w1, p_c1h,  p_c1l);
    k_split<<<32768, 256>>>(w3, p_c3h,  p_c3l);
    k_split<<<32768, 256>>>(w2, p_c2h,  p_c2l);
    k_split<<<32000, 256>>>(lm, p_clh,  p_cll);

    k_zero_aux<<<1, 32>>>();
    k_embed<<<T_, 256>>>(ids, embed_W);

    for (int l = 0; l < NL; l++) {
        // attention
        k_rms<<<T_, 256>>>(p_h, n1 + (size_t)l*D_, p_xn);
        k_split<<<2048, 256>>>(p_xn, p_ah, p_al);
        k_mma<<<dim3(16, 12), 256, SMEM_MMA>>>(p_ah, p_al,
            p_cqh + (size_t)l*D_*QKV_, p_cql + (size_t)l*D_*QKV_, p_qkv, D_, QKV_, QKV_, 0);
        k_rope<<<T_, 512>>>();
        k_split<<<3072, 256>>>(p_qkv, p_qkvh, p_qkvl);
        k_qk<<<dim3(4, 4, 64), 256, SMEM_QK>>>();
        k_softmax<<<NCK*NH*CH, 256>>>();
        k_split<<<16384, 256>>>(p_sc, p_hbh, p_hbl);
        k_avm<<<dim3(4, 1, 64), 256, SMEM_MMA>>>();
        k_split<<<2048, 256>>>(p_attn, p_ah, p_al);
        k_mma<<<dim3(16, 8), 256, SMEM_MMA>>>(p_ah, p_al,
            p_cwoh + (size_t)l*D_*D_, p_cwol + (size_t)l*D_*D_, p_h, D_, D_, D_, 1);

        // MoE
        k_rms<<<T_, 256>>>(p_h, n2 + (size_t)l*D_, p_xn);
        k_split<<<2048, 256>>>(p_xn, p_ah, p_al);
        k_router<<<T_/8, 256>>>(rw + (size_t)l*D_*NE);
        k_aux<<<1, 256>>>();
        k_zero_cnt<<<1, 32>>>();
        k_bucket<<<T_/256, 256>>>();
        k_moe_mma<<<dim3(16, 16, NE), 256, SMEM_MMA>>>(p_c1h + (size_t)l*NE*D_*F_, p_c1l + (size_t)l*NE*D_*F_, 0);
        k_moe_mma<<<dim3(16, 16, NE), 256, SMEM_MMA>>>(p_c3h + (size_t)l*NE*D_*F_, p_c3l + (size_t)l*NE*D_*F_, 1);
        k_moe_mma<<<dim3(16, 8,  NE), 256, SMEM_MMA>>>(p_c2h + (size_t)l*NE*F_*D_, p_c2l + (size_t)l*NE*F_*D_, 2);
        k_combine<<<T_, 256>>>();
    }

    // final norm + heads
    k_rms<<<T_, 256>>>(p_h, normf, p_xn);
    k_split<<<2048, 256>>>(p_xn, p_ah, p_al);
    k_mma<<<dim3(16, NV/128), 256, SMEM_MMA>>>(p_ah, p_al, p_clh, p_cll, out, D_, NV, NV, 0);
    k_task<<<16, 256>>>(tw, tb, out);
    k_mean1<<<16, 256>>>();
    k_mean2<<<4, 256>>>();
    k_eval<<<8, 256>>>(ew, eb, out);
    k_auxw<<<1, 1>>>(out);
}

// round 10
// speedup vs baseline: 2.4983x; 1.1214x over previous
#include <cuda_runtime.h>
#include <cuda_bf16.h>
#include <math.h>
#include <stdint.h>

#define T_   2048
#define D_   1024
#define NH   16
#define NKV  4
#define F_   2048
#define NE   8
#define NL   2
#define NV   32000
#define CH   512
#define NCK  4
#define QKV_ 1536

#define OUT_TASK   (T_*(size_t)NV)
#define OUT_EVAL   (OUT_TASK + 16)
#define OUT_AUX    (OUT_EVAL + 8)

typedef __nv_bfloat16 bf16;
typedef __nv_bfloat162 bf162;

// ---------------- scratch (device globals; no allocation) ----------------
__device__ float g_h   [(size_t)T_*D_];
__device__ float g_xn  [(size_t)T_*D_];
__device__ float g_qkv [(size_t)T_*QKV_];
__device__ float g_sc  [(size_t)NCK*NH*CH*CH];
__device__ float g_attn[(size_t)T_*D_];
__device__ float g_probs[(size_t)T_*NE];
__device__ int   g_ti  [T_*2];
__device__ float g_tw  [T_*2];
__device__ int   g_cnt [NE];
__device__ int   g_rows[NE*T_];
__device__ int   g_slot[T_*2];
__device__ float g_yb  [(size_t)NE*T_*D_];
__device__ float g_aux [1];
__device__ float g_xm  [D_];
__device__ float g_mp  [16*D_];
__device__ bf16  g_ah  [(size_t)T_*D_];
__device__ bf16  g_al  [(size_t)T_*D_];
__device__ bf16  g_qkvh[(size_t)T_*QKV_];
__device__ bf16  g_qkvl[(size_t)T_*QKV_];
__device__ float g_ub  [(size_t)NE*T_*F_];
__device__ bf16  g_hbh [(size_t)NE*T_*F_];   // also reused as P hi
__device__ bf16  g_hbl [(size_t)NE*T_*F_];   // also reused as P lo
// pre-converted weights (hi/lo bf16)
__device__ bf16  c_qkvh[(size_t)NL*D_*QKV_], c_qkvl[(size_t)NL*D_*QKV_];
__device__ bf16  c_woh [(size_t)NL*D_*D_],   c_wol [(size_t)NL*D_*D_];
__device__ bf16  c_w1h [(size_t)NL*NE*D_*F_], c_w1l[(size_t)NL*NE*D_*F_];
__device__ bf16  c_w3h [(size_t)NL*NE*D_*F_], c_w3l[(size_t)NL*NE*D_*F_];
__device__ bf16  c_w2h [(size_t)NL*NE*F_*D_], c_w2l[(size_t)NL*NE*F_*D_];
__device__ bf16  c_lmh [(size_t)D_*NV],      c_lml[(size_t)D_*NV];

// ---------------- asm helpers ----------------
__device__ __forceinline__ uint32_t smem_u32(const void* p) {
    uint32_t a;
    asm("{ .reg .u64 t; cvta.to.shared.u64 t, %1; cvt.u32.u64 %0, t; }" : "=r"(a) : "l"(p));
    return a;
}
__device__ __forceinline__ void cpa(uint32_t d, const void* s) {
    asm volatile("cp.async.cg.shared.global [%0], [%1], 16;" :: "r"(d), "l"(s));
}
__device__ __forceinline__ void cp_commit() { asm volatile("cp.async.commit_group;" ::: "memory"); }
__device__ __forceinline__ void cp_wait1()  { asm volatile("cp.async.wait_group 1;" ::: "memory"); }
__device__ __forceinline__ void cp_wait0()  { asm volatile("cp.async.wait_group 0;" ::: "memory"); }
__device__ __forceinline__ void ldsm4(uint32_t (&r)[4], uint32_t a) {
    asm volatile("ldmatrix.sync.aligned.m8n8.x4.shared.b16 {%0,%1,%2,%3}, [%4];"
        : "=r"(r[0]), "=r"(r[1]), "=r"(r[2]), "=r"(r[3]) : "r"(a));
}
__device__ __forceinline__ void ldsm2t(uint32_t (&r)[2], uint32_t a) {
    asm volatile("ldmatrix.sync.aligned.m8n8.x2.trans.shared.b16 {%0,%1}, [%2];"
        : "=r"(r[0]), "=r"(r[1]) : "r"(a));
}
__device__ __forceinline__ void ldsm2(uint32_t (&r)[2], uint32_t a) {
    asm volatile("ldmatrix.sync.aligned.m8n8.x2.shared.b16 {%0,%1}, [%2];"
        : "=r"(r[0]), "=r"(r[1]) : "r"(a));
}
__device__ __forceinline__ void mma16816(float (&d)[4], const uint32_t (&a)[4], const uint32_t (&b)[2]) {
    asm volatile("mma.sync.aligned.m16n8k16.row.col.f32.bf16.bf16.f32 "
        "{%0,%1,%2,%3}, {%4,%5,%6,%7}, {%8,%9}, {%0,%1,%2,%3};"
        : "+f"(d[0]), "+f"(d[1]), "+f"(d[2]), "+f"(d[3])
        : "r"(a[0]), "r"(a[1]), "r"(a[2]), "r"(a[3]), "r"(b[0]), "r"(b[1]));
}

// SMEM per buffer: Ah 128x80B @0 | Al @10240 | Bh 32x272B @20480 | Bl @29184
#define OFF_AL 10240
#define OFF_BH 20480
#define OFF_BL 29184
#define BUFSZ  37888
#define SMEM_MMA (3*BUFSZ)

// modes: 0 = C=acc, 1 = C+=acc, 2 = silu(U)*acc -> split bf16 to Hh/Hl
__device__ __forceinline__ void mma_block(
    const bf16* __restrict__ Ah, const bf16* __restrict__ Al, int lda,
    const int* __restrict__ rows, int count, int m0,
    const bf16* __restrict__ Bh, const bf16* __restrict__ Bl, int ldb, int n0, int nlim,
    int K, float* __restrict__ C, int ldc, int mode,
    const float* __restrict__ U, bf16* __restrict__ Hh, bf16* __restrict__ Hl,
    char* dsm, uint32_t sb)
{
    const int tid = threadIdx.x, lane = tid & 31, wid = tid >> 5;
    const int wm = (wid & 1) * 64, wn = (wid >> 1) * 32;
    const int ar = tid >> 1, akc = (tid & 1) * 16;
    const int bkr = tid >> 3, bn16 = (tid & 7) * 16;
    const int gm = m0 + ar;
    const bool av = gm < count;
    const bf16 *pAh = nullptr, *pAl = nullptr;
    if (av) {
        size_t rr = (size_t)(rows ? rows[gm] : gm) * lda + akc;
        pAh = Ah + rr; pAl = Al + rr;
    }
    const int bcol = (nlim < 128) ? (bn16 & (nlim - 1)) : bn16;
    const bf16* pBh = Bh + (size_t)bkr * ldb + n0 + bcol;
    const bf16* pBl = Bl + (size_t)bkr * ldb + n0 + bcol;
    const uint32_t ao = (uint32_t)ar * 80 + (uint32_t)akc * 2;
    const uint32_t bo = (uint32_t)OFF_BH + (uint32_t)bkr * 272 + (uint32_t)bn16 * 2;

    if (!av) {
        uint4 z = make_uint4(0,0,0,0);
        #pragma unroll
        for (int s = 0; s < 3; s++) {
            char* bb = dsm + s * BUFSZ;
            *(uint4*)(bb + ao) = z;            *(uint4*)(bb + ao + 16) = z;
            *(uint4*)(bb + OFF_AL + ao) = z;   *(uint4*)(bb + OFF_AL + ao + 16) = z;
        }
    }

    float acc[4][4][4];
    #pragma unroll
    for (int a = 0; a < 4; a++)
        #pragma unroll
        for (int b = 0; b < 4; b++)
            #pragma unroll
            for (int c = 0; c < 4; c++) acc[a][b][c] = 0.f;

    auto ISSUE = [&](int k0, uint32_t sbuf) {
        if (av) {
            cpa(sbuf + ao,               pAh + k0);
            cpa(sbuf + ao + 16,          pAh + k0 + 8);
            cpa(sbuf + OFF_AL + ao,      pAl + k0);
            cpa(sbuf + OFF_AL + ao + 16, pAl + k0 + 8);
        }
        const bf16* b = pBh + (size_t)k0 * ldb;
        cpa(sbuf + bo,      b);
        cpa(sbuf + bo + 16, b + 8);
        b = pBl + (size_t)k0 * ldb;
        cpa(sbuf + (OFF_BL - OFF_BH) + bo,      b);
        cpa(sbuf + (OFF_BL - OFF_BH) + bo + 16, b + 8);
    };

    auto COMPUTE = [&](uint32_t boff) {
        uint32_t abase = sb + boff + (uint32_t)(wm + (lane & 15)) * 80 + ((lane >> 4) * 8) * 2;
        uint32_t bbase = sb + boff + OFF_BH
                       + (uint32_t)((lane & 7) + ((lane >> 3) & 1) * 8) * 272
                       + (uint32_t)wn * 2;
        #pragma unroll
        for (int ks = 0; ks < 2; ks++) {
            uint32_t ah4[4][4], al4[4][4], bh2[4][2], bl2[4][2];
            #pragma unroll
            for (int mt = 0; mt < 4; mt++) {
                uint32_t aa = abase + mt * (16 * 80) + ks * 32;
                ldsm4(ah4[mt], aa);
                ldsm4(al4[mt], aa + OFF_AL);
            }
            #pragma unroll
            for (int nt = 0; nt < 4; nt++) {
                uint32_t ba = bbase + ks * (16 * 272) + nt * 16;
                ldsm2t(bh2[nt], ba);
                ldsm2t(bl2[nt], ba + (OFF_BL - OFF_BH));
            }
            #pragma unroll
            for (int mt = 0; mt < 4; mt++)
                #pragma unroll
                for (int nt = 0; nt < 4; nt++) {
                    mma16816(acc[mt][nt], ah4[mt], bh2[nt]);
                    mma16816(acc[mt][nt], ah4[mt], bl2[nt]);
                    mma16816(acc[mt][nt], al4[mt], bh2[nt]);
                }
        }
    };

    const int NC = K >> 5;
    ISSUE(0, sb); cp_commit();
    if (NC > 1) { ISSUE(32, sb + BUFSZ); cp_commit(); }
    for (int c = 0; c < NC; c++) {
        if (c == NC - 1) cp_wait0(); else cp_wait1();
        __syncthreads();
        COMPUTE((uint32_t)(c % 3) * BUFSZ);
        if (c + 2 < NC) { ISSUE((c + 2) << 5, sb + (uint32_t)((c + 2) % 3) * BUFSZ); cp_commit(); }
    }

    #pragma unroll
    for (int mt = 0; mt < 4; mt++) {
        int r0 = m0 + wm + mt * 16 + (lane >> 2);
        #pragma unroll
        for (int nt = 0; nt < 4; nt++) {
            int ln = wn + nt * 8 + (lane & 3) * 2;
            if (ln >= nlim) continue;
            int cc = n0 + ln;
            float* d = acc[mt][nt];
            #pragma unroll
            for (int hrow = 0; hrow < 2; hrow++) {
                int r = r0 + hrow * 8;
                if (r >= count) continue;
                float d0 = d[hrow*2], d1 = d[hrow*2 + 1];
                size_t o = (size_t)r * ldc + cc;
                if (mode == 0) {
                    *(float2*)(C + o) = make_float2(d0, d1);
                } else if (mode == 1) {
                    float2 p = *(const float2*)(C + o);
                    *(float2*)(C + o) = make_float2(p.x + d0, p.y + d1);
                } else {
                    float2 u = *(const float2*)(U + o);
                    float h0 = (u.x / (1.f + expf(-u.x))) * d0;
                    float h1 = (u.y / (1.f + expf(-u.y))) * d1;
                    bf162 hh = __floats2bfloat162_rn(h0, h1);
                    bf162 ll = __floats2bfloat162_rn(h0 - __low2float(hh), h1 - __high2float(hh));
                    *(bf162*)(Hh + o) = hh;
                    *(bf162*)(Hl + o) = ll;
                }
            }
        }
    }
}

// dense GEMM: grid (M/128, N/128)
__global__ __launch_bounds__(256, 1) void k_mma(
    const bf16* __restrict__ Ah, const bf16* __restrict__ Al,
    const bf16* __restrict__ Bh, const bf16* __restrict__ Bl,
    float* __restrict__ C, int K, int ldb, int ldc, int mode)
{
    extern __shared__ __align__(16) char dsm[];
    mma_block(Ah, Al, K, nullptr, 1 << 30, blockIdx.x * 128,
              Bh, Bl, ldb, blockIdx.y * 128, 128,
              K, C, ldc, mode, nullptr, nullptr, nullptr, dsm, smem_u32(dsm));
}

// MoE: which 0 = X W1 -> g_ub; 1 = X W3 fused silu -> hidden split; 2 = H W2 -> g_yb
__global__ __launch_bounds__(256, 1) void k_moe_mma(
    const bf16* __restrict__ Wh, const bf16* __restrict__ Wl, int which)
{
    int e = blockIdx.z;
    int count = g_cnt[e];
    int m0 = blockIdx.x * 128;
    if (m0 >= count) return;
    int n0 = blockIdx.y * 128;
    extern __shared__ __align__(16) char dsm[];
    uint32_t sb = smem_u32(dsm);
    if (which == 0) {
        mma_block(g_ah, g_al, D_, g_rows + e * T_, count, m0,
                  Wh + (size_t)e * D_ * F_, Wl + (size_t)e * D_ * F_, F_, n0, 128,
                  D_, g_ub + (size_t)e * T_ * F_, F_, 0, nullptr, nullptr, nullptr, dsm, sb);
    } else if (which == 1) {
        mma_block(g_ah, g_al, D_, g_rows + e * T_, count, m0,
                  Wh + (size_t)e * D_ * F_, Wl + (size_t)e * D_ * F_, F_, n0, 128,
                  D_, nullptr, F_, 2, g_ub + (size_t)e * T_ * F_,
                  g_hbh + (size_t)e * T_ * F_, g_hbl + (size_t)e * T_ * F_, dsm, sb);
    } else {
        mma_block(g_hbh + (size_t)e * T_ * F_, g_hbl + (size_t)e * T_ * F_, F_, nullptr, count, m0,
                  Wh + (size_t)e * F_ * D_, Wl + (size_t)e * F_ * D_, D_, n0, 128,
                  F_, g_yb + (size_t)e * T_ * D_, D_, 0, nullptr, nullptr, nullptr, dsm, sb);
    }
}

// O = P V: grid (4, 1, 64); P split lives in g_hbh/g_hbl
__global__ __launch_bounds__(256, 1) void k_avm()
{
    int b = blockIdx.z, chunk = b >> 4, head = b & 15, kvh = head >> 2;
    extern __shared__ __align__(16) char dsm[];
    mma_block(g_hbh + (size_t)b * CH * CH, g_hbl + (size_t)b * CH * CH, CH, nullptr, CH, blockIdx.x * 128,
              g_qkvh + (size_t)chunk * CH * QKV_ + 1280 + kvh * 64,
              g_qkvl + (size_t)chunk * CH * QKV_ + 1280 + kvh * 64, QKV_, 0, 64,
              CH, g_attn + (size_t)chunk * CH * D_ + head * 64, D_, 0,
              nullptr, nullptr, nullptr, dsm, smem_u32(dsm));
}

// ---------------- scores S = Q K^T: grid (4, 4, 64); skips n0>m0 tiles ----------------
#define QK_AL 10240
#define QK_KH 20480
#define QK_KL 30720
#define QK_BUF 40960
#define SMEM_QK (2*QK_BUF)

__global__ __launch_bounds__(256, 1) void k_qk()
{
    if (blockIdx.y > blockIdx.x) return;   // fully causal-masked tile
    extern __shared__ __align__(16) char dsm[];
    uint32_t sb = smem_u32(dsm);
    int b = blockIdx.z, chunk = b >> 4, head = b & 15, kvh = head >> 2;
    int m0 = blockIdx.x * 128, n0 = blockIdx.y * 128;
    int tid = threadIdx.x, lane = tid & 31, wid = tid >> 5;
    int wm = (wid & 1) * 64, wn = (wid >> 1) * 32;
    int ar = tid >> 1, akc = (tid & 1) * 16;
    const bf16* pQh = g_qkvh + (size_t)(chunk*CH + m0 + ar) * QKV_ + head * 64 + akc;
    const bf16* pQl = g_qkvl + (size_t)(chunk*CH + m0 + ar) * QKV_ + head * 64 + akc;
    const bf16* pKh = g_qkvh + (size_t)(chunk*CH + n0 + ar) * QKV_ + 1024 + kvh * 64 + akc;
    const bf16* pKl = g_qkvl + (size_t)(chunk*CH + n0 + ar) * QKV_ + 1024 + kvh * 64 + akc;
    const uint32_t ao = (uint32_t)ar * 80 + (uint32_t)akc * 2;

    float acc[4][4][4];
    #pragma unroll
    for (int a = 0; a < 4; a++)
        #pragma unroll
        for (int bb = 0; bb < 4; bb++)
            #pragma unroll
            for (int c = 0; c < 4; c++) acc[a][bb][c] = 0.f;

    auto ISSUE = [&](int k0, uint32_t sbuf) {
        cpa(sbuf + ao,               pQh + k0); cpa(sbuf + ao + 16,           pQh + k0 + 8);
        cpa(sbuf + QK_AL + ao,       pQl + k0); cpa(sbuf + QK_AL + ao + 16,   pQl + k0 + 8);
        cpa(sbuf + QK_KH + ao,       pKh + k0); cpa(sbuf + QK_KH + ao + 16,   pKh + k0 + 8);
        cpa(sbuf + QK_KL + ao,       pKl + k0); cpa(sbuf + QK_KL + ao + 16,   pKl + k0 + 8);
    };
    auto COMPUTE = [&](uint32_t boff) {
        uint32_t abase = sb + boff + (uint32_t)(wm + (lane & 15)) * 80 + ((lane >> 4) * 8) * 2;
        #pragma unroll
        for (int ks = 0; ks < 2; ks++) {
            uint32_t ah4[4][4], al4[4][4], bh2[4][2], bl2[4][2];
            #pragma unroll
            for (int mt = 0; mt < 4; mt++) {
                uint32_t aa = abase + mt * (16 * 80) + ks * 32;
                ldsm4(ah4[mt], aa);
                ldsm4(al4[mt], aa + QK_AL);
            }
            #pragma unroll
            for (int nt = 0; nt < 4; nt++) {
                uint32_t ba = sb + boff + QK_KH
                            + (uint32_t)(wn + nt * 8 + (lane & 7)) * 80
                            + ks * 32 + ((lane >> 3) & 1) * 16;
                ldsm2(bh2[nt], ba);
                ldsm2(bl2[nt], ba + (QK_KL - QK_KH));
            }
            #pragma unroll
            for (int mt = 0; mt < 4; mt++)
                #pragma unroll
                for (int nt = 0; nt < 4; nt++) {
                    mma16816(acc[mt][nt], ah4[mt], bh2[nt]);
                    mma16816(acc[mt][nt], ah4[mt], bl2[nt]);
                    mma16816(acc[mt][nt], al4[mt], bh2[nt]);
                }
        }
    };

    ISSUE(0, sb); cp_commit();
    ISSUE(32, sb + QK_BUF); cp_commit();
    cp_wait1(); __syncthreads(); COMPUTE(0);
    cp_wait0(); __syncthreads(); COMPUTE(QK_BUF);

    float* S = g_sc + (size_t)b * CH * CH;
    #pragma unroll
    for (int mt = 0; mt < 4; mt++) {
        int r0 = wm + mt * 16 + (lane >> 2);
        #pragma unroll
        for (int nt = 0; nt < 4; nt++) {
            int c0 = wn + nt * 8 + (lane & 3) * 2;
            float* d = acc[mt][nt];
            #pragma unroll
            for (int hrow = 0; hrow < 2; hrow++) {
                int qg = m0 + r0 + hrow * 8;
                int kg = n0 + c0;
                float v0 = d[hrow*2] * 0.125f, v1 = d[hrow*2 + 1] * 0.125f;
                if (kg > qg)     v0 = -1e30f;
                if (kg + 1 > qg) v1 = -1e30f;
                *(float2*)(S + (size_t)qg * CH + kg) = make_float2(v0, v1);
            }
        }
    }
}

// ---- fp32 -> bf16 hi/lo, 8 elems/thread, 16B stores ----
__global__ void k_split8(const float* __restrict__ x, bf16* __restrict__ hh, bf16* __restrict__ ll) {
    size_t i = (size_t)blockIdx.x * 256 + threadIdx.x;
    const float4* xv = (const float4*)x;
    float4 a = xv[2*i], b = xv[2*i+1];
    bf162 h0 = __floats2bfloat162_rn(a.x, a.y);
    bf162 h1 = __floats2bfloat162_rn(a.z, a.w);
    bf162 h2 = __floats2bfloat162_rn(b.x, b.y);
    bf162 h3 = __floats2bfloat162_rn(b.z, b.w);
    bf162 l0 = __floats2bfloat162_rn(a.x - __low2float(h0), a.y - __high2float(h0));
    bf162 l1 = __floats2bfloat162_rn(a.z - __low2float(h1), a.w - __high2float(h1));
    bf162 l2 = __floats2bfloat162_rn(b.x - __low2float(h2), b.y - __high2float(h2));
    bf162 l3 = __floats2bfloat162_rn(b.z - __low2float(h3), b.w - __high2float(h3));
    ((uint4*)hh)[i] = make_uint4(*(uint32_t*)&h0, *(uint32_t*)&h1, *(uint32_t*)&h2, *(uint32_t*)&h3);
    ((uint4*)ll)[i] = make_uint4(*(uint32_t*)&l0, *(uint32_t*)&l1, *(uint32_t*)&l2, *(uint32_t*)&l3);
}
// strided (pack wq/wk/wv into [K,1536])
__global__ void k_convs(const float* __restrict__ src, bf16* __restrict__ h, bf16* __restrict__ l,
                        int N, int ldd) {
    size_t i = (size_t)blockIdx.x * 256 + threadIdx.x;
    size_t e = i * 4;
    int r = (int)(e / N), c = (int)(e % N);
    float4 v = *(const float4*)(src + e);
    size_t o = (size_t)r * ldd + c;
    bf162 h0 = __floats2bfloat162_rn(v.x, v.y);
    bf162 l0 = __floats2bfloat162_rn(v.x - __low2float(h0), v.y - __high2float(h0));
    bf162 h1 = __floats2bfloat162_rn(v.z, v.w);
    bf162 l1 = __floats2bfloat162_rn(v.z - __low2float(h1), v.w - __high2float(h1));
    *(bf162*)(h+o) = h0; *(bf162*)(h+o+2) = h1;
    *(bf162*)(l+o) = l0; *(bf162*)(l+o+2) = l1;
}

// ---------------- misc kernels ----------------
__global__ void k_zero_aux() { if (threadIdx.x == 0) g_aux[0] = 0.f; }
__global__ void k_zero_cnt() { if (threadIdx.x < NE) g_cnt[threadIdx.x] = 0; }
__global__ void k_embed(const int* __restrict__ ids, const float* __restrict__ ew) {
    int t = blockIdx.x;
    size_t r = (size_t)ids[t] * D_;
    for (int d = threadIdx.x; d < D_; d += blockDim.x) g_h[(size_t)t*D_ + d] = ew[r + d];
}
__global__ void k_rms(const float* __restrict__ x, const float* __restrict__ w, float* __restrict__ out) {
    int t = blockIdx.x, tid = threadIdx.x;
    __shared__ float sh[256];
    const float* xr = x + (size_t)t*D_;
    float s = 0.f;
    for (int d = tid; d < D_; d += 256) { float v = xr[d]; s += v*v; }
    sh[tid] = s; __syncthreads();
    for (int o = 128; o > 0; o >>= 1) { if (tid < o) sh[tid] += sh[tid+o]; __syncthreads(); }
    float scale = rsqrtf(sh[0] / (float)D_ + 1e-6f);
    float* orow = out + (size_t)t*D_;
    for (int d = tid; d < D_; d += 256) orow[d] = w[d] * xr[d] * scale;
}
__global__ void k_rope() {
    int t = blockIdx.x, tid = threadIdx.x;
    float p = (float)(t & (CH-1));
    float* base = g_qkv + (size_t)t*QKV_;
    if (tid < NH*32) {
        int h = tid >> 5, i = tid & 31;
        float ang = p * powf(1000000.0f, -(float)i/32.0f);
        float c = cosf(ang), s = sinf(ang);
        float* q = base + h*64 + 2*i;
        float x1 = q[0], x2 = q[1];
        q[0] = x1*c - x2*s; q[1] = x1*s + x2*c;
    }
    if (tid < NKV*32) {
        int h = tid >> 5, i = tid & 31;
        float ang = p * powf(1000000.0f, -(float)i/32.0f);
        float c = cosf(ang), s = sinf(ang);
        float* kk = base + 1024 + h*64 + 2*i;
        float x1 = kk[0], x2 = kk[1];
        kk[0] = x1*c - x2*s; kk[1] = x1*s + x2*c;
    }
}
// fused softmax: reads fp32 S, writes P directly as bf16 hi/lo into g_hbh/g_hbl
__global__ void k_softmax() {
    int row = blockIdx.x;
    int q = row & (CH-1);
    int tid = threadIdx.x;
    const float* r = g_sc + (size_t)row*CH;
    __shared__ float sh[256];
    int c0 = tid * 2;
    bool v0 = (c0 <= q), v1 = (c0 + 1 <= q);
    float x0 = v0 ? r[c0]   : -1e30f;
    float x1 = v1 ? r[c0+1] : -1e30f;
    sh[tid] = fmaxf(x0, x1); __syncthreads();
    for (int o = 128; o > 0; o >>= 1) { if (tid < o) sh[tid] = fmaxf(sh[tid], sh[tid+o]); __syncthreads(); }
    float m = sh[0]; __syncthreads();
    float e0 = v0 ? expf(x0 - m) : 0.f;
    float e1 = v1 ? expf(x1 - m) : 0.f;
    sh[tid] = e0 + e1; __syncthreads();
    for (int o = 128; o > 0; o >>= 1) { if (tid < o) sh[tid] += sh[tid+o]; __syncthreads(); }
    float inv = 1.f / sh[0];
    float p0 = e0 * inv, p1 = e1 * inv;
    bf162 hh = __floats2bfloat162_rn(p0, p1);
    bf162 ll = __floats2bfloat162_rn(p0 - __low2float(hh), p1 - __high2float(hh));
    size_t o = (size_t)row * CH + c0;
    *(bf162*)(g_hbh + o) = hh;
    *(bf162*)(g_hbl + o) = ll;
}
__global__ void k_router(const float* __restrict__ rw) {
    int tid = threadIdx.x, lane = tid & 31, w = tid >> 5;
    int t = blockIdx.x*8 + w;
    const float* xr = g_xn + (size_t)t*D_;
    float acc[NE] = {};
    for (int dd = 0; dd < 32; dd++) {
        int d = dd*32 + lane;
        float x = xr[d];
        const float* rr = rw + (size_t)d*NE;
        #pragma unroll
        for (int e = 0; e < NE; e++) acc[e] += x * rr[e];
    }
    #pragma unroll
    for (int e = 0; e < NE; e++)
        for (int o = 16; o > 0; o >>= 1) acc[e] += __shfl_down_sync(0xffffffffu, acc[e], o);
    if (lane == 0) {
        float m = acc[0];
        #pragma unroll
        for (int e = 1; e < NE; e++) m = fmaxf(m, acc[e]);
        float p[NE], s = 0.f;
        #pragma unroll
        for (int e = 0; e < NE; e++) { p[e] = expf(acc[e]-m); s += p[e]; }
        float inv = 1.f/s;
        #pragma unroll
        for (int e = 0; e < NE; e++) { p[e] *= inv; g_probs[(size_t)t*NE + e] = p[e]; }
        int i0 = 0;
        #pragma unroll
        for (int e = 1; e < NE; e++) if (p[e] > p[i0]) i0 = e;
        int i1 = (i0 == 0) ? 1 : 0;
        #pragma unroll
        for (int e = 0; e < NE; e++) if (e != i0 && p[e] > p[i1]) i1 = e;
        float ws = p[i0] + p[i1];
        g_ti[2*t] = i0; g_ti[2*t+1] = i1;
        g_tw[2*t] = p[i0]/ws; g_tw[2*t+1] = p[i1]/ws;
    }
}
__global__ void k_aux() {
    int tid = threadIdx.x;
    __shared__ float sh[256];
    __shared__ float totp[NE], totc[NE];
    float ps[NE] = {}, cs[NE] = {};
    for (int t = tid; t < T_; t += 256) {
        cs[g_ti[2*t]] += 1.f;
        #pragma unroll
        for (int e = 0; e < NE; e++) ps[e] += g_probs[(size_t)t*NE + e];
    }
    for (int e = 0; e < NE; e++) {
        sh[tid] = ps[e]; __syncthreads();
        for (int o = 128; o > 0; o >>= 1) { if (tid < o) sh[tid] += sh[tid+o]; __syncthreads(); }
        if (tid == 0) totp[e] = sh[0];
        __syncthreads();
        sh[tid] = cs[e]; __syncthreads();
        for (int o = 128; o > 0; o >>= 1) { if (tid < o) sh[tid] += sh[tid+o]; __syncthreads(); }
        if (tid == 0) totc[e] = sh[0];
        __syncthreads();
    }
    if (tid == 0) {
        float a = 0.f;
        for (int e = 0; e < NE; e++) a += (totc[e]/(float)T_) * (totp[e]/(float)T_);
        g_aux[0] += (float)NE * a;
    }
}
__global__ void k_bucket() {
    int t = blockIdx.x*256 + threadIdx.x;
    if (t >= T_) return;
    for (int j = 0; j < 2; j++) {
        int e = g_ti[2*t + j];
        int pos = atomicAdd(&g_cnt[e], 1);
        g_rows[e*T_ + pos] = t;
        g_slot[2*t + j] = e*T_ + pos;
    }
}
__global__ void k_combine() {
    int t = blockIdx.x, tid = threadIdx.x;
    int s0 = g_slot[2*t], s1 = g_slot[2*t+1];
    float w0 = g_tw[2*t], w1 = g_tw[2*t+1];
    const float* y0 = g_yb + (size_t)s0*D_;
    const float* y1 = g_yb + (size_t)s1*D_;
    float* hr = g_h + (size_t)t*D_;
    for (int d = tid; d < D_; d += 256) hr[d] += w0*y0[d] + w1*y1[d];
}
__global__ void k_task(const float* __restrict__ tw, const float* __restrict__ tb, float* __restrict__ out) {
    int c = blockIdx.x, tid = threadIdx.x;
    __shared__ float sh[256];
    float s = 0.f;
    for (int d = tid; d < D_; d += 256) s += g_xn[d] * tw[(size_t)d*16 + c];
    sh[tid] = s; __syncthreads();
    for (int o = 128; o > 0; o >>= 1) { if (tid < o) sh[tid] += sh[tid+o]; __syncthreads(); }
    if (tid == 0) out[OUT_TASK + c] = sh[0] + tb[c];
}
__global__ void k_mean1() {
    int b = blockIdx.x, tid = threadIdx.x;
    const float* x = g_xn + (size_t)b*128*D_ + tid*4;
    float4 a = make_float4(0.f,0.f,0.f,0.f);
    for (int r = 0; r < 128; r++) {
        float4 v = *(const float4*)(x + (size_t)r*D_);
        a.x += v.x; a.y += v.y; a.z += v.z; a.w += v.w;
    }
    *(float4*)(g_mp + b*D_ + tid*4) = a;
}
__global__ void k_mean2() {
    int d = blockIdx.x*256 + threadIdx.x;
    float s = 0.f;
    for (int b = 0; b < 16; b++) s += g_mp[b*D_ + d];
    g_xm[d] = s / (float)T_;
}
__global__ void k_eval(const float* __restrict__ ew, const float* __restrict__ eb, float* __restrict__ out) {
    int c = blockIdx.x, tid = threadIdx.x;
    __shared__ float sh[256];
    float s = 0.f;
    for (int d = tid; d < D_; d += 256) s += g_xm[d] * ew[(size_t)d*8 + c];
    sh[tid] = s; __syncthreads();
    for (int o = 128; o > 0; o >>= 1) { if (tid < o) sh[tid] += sh[tid+o]; __syncthreads(); }
    if (tid == 0) out[OUT_EVAL + c] = sh[0] + eb[c];
}
__global__ void k_auxw(float* __restrict__ out) { out[OUT_AUX] = g_aux[0]; }

// ---------------- launch ----------------
extern "C" void kernel_launch(void* const* d_in, const int* in_sizes, int n_in,
                              void* d_out, int out_size) {
    const int*   ids     = (const int*)  d_in[0];
    const float* embed_W = (const float*)d_in[1];
    const float* n1      = (const float*)d_in[2];
    const float* n2      = (const float*)d_in[3];
    const float* wq      = (const float*)d_in[4];
    const float* wk      = (const float*)d_in[5];
    const float* wv      = (const float*)d_in[6];
    const float* wo      = (const float*)d_in[7];
    const float* rw      = (const float*)d_in[8];
    const float* w1      = (const float*)d_in[9];
    const float* w3      = (const float*)d_in[10];
    const float* w2      = (const float*)d_in[11];
    const float* normf   = (const float*)d_in[12];
    const float* lm      = (const float*)d_in[13];
    const float* tw      = (const float*)d_in[14];
    const float* tb      = (const float*)d_in[15];
    const float* ew      = (const float*)d_in[16];
    const float* eb      = (const float*)d_in[17];
    float* out = (float*)d_out;

    float *p_h, *p_xn, *p_qkv, *p_attn;
    bf16 *p_ah, *p_al, *p_qkvh, *p_qkvl;
    bf16 *p_cqh, *p_cql, *p_cwoh, *p_cwol, *p_c1h, *p_c1l, *p_c3h, *p_c3l, *p_c2h, *p_c2l, *p_clh, *p_cll;
    cudaGetSymbolAddress((void**)&p_h,    g_h);
    cudaGetSymbolAddress((void**)&p_xn,   g_xn);
    cudaGetSymbolAddress((void**)&p_qkv,  g_qkv);
    cudaGetSymbolAddress((void**)&p_attn, g_attn);
    cudaGetSymbolAddress((void**)&p_ah,   g_ah);
    cudaGetSymbolAddress((void**)&p_al,   g_al);
    cudaGetSymbolAddress((void**)&p_qkvh, g_qkvh);
    cudaGetSymbolAddress((void**)&p_qkvl, g_qkvl);
    cudaGetSymbolAddress((void**)&p_cqh,  c_qkvh);
    cudaGetSymbolAddress((void**)&p_cql,  c_qkvl);
    cudaGetSymbolAddress((void**)&p_cwoh, c_woh);
    cudaGetSymbolAddress((void**)&p_cwol, c_wol);
    cudaGetSymbolAddress((void**)&p_c1h,  c_w1h);
    cudaGetSymbolAddress((void**)&p_c1l,  c_w1l);
    cudaGetSymbolAddress((void**)&p_c3h,  c_w3h);
    cudaGetSymbolAddress((void**)&p_c3l,  c_w3l);
    cudaGetSymbolAddress((void**)&p_c2h,  c_w2h);
    cudaGetSymbolAddress((void**)&p_c2l,  c_w2l);
    cudaGetSymbolAddress((void**)&p_clh,  c_lmh);
    cudaGetSymbolAddress((void**)&p_cll,  c_lml);

    cudaFuncSetAttribute(k_mma,     cudaFuncAttributeMaxDynamicSharedMemorySize, SMEM_MMA);
    cudaFuncSetAttribute(k_moe_mma, cudaFuncAttributeMaxDynamicSharedMemorySize, SMEM_MMA);
    cudaFuncSetAttribute(k_avm,     cudaFuncAttributeMaxDynamicSharedMemorySize, SMEM_MMA);
    cudaFuncSetAttribute(k_qk,      cudaFuncAttributeMaxDynamicSharedMemorySize, SMEM_QK);

    // ---- weight conversion (once per call) ----
    for (int l = 0; l < NL; l++) {
        k_convs<<<1024, 256>>>(wq + (size_t)l*D_*1024, p_cqh + (size_t)l*D_*QKV_,        p_cql + (size_t)l*D_*QKV_,        1024, QKV_);
        k_convs<<<256,  256>>>(wk + (size_t)l*D_*256,  p_cqh + (size_t)l*D_*QKV_ + 1024, p_cql + (size_t)l*D_*QKV_ + 1024, 256,  QKV_);
        k_convs<<<256,  256>>>(wv + (size_t)l*D_*256,  p_cqh + (size_t)l*D_*QKV_ + 1280, p_cql + (size_t)l*D_*QKV_ + 1280, 256,  QKV_);
    }
    k_split8<<<1024,  256>>>(wo, p_cwoh, p_cwol);
    k_split8<<<16384, 256>>>(w1, p_c1h,  p_c1l);
    k_split8<<<16384, 256>>>(w3, p_c3h,  p_c3l);
    k_split8<<<16384, 256>>>(w2, p_c2h,  p_c2l);
    k_split8<<<16000, 256>>>(lm, p_clh,  p_cll);

    k_zero_aux<<<1, 32>>>();
    k_embed<<<T_, 256>>>(ids, embed_W);

    for (int l = 0; l < NL; l++) {
        // attention
        k_rms<<<T_, 256>>>(p_h, n1 + (size_t)l*D_, p_xn);
        k_split8<<<1024, 256>>>(p_xn, p_ah, p_al);
        k_mma<<<dim3(16, 12), 256, SMEM_MMA>>>(p_ah, p_al,
            p_cqh + (size_t)l*D_*QKV_, p_cql + (size_t)l*D_*QKV_, p_qkv, D_, QKV_, QKV_, 0);
        k_rope<<<T_, 512>>>();
        k_split8<<<1536, 256>>>(p_qkv, p_qkvh, p_qkvl);
        k_qk<<<dim3(4, 4, 64), 256, SMEM_QK>>>();
        k_softmax<<<NCK*NH*CH, 256>>>();
        k_avm<<<dim3(4, 1, 64), 256, SMEM_MMA>>>();
        k_split8<<<1024, 256>>>(p_attn, p_ah, p_al);
        k_mma<<<dim3(16, 8), 256, SMEM_MMA>>>(p_ah, p_al,
            p_cwoh + (size_t)l*D_*D_, p_cwol + (size_t)l*D_*D_, p_h, D_, D_, D_, 1);

        // MoE
        k_rms<<<T_, 256>>>(p_h, n2 + (size_t)l*D_, p_xn);
        k_split8<<<1024, 256>>>(p_xn, p_ah, p_al);
        k_router<<<T_/8, 256>>>(rw + (size_t)l*D_*NE);
        k_aux<<<1, 256>>>();
        k_zero_cnt<<<1, 32>>>();
        k_bucket<<<T_/256, 256>>>();
        k_moe_mma<<<dim3(16, 16, NE), 256, SMEM_MMA>>>(p_c1h + (size_t)l*NE*D_*F_, p_c1l + (size_t)l*NE*D_*F_, 0);
        k_moe_mma<<<dim3(16, 16, NE), 256, SMEM_MMA>>>(p_c3h + (size_t)l*NE*D_*F_, p_c3l + (size_t)l*NE*D_*F_, 1);
        k_moe_mma<<<dim3(16, 8,  NE), 256, SMEM_MMA>>>(p_c2h + (size_t)l*NE*F_*D_, p_c2l + (size_t)l*NE*F_*D_, 2);
        k_combine<<<T_, 256>>>();
    }

    // final norm + heads
    k_rms<<<T_, 256>>>(p_h, normf, p_xn);
    k_split8<<<1024, 256>>>(p_xn, p_ah, p_al);
    k_mma<<<dim3(16, NV/128), 256, SMEM_MMA>>>(p_ah, p_al, p_clh, p_cll, out, D_, NV, NV, 0);
    k_task<<<16, 256>>>(tw, tb, out);
    k_mean1<<<16, 256>>>();
    k_mean2<<<4, 256>>>();
    k_eval<<<8, 256>>>(ew, eb, out);
    k_auxw<<<1, 1>>>(out);
}

// round 11
// speedup vs baseline: 2.7717x; 1.1095x over previous
#include <cuda_runtime.h>
#include <cuda_bf16.h>
#include <math.h>
#include <stdint.h>

#define T_   2048
#define D_   1024
#define NH   16
#define NKV  4
#define F_   2048
#define NE   8
#define NL   2
#define NV   32000
#define CH   512
#define NCK  4
#define QKV_ 1536

#define OUT_TASK   (T_*(size_t)NV)
#define OUT_EVAL   (OUT_TASK + 16)
#define OUT_AUX    (OUT_EVAL + 8)

typedef __nv_bfloat16 bf16;
typedef __nv_bfloat162 bf162;

// ---------------- scratch (device globals; no allocation) ----------------
__device__ float g_h   [(size_t)T_*D_];
__device__ float g_xn  [(size_t)T_*D_];
__device__ float g_qkv [(size_t)T_*QKV_];
__device__ float g_sc  [(size_t)NCK*NH*CH*CH];
__device__ float g_attn[(size_t)T_*D_];
__device__ float g_probs[(size_t)T_*NE];
__device__ int   g_ti  [T_*2];
__device__ float g_tw  [T_*2];
__device__ int   g_cnt [NE];
__device__ int   g_rows[NE*T_];
__device__ int   g_slot[T_*2];
__device__ float g_yb  [(size_t)NE*T_*D_];
__device__ float g_aux [1];
__device__ float g_xm  [D_];
__device__ float g_mp  [16*D_];
__device__ bf16  g_ah  [(size_t)T_*D_];
__device__ bf16  g_al  [(size_t)T_*D_];
__device__ bf16  g_qkvh[(size_t)T_*QKV_];
__device__ bf16  g_qkvl[(size_t)T_*QKV_];
__device__ float g_ub  [(size_t)NE*T_*F_];
__device__ bf16  g_hbh [(size_t)NE*T_*F_];   // also reused as P hi
__device__ bf16  g_hbl [(size_t)NE*T_*F_];   // also reused as P lo
// pre-converted weights (hi/lo bf16)
__device__ bf16  c_qkvh[(size_t)NL*D_*QKV_], c_qkvl[(size_t)NL*D_*QKV_];
__device__ bf16  c_woh [(size_t)NL*D_*D_],   c_wol [(size_t)NL*D_*D_];
__device__ bf16  c_w1h [(size_t)NL*NE*D_*F_], c_w1l[(size_t)NL*NE*D_*F_];
__device__ bf16  c_w3h [(size_t)NL*NE*D_*F_], c_w3l[(size_t)NL*NE*D_*F_];
__device__ bf16  c_w2h [(size_t)NL*NE*F_*D_], c_w2l[(size_t)NL*NE*F_*D_];
__device__ bf16  c_lmh [(size_t)D_*NV],      c_lml[(size_t)D_*NV];

// ---------------- asm helpers ----------------
__device__ __forceinline__ uint32_t smem_u32(const void* p) {
    uint32_t a;
    asm("{ .reg .u64 t; cvta.to.shared.u64 t, %1; cvt.u32.u64 %0, t; }" : "=r"(a) : "l"(p));
    return a;
}
__device__ __forceinline__ void cpa(uint32_t d, const void* s) {
    asm volatile("cp.async.cg.shared.global [%0], [%1], 16;" :: "r"(d), "l"(s));
}
__device__ __forceinline__ void cp_commit() { asm volatile("cp.async.commit_group;" ::: "memory"); }
__device__ __forceinline__ void cp_wait1()  { asm volatile("cp.async.wait_group 1;" ::: "memory"); }
__device__ __forceinline__ void cp_wait0()  { asm volatile("cp.async.wait_group 0;" ::: "memory"); }
__device__ __forceinline__ void ldsm4(uint32_t (&r)[4], uint32_t a) {
    asm volatile("ldmatrix.sync.aligned.m8n8.x4.shared.b16 {%0,%1,%2,%3}, [%4];"
        : "=r"(r[0]), "=r"(r[1]), "=r"(r[2]), "=r"(r[3]) : "r"(a));
}
__device__ __forceinline__ void ldsm4t(uint32_t (&r)[4], uint32_t a) {
    asm volatile("ldmatrix.sync.aligned.m8n8.x4.trans.shared.b16 {%0,%1,%2,%3}, [%4];"
        : "=r"(r[0]), "=r"(r[1]), "=r"(r[2]), "=r"(r[3]) : "r"(a));
}
__device__ __forceinline__ void ldsm2t(uint32_t (&r)[2], uint32_t a) {
    asm volatile("ldmatrix.sync.aligned.m8n8.x2.trans.shared.b16 {%0,%1}, [%2];"
        : "=r"(r[0]), "=r"(r[1]) : "r"(a));
}
__device__ __forceinline__ void ldsm2(uint32_t (&r)[2], uint32_t a) {
    asm volatile("ldmatrix.sync.aligned.m8n8.x2.shared.b16 {%0,%1}, [%2];"
        : "=r"(r[0]), "=r"(r[1]) : "r"(a));
}
__device__ __forceinline__ void mma16816(float (&d)[4], const uint32_t (&a)[4], const uint32_t (&b)[2]) {
    asm volatile("mma.sync.aligned.m16n8k16.row.col.f32.bf16.bf16.f32 "
        "{%0,%1,%2,%3}, {%4,%5,%6,%7}, {%8,%9}, {%0,%1,%2,%3};"
        : "+f"(d[0]), "+f"(d[1]), "+f"(d[2]), "+f"(d[3])
        : "r"(a[0]), "r"(a[1]), "r"(a[2]), "r"(a[3]), "r"(b[0]), "r"(b[1]));
}

// ============== 128x256 tile GEMM (main path) ==============
// per buffer: Ah 128x80B @0 | Al @10240 | Bh 32x528B @20480 | Bl @37376
#define W_OFF_AL 10240
#define W_OFF_BH 20480
#define W_OFF_BL 37376
#define W_BUFSZ  54272
#define SMEM_W   (3*W_BUFSZ)

// modes: 0 = C=acc, 1 = C+=acc, 2 = silu(U)*acc -> split bf16 to Hh/Hl
__device__ __forceinline__ void mma_block256(
    const bf16* __restrict__ Ah, const bf16* __restrict__ Al, int lda,
    const int* __restrict__ rows, int count, int m0,
    const bf16* __restrict__ Bh, const bf16* __restrict__ Bl, int ldb, int n0,
    int K, float* __restrict__ C, int ldc, int mode,
    const float* __restrict__ U, bf16* __restrict__ Hh, bf16* __restrict__ Hl,
    char* dsm, uint32_t sb)
{
    const int tid = threadIdx.x, lane = tid & 31, wid = tid >> 5;
    const int wm = (wid & 1) * 64, wn = (wid >> 1) * 64;
    const int ar = tid >> 1, akc = (tid & 1) * 16;
    const int gm = m0 + ar;
    const bool av = gm < count;
    const bf16 *pAh = nullptr, *pAl = nullptr;
    if (av) {
        size_t rr = (size_t)(rows ? rows[gm] : gm) * lda + akc;
        pAh = Ah + rr; pAl = Al + rr;
    }
    const uint32_t ao = (uint32_t)ar * 80 + (uint32_t)akc * 2;

    if (!av) {
        uint4 z = make_uint4(0,0,0,0);
        #pragma unroll
        for (int s = 0; s < 3; s++) {
            char* bb = dsm + s * W_BUFSZ;
            *(uint4*)(bb + ao) = z;              *(uint4*)(bb + ao + 16) = z;
            *(uint4*)(bb + W_OFF_AL + ao) = z;   *(uint4*)(bb + W_OFF_AL + ao + 16) = z;
        }
    }

    float acc[4][8][4];
    #pragma unroll
    for (int a = 0; a < 4; a++)
        #pragma unroll
        for (int b = 0; b < 8; b++)
            #pragma unroll
            for (int c = 0; c < 4; c++) acc[a][b][c] = 0.f;

    auto ISSUE = [&](int k0, uint32_t sbuf) {
        if (av) {
            cpa(sbuf + ao,                 pAh + k0);
            cpa(sbuf + ao + 16,            pAh + k0 + 8);
            cpa(sbuf + W_OFF_AL + ao,      pAl + k0);
            cpa(sbuf + W_OFF_AL + ao + 16, pAl + k0 + 8);
        }
        #pragma unroll
        for (int j = 0; j < 4; j++) {
            int u = tid + j * 256;
            int row = u >> 5, c16 = u & 31;
            uint32_t doff = (uint32_t)row * 528 + (uint32_t)c16 * 16;
            const bf16* sh = Bh + (size_t)(k0 + row) * ldb + n0 + c16 * 8;
            const bf16* sl = Bl + (size_t)(k0 + row) * ldb + n0 + c16 * 8;
            cpa(sbuf + W_OFF_BH + doff, sh);
            cpa(sbuf + W_OFF_BL + doff, sl);
        }
    };

    auto COMPUTE = [&](uint32_t boff) {
        uint32_t abase = sb + boff + (uint32_t)(wm + (lane & 15)) * 80 + ((lane >> 4) * 16);
        uint32_t klocal = (uint32_t)((lane & 7) + ((lane >> 3) & 1) * 8);
        uint32_t bcol = (uint32_t)(wn + ((lane >> 4) & 1) * 8);
        #pragma unroll
        for (int ks = 0; ks < 2; ks++) {
            uint32_t ah4[4][4], al4[4][4];
            #pragma unroll
            for (int mt = 0; mt < 4; mt++) {
                uint32_t aa = abase + mt * (16 * 80) + ks * 32;
                ldsm4(ah4[mt], aa);
                ldsm4(al4[mt], aa + W_OFF_AL);
            }
            uint32_t bh[4][4], bl[4][4];
            uint32_t bkb = sb + boff + W_OFF_BH + (klocal + ks * 16) * 528 + bcol * 2;
            #pragma unroll
            for (int ng = 0; ng < 4; ng++) {
                uint32_t ba = bkb + ng * 32;   // 16 cols * 2B
                ldsm4t(bh[ng], ba);
                ldsm4t(bl[ng], ba + (W_OFF_BL - W_OFF_BH));
            }
            #pragma unroll
            for (int mt = 0; mt < 4; mt++)
                #pragma unroll
                for (int nt = 0; nt < 8; nt++) {
                    const int ng = nt >> 1, hf = (nt & 1) * 2;
                    uint32_t bhf[2] = { bh[ng][hf], bh[ng][hf + 1] };
                    uint32_t blf[2] = { bl[ng][hf], bl[ng][hf + 1] };
                    mma16816(acc[mt][nt], ah4[mt], bhf);
                    mma16816(acc[mt][nt], ah4[mt], blf);
                    mma16816(acc[mt][nt], al4[mt], bhf);
                }
        }
    };

    const int NC = K >> 5;
    ISSUE(0, sb); cp_commit();
    if (NC > 1) { ISSUE(32, sb + W_BUFSZ); cp_commit(); }
    for (int c = 0; c < NC; c++) {
        if (c == NC - 1) cp_wait0(); else cp_wait1();
        __syncthreads();
        COMPUTE((uint32_t)(c % 3) * W_BUFSZ);
        if (c + 2 < NC) { ISSUE((c + 2) << 5, sb + (uint32_t)((c + 2) % 3) * W_BUFSZ); cp_commit(); }
    }

    #pragma unroll
    for (int mt = 0; mt < 4; mt++) {
        int r0 = m0 + wm + mt * 16 + (lane >> 2);
        #pragma unroll
        for (int nt = 0; nt < 8; nt++) {
            int cc = n0 + wn + nt * 8 + (lane & 3) * 2;
            float* d = acc[mt][nt];
            #pragma unroll
            for (int hrow = 0; hrow < 2; hrow++) {
                int r = r0 + hrow * 8;
                if (r >= count) continue;
                float d0 = d[hrow*2], d1 = d[hrow*2 + 1];
                size_t o = (size_t)r * ldc + cc;
                if (mode == 0) {
                    *(float2*)(C + o) = make_float2(d0, d1);
                } else if (mode == 1) {
                    float2 p = *(const float2*)(C + o);
                    *(float2*)(C + o) = make_float2(p.x + d0, p.y + d1);
                } else {
                    float2 u = *(const float2*)(U + o);
                    float h0 = (u.x / (1.f + expf(-u.x))) * d0;
                    float h1 = (u.y / (1.f + expf(-u.y))) * d1;
                    bf162 hh = __floats2bfloat162_rn(h0, h1);
                    bf162 ll = __floats2bfloat162_rn(h0 - __low2float(hh), h1 - __high2float(hh));
                    *(bf162*)(Hh + o) = hh;
                    *(bf162*)(Hl + o) = ll;
                }
            }
        }
    }
}

// dense GEMM: grid (M/128, N/256)
__global__ __launch_bounds__(256, 1) void k_mma256(
    const bf16* __restrict__ Ah, const bf16* __restrict__ Al,
    const bf16* __restrict__ Bh, const bf16* __restrict__ Bl,
    float* __restrict__ C, int K, int ldb, int ldc, int mode)
{
    extern __shared__ __align__(16) char dsm[];
    mma_block256(Ah, Al, K, nullptr, 1 << 30, blockIdx.x * 128,
                 Bh, Bl, ldb, blockIdx.y * 256,
                 K, C, ldc, mode, nullptr, nullptr, nullptr, dsm, smem_u32(dsm));
}

// MoE: which 0 = X W1 -> g_ub; 1 = X W3 fused silu -> hidden split; 2 = H W2 -> g_yb
__global__ __launch_bounds__(256, 1) void k_moe_mma(
    const bf16* __restrict__ Wh, const bf16* __restrict__ Wl, int which)
{
    int e = blockIdx.z;
    int count = g_cnt[e];
    int m0 = blockIdx.x * 128;
    if (m0 >= count) return;
    int n0 = blockIdx.y * 256;
    extern __shared__ __align__(16) char dsm[];
    uint32_t sb = smem_u32(dsm);
    if (which == 0) {
        mma_block256(g_ah, g_al, D_, g_rows + e * T_, count, m0,
                     Wh + (size_t)e * D_ * F_, Wl + (size_t)e * D_ * F_, F_, n0,
                     D_, g_ub + (size_t)e * T_ * F_, F_, 0, nullptr, nullptr, nullptr, dsm, sb);
    } else if (which == 1) {
        mma_block256(g_ah, g_al, D_, g_rows + e * T_, count, m0,
                     Wh + (size_t)e * D_ * F_, Wl + (size_t)e * D_ * F_, F_, n0,
                     D_, nullptr, F_, 2, g_ub + (size_t)e * T_ * F_,
                     g_hbh + (size_t)e * T_ * F_, g_hbl + (size_t)e * T_ * F_, dsm, sb);
    } else {
        mma_block256(g_hbh + (size_t)e * T_ * F_, g_hbl + (size_t)e * T_ * F_, F_, nullptr, count, m0,
                     Wh + (size_t)e * F_ * D_, Wl + (size_t)e * F_ * D_, D_, n0,
                     F_, g_yb + (size_t)e * T_ * D_, D_, 0, nullptr, nullptr, nullptr, dsm, sb);
    }
}

// ============== 128x128 tile path (k_avm only, nlim=64) ==============
#define OFF_AL 10240
#define OFF_BH 20480
#define OFF_BL 29184
#define BUFSZ  37888
#define SMEM_MMA128 (3*BUFSZ)

__device__ __forceinline__ void mma_block128(
    const bf16* __restrict__ Ah, const bf16* __restrict__ Al, int lda,
    int count, int m0,
    const bf16* __restrict__ Bh, const bf16* __restrict__ Bl, int ldb, int n0, int nlim,
    int K, float* __restrict__ C, int ldc,
    char* dsm, uint32_t sb)
{
    const int tid = threadIdx.x, lane = tid & 31, wid = tid >> 5;
    const int wm = (wid & 1) * 64, wn = (wid >> 1) * 32;
    const int ar = tid >> 1, akc = (tid & 1) * 16;
    const int bkr = tid >> 3, bn16 = (tid & 7) * 16;
    const int gm = m0 + ar;
    const bool av = gm < count;
    const bf16 *pAh = nullptr, *pAl = nullptr;
    if (av) {
        size_t rr = (size_t)gm * lda + akc;
        pAh = Ah + rr; pAl = Al + rr;
    }
    const int bcol = (nlim < 128) ? (bn16 & (nlim - 1)) : bn16;
    const bf16* pBh = Bh + (size_t)bkr * ldb + n0 + bcol;
    const bf16* pBl = Bl + (size_t)bkr * ldb + n0 + bcol;
    const uint32_t ao = (uint32_t)ar * 80 + (uint32_t)akc * 2;
    const uint32_t bo = (uint32_t)OFF_BH + (uint32_t)bkr * 272 + (uint32_t)bn16 * 2;

    if (!av) {
        uint4 z = make_uint4(0,0,0,0);
        #pragma unroll
        for (int s = 0; s < 3; s++) {
            char* bb = dsm + s * BUFSZ;
            *(uint4*)(bb + ao) = z;            *(uint4*)(bb + ao + 16) = z;
            *(uint4*)(bb + OFF_AL + ao) = z;   *(uint4*)(bb + OFF_AL + ao + 16) = z;
        }
    }

    float acc[4][4][4];
    #pragma unroll
    for (int a = 0; a < 4; a++)
        #pragma unroll
        for (int b = 0; b < 4; b++)
            #pragma unroll
            for (int c = 0; c < 4; c++) acc[a][b][c] = 0.f;

    auto ISSUE = [&](int k0, uint32_t sbuf) {
        if (av) {
            cpa(sbuf + ao,               pAh + k0);
            cpa(sbuf + ao + 16,          pAh + k0 + 8);
            cpa(sbuf + OFF_AL + ao,      pAl + k0);
            cpa(sbuf + OFF_AL + ao + 16, pAl + k0 + 8);
        }
        const bf16* b = pBh + (size_t)k0 * ldb;
        cpa(sbuf + bo,      b);
        cpa(sbuf + bo + 16, b + 8);
        b = pBl + (size_t)k0 * ldb;
        cpa(sbuf + (OFF_BL - OFF_BH) + bo,      b);
        cpa(sbuf + (OFF_BL - OFF_BH) + bo + 16, b + 8);
    };

    auto COMPUTE = [&](uint32_t boff) {
        uint32_t abase = sb + boff + (uint32_t)(wm + (lane & 15)) * 80 + ((lane >> 4) * 8) * 2;
        uint32_t bbase = sb + boff + OFF_BH
                       + (uint32_t)((lane & 7) + ((lane >> 3) & 1) * 8) * 272
                       + (uint32_t)wn * 2;
        #pragma unroll
        for (int ks = 0; ks < 2; ks++) {
            uint32_t ah4[4][4], al4[4][4], bh2[4][2], bl2[4][2];
            #pragma unroll
            for (int mt = 0; mt < 4; mt++) {
                uint32_t aa = abase + mt * (16 * 80) + ks * 32;
                ldsm4(ah4[mt], aa);
                ldsm4(al4[mt], aa + OFF_AL);
            }
            #pragma unroll
            for (int nt = 0; nt < 4; nt++) {
                uint32_t ba = bbase + ks * (16 * 272) + nt * 16;
                ldsm2t(bh2[nt], ba);
                ldsm2t(bl2[nt], ba + (OFF_BL - OFF_BH));
            }
            #pragma unroll
            for (int mt = 0; mt < 4; mt++)
                #pragma unroll
                for (int nt = 0; nt < 4; nt++) {
                    mma16816(acc[mt][nt], ah4[mt], bh2[nt]);
                    mma16816(acc[mt][nt], ah4[mt], bl2[nt]);
                    mma16816(acc[mt][nt], al4[mt], bh2[nt]);
                }
        }
    };

    const int NC = K >> 5;
    ISSUE(0, sb); cp_commit();
    if (NC > 1) { ISSUE(32, sb + BUFSZ); cp_commit(); }
    for (int c = 0; c < NC; c++) {
        if (c == NC - 1) cp_wait0(); else cp_wait1();
        __syncthreads();
        COMPUTE((uint32_t)(c % 3) * BUFSZ);
        if (c + 2 < NC) { ISSUE((c + 2) << 5, sb + (uint32_t)((c + 2) % 3) * BUFSZ); cp_commit(); }
    }

    #pragma unroll
    for (int mt = 0; mt < 4; mt++) {
        int r0 = m0 + wm + mt * 16 + (lane >> 2);
        #pragma unroll
        for (int nt = 0; nt < 4; nt++) {
            int ln = wn + nt * 8 + (lane & 3) * 2;
            if (ln >= nlim) continue;
            int cc = n0 + ln;
            float* d = acc[mt][nt];
            #pragma unroll
            for (int hrow = 0; hrow < 2; hrow++) {
                int r = r0 + hrow * 8;
                if (r >= count) continue;
                *(float2*)(C + (size_t)r * ldc + cc) = make_float2(d[hrow*2], d[hrow*2 + 1]);
            }
        }
    }
}

// O = P V: grid (4, 1, 64); P split lives in g_hbh/g_hbl
__global__ __launch_bounds__(256, 1) void k_avm()
{
    int b = blockIdx.z, chunk = b >> 4, head = b & 15, kvh = head >> 2;
    extern __shared__ __align__(16) char dsm[];
    mma_block128(g_hbh + (size_t)b * CH * CH, g_hbl + (size_t)b * CH * CH, CH, CH, blockIdx.x * 128,
                 g_qkvh + (size_t)chunk * CH * QKV_ + 1280 + kvh * 64,
                 g_qkvl + (size_t)chunk * CH * QKV_ + 1280 + kvh * 64, QKV_, 0, 64,
                 CH, g_attn + (size_t)chunk * CH * D_ + head * 64, D_, dsm, smem_u32(dsm));
}

// ---------------- scores S = Q K^T: grid (4, 4, 64); skips n0>m0 tiles ----------------
#define QK_AL 10240
#define QK_KH 20480
#define QK_KL 30720
#define QK_BUF 40960
#define SMEM_QK (2*QK_BUF)

__global__ __launch_bounds__(256, 1) void k_qk()
{
    if (blockIdx.y > blockIdx.x) return;
    extern __shared__ __align__(16) char dsm[];
    uint32_t sb = smem_u32(dsm);
    int b = blockIdx.z, chunk = b >> 4, head = b & 15, kvh = head >> 2;
    int m0 = blockIdx.x * 128, n0 = blockIdx.y * 128;
    int tid = threadIdx.x, lane = tid & 31, wid = tid >> 5;
    int wm = (wid & 1) * 64, wn = (wid >> 1) * 32;
    int ar = tid >> 1, akc = (tid & 1) * 16;
    const bf16* pQh = g_qkvh + (size_t)(chunk*CH + m0 + ar) * QKV_ + head * 64 + akc;
    const bf16* pQl = g_qkvl + (size_t)(chunk*CH + m0 + ar) * QKV_ + head * 64 + akc;
    const bf16* pKh = g_qkvh + (size_t)(chunk*CH + n0 + ar) * QKV_ + 1024 + kvh * 64 + akc;
    const bf16* pKl = g_qkvl + (size_t)(chunk*CH + n0 + ar) * QKV_ + 1024 + kvh * 64 + akc;
    const uint32_t ao = (uint32_t)ar * 80 + (uint32_t)akc * 2;

    float acc[4][4][4];
    #pragma unroll
    for (int a = 0; a < 4; a++)
        #pragma unroll
        for (int bb = 0; bb < 4; bb++)
            #pragma unroll
            for (int c = 0; c < 4; c++) acc[a][bb][c] = 0.f;

    auto ISSUE = [&](int k0, uint32_t sbuf) {
        cpa(sbuf + ao,               pQh + k0); cpa(sbuf + ao + 16,           pQh + k0 + 8);
        cpa(sbuf + QK_AL + ao,       pQl + k0); cpa(sbuf + QK_AL + ao + 16,   pQl + k0 + 8);
        cpa(sbuf + QK_KH + ao,       pKh + k0); cpa(sbuf + QK_KH + ao + 16,   pKh + k0 + 8);
        cpa(sbuf + QK_KL + ao,       pKl + k0); cpa(sbuf + QK_KL + ao + 16,   pKl + k0 + 8);
    };
    auto COMPUTE = [&](uint32_t boff) {
        uint32_t abase = sb + boff + (uint32_t)(wm + (lane & 15)) * 80 + ((lane >> 4) * 8) * 2;
        #pragma unroll
        for (int ks = 0; ks < 2; ks++) {
            uint32_t ah4[4][4], al4[4][4], bh2[4][2], bl2[4][2];
            #pragma unroll
            for (int mt = 0; mt < 4; mt++) {
                uint32_t aa = abase + mt * (16 * 80) + ks * 32;
                ldsm4(ah4[mt], aa);
                ldsm4(al4[mt], aa + QK_AL);
            }
            #pragma unroll
            for (int nt = 0; nt < 4; nt++) {
                uint32_t ba = sb + boff + QK_KH
                            + (uint32_t)(wn + nt * 8 + (lane & 7)) * 80
                            + ks * 32 + ((lane >> 3) & 1) * 16;
                ldsm2(bh2[nt], ba);
                ldsm2(bl2[nt], ba + (QK_KL - QK_KH));
            }
            #pragma unroll
            for (int mt = 0; mt < 4; mt++)
                #pragma unroll
                for (int nt = 0; nt < 4; nt++) {
                    mma16816(acc[mt][nt], ah4[mt], bh2[nt]);
                    mma16816(acc[mt][nt], ah4[mt], bl2[nt]);
                    mma16816(acc[mt][nt], al4[mt], bh2[nt]);
                }
        }
    };

    ISSUE(0, sb); cp_commit();
    ISSUE(32, sb + QK_BUF); cp_commit();
    cp_wait1(); __syncthreads(); COMPUTE(0);
    cp_wait0(); __syncthreads(); COMPUTE(QK_BUF);

    float* S = g_sc + (size_t)b * CH * CH;
    #pragma unroll
    for (int mt = 0; mt < 4; mt++) {
        int r0 = wm + mt * 16 + (lane >> 2);
        #pragma unroll
        for (int nt = 0; nt < 4; nt++) {
            int c0 = wn + nt * 8 + (lane & 3) * 2;
            float* d = acc[mt][nt];
            #pragma unroll
            for (int hrow = 0; hrow < 2; hrow++) {
                int qg = m0 + r0 + hrow * 8;
                int kg = n0 + c0;
                float v0 = d[hrow*2] * 0.125f, v1 = d[hrow*2 + 1] * 0.125f;
                if (kg > qg)     v0 = -1e30f;
                if (kg + 1 > qg) v1 = -1e30f;
                *(float2*)(S + (size_t)qg * CH + kg) = make_float2(v0, v1);
            }
        }
    }
}

// ---- fp32 -> bf16 hi/lo, 8 elems/thread ----
__device__ __forceinline__ void split8_body(const float* __restrict__ x,
    bf16* __restrict__ hh, bf16* __restrict__ ll, size_t i) {
    const float4* xv = (const float4*)x;
    float4 a = xv[2*i], b = xv[2*i+1];
    bf162 h0 = __floats2bfloat162_rn(a.x, a.y);
    bf162 h1 = __floats2bfloat162_rn(a.z, a.w);
    bf162 h2 = __floats2bfloat162_rn(b.x, b.y);
    bf162 h3 = __floats2bfloat162_rn(b.z, b.w);
    bf162 l0 = __floats2bfloat162_rn(a.x - __low2float(h0), a.y - __high2float(h0));
    bf162 l1 = __floats2bfloat162_rn(a.z - __low2float(h1), a.w - __high2float(h1));
    bf162 l2 = __floats2bfloat162_rn(b.x - __low2float(h2), b.y - __high2float(h2));
    bf162 l3 = __floats2bfloat162_rn(b.z - __low2float(h3), b.w - __high2float(h3));
    ((uint4*)hh)[i] = make_uint4(*(uint32_t*)&h0, *(uint32_t*)&h1, *(uint32_t*)&h2, *(uint32_t*)&h3);
    ((uint4*)ll)[i] = make_uint4(*(uint32_t*)&l0, *(uint32_t*)&l1, *(uint32_t*)&l2, *(uint32_t*)&l3);
}
__global__ void k_split8(const float* __restrict__ x, bf16* __restrict__ hh, bf16* __restrict__ ll) {
    split8_body(x, hh, ll, (size_t)blockIdx.x * 256 + threadIdx.x);
}
// all qkv weight segments in one launch: grid (1024, 6)
__global__ void k_convqkv(const float* __restrict__ wq, const float* __restrict__ wk,
                          const float* __restrict__ wv) {
    int seg = blockIdx.y, l = seg / 3, which = seg - l * 3;
    const float* src; int N; size_t doff;
    if (which == 0)      { src = wq + (size_t)l*D_*1024; N = 1024; doff = (size_t)l*D_*QKV_; }
    else if (which == 1) { src = wk + (size_t)l*D_*256;  N = 256;  doff = (size_t)l*D_*QKV_ + 1024; }
    else                 { src = wv + (size_t)l*D_*256;  N = 256;  doff = (size_t)l*D_*QKV_ + 1280; }
    size_t i = (size_t)blockIdx.x * 256 + threadIdx.x;
    size_t e = i * 4;
    if (e >= (size_t)D_ * N) return;
    int r = (int)(e / N), c = (int)(e % N);
    float4 v = *(const float4*)(src + e);
    size_t o = doff + (size_t)r * QKV_ + c;
    bf162 h0 = __floats2bfloat162_rn(v.x, v.y);
    bf162 l0 = __floats2bfloat162_rn(v.x - __low2float(h0), v.y - __high2float(h0));
    bf162 h1 = __floats2bfloat162_rn(v.z, v.w);
    bf162 l1 = __floats2bfloat162_rn(v.z - __low2float(h1), v.w - __high2float(h1));
    *(bf162*)(c_qkvh+o) = h0; *(bf162*)(c_qkvh+o+2) = h1;
    *(bf162*)(c_qkvl+o) = l0; *(bf162*)(c_qkvl+o+2) = l1;
}
// wo/w1/w3/w2/lm in one launch: grid (16384, 5)
__global__ void k_convw5(const float* __restrict__ wo, const float* __restrict__ w1,
                         const float* __restrict__ w3, const float* __restrict__ w2,
                         const float* __restrict__ lm) {
    int y = blockIdx.y;
    const float* src; bf16 *dh, *dl; size_t n;
    if (y == 0)      { src = wo; dh = c_woh; dl = c_wol; n = (size_t)NL*D_*D_; }
    else if (y == 1) { src = w1; dh = c_w1h; dl = c_w1l; n = (size_t)NL*NE*D_*F_; }
    else if (y == 2) { src = w3; dh = c_w3h; dl = c_w3l; n = (size_t)NL*NE*D_*F_; }
    else if (y == 3) { src = w2; dh = c_w2h; dl = c_w2l; n = (size_t)NL*NE*F_*D_; }
    else             { src = lm; dh = c_lmh; dl = c_lml; n = (size_t)D_*NV; }
    size_t i = (size_t)blockIdx.x * 256 + threadIdx.x;
    if (i * 8 >= n) return;
    split8_body(src, dh, dl, i);
}

// ---------------- misc kernels ----------------
__global__ void k_zero_cnt() { if (threadIdx.x < NE) g_cnt[threadIdx.x] = 0; }
__global__ void k_embed(const int* __restrict__ ids, const float* __restrict__ ew) {
    int t = blockIdx.x;
    if (t == 0 && threadIdx.x == 0) g_aux[0] = 0.f;
    size_t r = (size_t)ids[t] * D_;
    for (int d = threadIdx.x; d < D_; d += blockDim.x) g_h[(size_t)t*D_ + d] = ew[r + d];
}
__global__ void k_rms(const float* __restrict__ x, const float* __restrict__ w, float* __restrict__ out) {
    int t = blockIdx.x, tid = threadIdx.x;
    __shared__ float sh[256];
    const float* xr = x + (size_t)t*D_;
    float s = 0.f;
    for (int d = tid; d < D_; d += 256) { float v = xr[d]; s += v*v; }
    sh[tid] = s; __syncthreads();
    for (int o = 128; o > 0; o >>= 1) { if (tid < o) sh[tid] += sh[tid+o]; __syncthreads(); }
    float scale = rsqrtf(sh[0] / (float)D_ + 1e-6f);
    float* orow = out + (size_t)t*D_;
    for (int d = tid; d < D_; d += 256) orow[d] = w[d] * xr[d] * scale;
}
__global__ void k_rope() {
    int t = blockIdx.x, tid = threadIdx.x;
    float p = (float)(t & (CH-1));
    float* base = g_qkv + (size_t)t*QKV_;
    if (tid < NH*32) {
        int h = tid >> 5, i = tid & 31;
        float ang = p * powf(1000000.0f, -(float)i/32.0f);
        float c = cosf(ang), s = sinf(ang);
        float* q = base + h*64 + 2*i;
        float x1 = q[0], x2 = q[1];
        q[0] = x1*c - x2*s; q[1] = x1*s + x2*c;
    }
    if (tid < NKV*32) {
        int h = tid >> 5, i = tid & 31;
        float ang = p * powf(1000000.0f, -(float)i/32.0f);
        float c = cosf(ang), s = sinf(ang);
        float* kk = base + 1024 + h*64 + 2*i;
        float x1 = kk[0], x2 = kk[1];
        kk[0] = x1*c - x2*s; kk[1] = x1*s + x2*c;
    }
}
// fused softmax: reads fp32 S, writes P directly as bf16 hi/lo into g_hbh/g_hbl
__global__ void k_softmax() {
    int row = blockIdx.x;
    int q = row & (CH-1);
    int tid = threadIdx.x;
    const float* r = g_sc + (size_t)row*CH;
    __shared__ float sh[256];
    int c0 = tid * 2;
    bool v0 = (c0 <= q), v1 = (c0 + 1 <= q);
    float x0 = v0 ? r[c0]   : -1e30f;
    float x1 = v1 ? r[c0+1] : -1e30f;
    sh[tid] = fmaxf(x0, x1); __syncthreads();
    for (int o = 128; o > 0; o >>= 1) { if (tid < o) sh[tid] = fmaxf(sh[tid], sh[tid+o]); __syncthreads(); }
    float m = sh[0]; __syncthreads();
    float e0 = v0 ? expf(x0 - m) : 0.f;
    float e1 = v1 ? expf(x1 - m) : 0.f;
    sh[tid] = e0 + e1; __syncthreads();
    for (int o = 128; o > 0; o >>= 1) { if (tid < o) sh[tid] += sh[tid+o]; __syncthreads(); }
    float inv = 1.f / sh[0];
    float p0 = e0 * inv, p1 = e1 * inv;
    bf162 hh = __floats2bfloat162_rn(p0, p1);
    bf162 ll = __floats2bfloat162_rn(p0 - __low2float(hh), p1 - __high2float(hh));
    size_t o = (size_t)row * CH + c0;
    *(bf162*)(g_hbh + o) = hh;
    *(bf162*)(g_hbl + o) = ll;
}
__global__ void k_router(const float* __restrict__ rw) {
    int tid = threadIdx.x, lane = tid & 31, w = tid >> 5;
    int t = blockIdx.x*8 + w;
    const float* xr = g_xn + (size_t)t*D_;
    float acc[NE] = {};
    for (int dd = 0; dd < 32; dd++) {
        int d = dd*32 + lane;
        float x = xr[d];
        const float* rr = rw + (size_t)d*NE;
        #pragma unroll
        for (int e = 0; e < NE; e++) acc[e] += x * rr[e];
    }
    #pragma unroll
    for (int e = 0; e < NE; e++)
        for (int o = 16; o > 0; o >>= 1) acc[e] += __shfl_down_sync(0xffffffffu, acc[e], o);
    if (lane == 0) {
        float m = acc[0];
        #pragma unroll
        for (int e = 1; e < NE; e++) m = fmaxf(m, acc[e]);
        float p[NE], s = 0.f;
        #pragma unroll
        for (int e = 0; e < NE; e++) { p[e] = expf(acc[e]-m); s += p[e]; }
        float inv = 1.f/s;
        #pragma unroll
        for (int e = 0; e < NE; e++) { p[e] *= inv; g_probs[(size_t)t*NE + e] = p[e]; }
        int i0 = 0;
        #pragma unroll
        for (int e = 1; e < NE; e++) if (p[e] > p[i0]) i0 = e;
        int i1 = (i0 == 0) ? 1 : 0;
        #pragma unroll
        for (int e = 0; e < NE; e++) if (e != i0 && p[e] > p[i1]) i1 = e;
        float ws = p[i0] + p[i1];
        g_ti[2*t] = i0; g_ti[2*t+1] = i1;
        g_tw[2*t] = p[i0]/ws; g_tw[2*t+1] = p[i1]/ws;
    }
}
__global__ void k_aux() {
    int tid = threadIdx.x;
    __shared__ float sh[256];
    __shared__ float totp[NE], totc[NE];
    float ps[NE] = {}, cs[NE] = {};
    for (int t = tid; t < T_; t += 256) {
        cs[g_ti[2*t]] += 1.f;
        #pragma unroll
        for (int e = 0; e < NE; e++) ps[e] += g_probs[(size_t)t*NE + e];
    }
    for (int e = 0; e < NE; e++) {
        sh[tid] = ps[e]; __syncthreads();
        for (int o = 128; o > 0; o >>= 1) { if (tid < o) sh[tid] += sh[tid+o]; __syncthreads(); }
        if (tid == 0) totp[e] = sh[0];
        __syncthreads();
        sh[tid] = cs[e]; __syncthreads();
        for (int o = 128; o > 0; o >>= 1) { if (tid < o) sh[tid] += sh[tid+o]; __syncthreads(); }
        if (tid == 0) totc[e] = sh[0];
        __syncthreads();
    }
    if (tid == 0) {
        float a = 0.f;
        for (int e = 0; e < NE; e++) a += (totc[e]/(float)T_) * (totp[e]/(float)T_);
        g_aux[0] += (float)NE * a;
    }
}
__global__ void k_bucket() {
    int t = blockIdx.x*256 + threadIdx.x;
    if (t >= T_) return;
    for (int j = 0; j < 2; j++) {
        int e = g_ti[2*t + j];
        int pos = atomicAdd(&g_cnt[e], 1);
        g_rows[e*T_ + pos] = t;
        g_slot[2*t + j] = e*T_ + pos;
    }
}
__global__ void k_combine() {
    int t = blockIdx.x, tid = threadIdx.x;
    int s0 = g_slot[2*t], s1 = g_slot[2*t+1];
    float w0 = g_tw[2*t], w1 = g_tw[2*t+1];
    const float* y0 = g_yb + (size_t)s0*D_;
    const float* y1 = g_yb + (size_t)s1*D_;
    float* hr = g_h + (size_t)t*D_;
    for (int d = tid; d < D_; d += 256) hr[d] += w0*y0[d] + w1*y1[d];
}
__global__ void k_task(const float* __restrict__ tw, const float* __restrict__ tb, float* __restrict__ out) {
    int c = blockIdx.x, tid = threadIdx.x;
    __shared__ float sh[256];
    float s = 0.f;
    for (int d = tid; d < D_; d += 256) s += g_xn[d] * tw[(size_t)d*16 + c];
    sh[tid] = s; __syncthreads();
    for (int o = 128; o > 0; o >>= 1) { if (tid < o) sh[tid] += sh[tid+o]; __syncthreads(); }
    if (tid == 0) out[OUT_TASK + c] = sh[0] + tb[c];
}
__global__ void k_mean1() {
    int b = blockIdx.x, tid = threadIdx.x;
    const float* x = g_xn + (size_t)b*128*D_ + tid*4;
    float4 a = make_float4(0.f,0.f,0.f,0.f);
    for (int r = 0; r < 128; r++) {
        float4 v = *(const float4*)(x + (size_t)r*D_);
        a.x += v.x; a.y += v.y; a.z += v.z; a.w += v.w;
    }
    *(float4*)(g_mp + b*D_ + tid*4) = a;
}
__global__ void k_mean2() {
    int d = blockIdx.x*256 + threadIdx.x;
    float s = 0.f;
    for (int b = 0; b < 16; b++) s += g_mp[b*D_ + d];
    g_xm[d] = s / (float)T_;
}
__global__ void k_eval(const float* __restrict__ ew, const float* __restrict__ eb, float* __restrict__ out) {
    int c = blockIdx.x, tid = threadIdx.x;
    __shared__ float sh[256];
    float s = 0.f;
    for (int d = tid; d < D_; d += 256) s += g_xm[d] * ew[(size_t)d*8 + c];
    sh[tid] = s; __syncthreads();
    for (int o = 128; o > 0; o >>= 1) { if (tid < o) sh[tid] += sh[tid+o]; __syncthreads(); }
    if (tid == 0) out[OUT_EVAL + c] = sh[0] + eb[c];
}
__global__ void k_auxw(float* __restrict__ out) { out[OUT_AUX] = g_aux[0]; }

// ---------------- launch ----------------
extern "C" void kernel_launch(void* const* d_in, const int* in_sizes, int n_in,
                              void* d_out, int out_size) {
    const int*   ids     = (const int*)  d_in[0];
    const float* embed_W = (const float*)d_in[1];
    const float* n1      = (const float*)d_in[2];
    const float* n2      = (const float*)d_in[3];
    const float* wq      = (const float*)d_in[4];
    const float* wk      = (const float*)d_in[5];
    const float* wv      = (const float*)d_in[6];
    const float* wo      = (const float*)d_in[7];
    const float* rw      = (const float*)d_in[8];
    const float* w1      = (const float*)d_in[9];
    const float* w3      = (const float*)d_in[10];
    const float* w2      = (const float*)d_in[11];
    const float* normf   = (const float*)d_in[12];
    const float* lm      = (const float*)d_in[13];
    const float* tw      = (const float*)d_in[14];
    const float* tb      = (const float*)d_in[15];
    const float* ew      = (const float*)d_in[16];
    const float* eb      = (const float*)d_in[17];
    float* out = (float*)d_out;

    float *p_h, *p_xn, *p_qkv, *p_attn;
    bf16 *p_ah, *p_al, *p_qkvh, *p_qkvl;
    bf16 *p_cqh, *p_cql, *p_cwoh, *p_cwol, *p_c1h, *p_c1l, *p_c3h, *p_c3l, *p_c2h, *p_c2l, *p_clh, *p_cll;
    cudaGetSymbolAddress((void**)&p_h,    g_h);
    cudaGetSymbolAddress((void**)&p_xn,   g_xn);
    cudaGetSymbolAddress((void**)&p_qkv,  g_qkv);
    cudaGetSymbolAddress((void**)&p_attn, g_attn);
    cudaGetSymbolAddress((void**)&p_ah,   g_ah);
    cudaGetSymbolAddress((void**)&p_al,   g_al);
    cudaGetSymbolAddress((void**)&p_qkvh, g_qkvh);
    cudaGetSymbolAddress((void**)&p_qkvl, g_qkvl);
    cudaGetSymbolAddress((void**)&p_cqh,  c_qkvh);
    cudaGetSymbolAddress((void**)&p_cql,  c_qkvl);
    cudaGetSymbolAddress((void**)&p_cwoh, c_woh);
    cudaGetSymbolAddress((void**)&p_cwol, c_wol);
    cudaGetSymbolAddress((void**)&p_c1h,  c_w1h);
    cudaGetSymbolAddress((void**)&p_c1l,  c_w1l);
    cudaGetSymbolAddress((void**)&p_c3h,  c_w3h);
    cudaGetSymbolAddress((void**)&p_c3l,  c_w3l);
    cudaGetSymbolAddress((void**)&p_c2h,  c_w2h);
    cudaGetSymbolAddress((void**)&p_c2l,  c_w2l);
    cudaGetSymbolAddress((void**)&p_clh,  c_lmh);
    cudaGetSymbolAddress((void**)&p_cll,  c_lml);

    cudaFuncSetAttribute(k_mma256,  cudaFuncAttributeMaxDynamicSharedMemorySize, SMEM_W);
    cudaFuncSetAttribute(k_moe_mma, cudaFuncAttributeMaxDynamicSharedMemorySize, SMEM_W);
    cudaFuncSetAttribute(k_avm,     cudaFuncAttributeMaxDynamicSharedMemorySize, SMEM_MMA128);
    cudaFuncSetAttribute(k_qk,      cudaFuncAttributeMaxDynamicSharedMemorySize, SMEM_QK);

    // order engineered so launch #6 (ncu -s 5 -c 1) is the first k_mma256
    k_embed<<<T_, 256>>>(ids, embed_W);                                  // 1 (+aux zero)
    k_rms<<<T_, 256>>>(p_h, n1, p_xn);                                   // 2 (layer 0)
    k_split8<<<1024, 256>>>(p_xn, p_ah, p_al);                           // 3
    k_convqkv<<<dim3(1024, 6), 256>>>(wq, wk, wv);                       // 4
    k_convw5<<<dim3(16384, 5), 256>>>(wo, w1, w3, w2, lm);               // 5

    for (int l = 0; l < NL; l++) {
        if (l > 0) {
            k_rms<<<T_, 256>>>(p_h, n1 + (size_t)l*D_, p_xn);
            k_split8<<<1024, 256>>>(p_xn, p_ah, p_al);
        }
        // attention
        k_mma256<<<dim3(16, 6), 256, SMEM_W>>>(p_ah, p_al,               // 6 on l=0
            p_cqh + (size_t)l*D_*QKV_, p_cql + (size_t)l*D_*QKV_, p_qkv, D_, QKV_, QKV_, 0);
        k_rope<<<T_, 512>>>();
        k_split8<<<1536, 256>>>(p_qkv, p_qkvh, p_qkvl);
        k_qk<<<dim3(4, 4, 64), 256, SMEM_QK>>>();
        k_softmax<<<NCK*NH*CH, 256>>>();
        k_avm<<<dim3(4, 1, 64), 256, SMEM_MMA128>>>();
        k_split8<<<1024, 256>>>(p_attn, p_ah, p_al);
        k_mma256<<<dim3(16, 4), 256, SMEM_W>>>(p_ah, p_al,
            p_cwoh + (size_t)l*D_*D_, p_cwol + (size_t)l*D_*D_, p_h, D_, D_, D_, 1);

        // MoE
        k_rms<<<T_, 256>>>(p_h, n2 + (size_t)l*D_, p_xn);
        k_split8<<<1024, 256>>>(p_xn, p_ah, p_al);
        k_router<<<T_/8, 256>>>(rw + (size_t)l*D_*NE);
        k_aux<<<1, 256>>>();
        k_zero_cnt<<<1, 32>>>();
        k_bucket<<<T_/256, 256>>>();
        k_moe_mma<<<dim3(16, 8, NE), 256, SMEM_W>>>(p_c1h + (size_t)l*NE*D_*F_, p_c1l + (size_t)l*NE*D_*F_, 0);
        k_moe_mma<<<dim3(16, 8, NE), 256, SMEM_W>>>(p_c3h + (size_t)l*NE*D_*F_, p_c3l + (size_t)l*NE*D_*F_, 1);
        k_moe_mma<<<dim3(16, 4, NE), 256, SMEM_W>>>(p_c2h + (size_t)l*NE*F_*D_, p_c2l + (size_t)l*NE*F_*D_, 2);
        k_combine<<<T_, 256>>>();
    }

    // final norm + heads
    k_rms<<<T_, 256>>>(p_h, normf, p_xn);
    k_split8<<<1024, 256>>>(p_xn, p_ah, p_al);
    k_mma256<<<dim3(16, NV/256), 256, SMEM_W>>>(p_ah, p_al, p_clh, p_cll, out, D_, NV, NV, 0);
    k_task<<<16, 256>>>(tw, tb, out);
    k_mean1<<<16, 256>>>();
    k_mean2<<<4, 256>>>();
    k_eval<<<8, 256>>>(ew, eb, out);
    k_auxw<<<1, 1>>>(out);
}

// round 12
// speedup vs baseline: 2.9122x; 1.0507x over previous
#include <cuda_runtime.h>
#include <cuda_bf16.h>
#include <math.h>
#include <stdint.h>

#define T_   2048
#define D_   1024
#define NH   16
#define NKV  4
#define F_   2048
#define NE   8
#define NL   2
#define NV   32000
#define CH   512
#define NCK  4
#define QKV_ 1536

#define OUT_TASK   (T_*(size_t)NV)
#define OUT_EVAL   (OUT_TASK + 16)
#define OUT_AUX    (OUT_EVAL + 8)

typedef __nv_bfloat16 bf16;
typedef __nv_bfloat162 bf162;

// ---------------- scratch (device globals; no allocation) ----------------
__device__ float g_h   [(size_t)T_*D_];
__device__ float g_xn  [(size_t)T_*D_];
__device__ float g_qkv [(size_t)T_*QKV_];
__device__ float g_sc  [(size_t)NCK*NH*CH*CH];
__device__ float g_attn[(size_t)T_*D_];
__device__ float g_probs[(size_t)T_*NE];
__device__ int   g_ti  [T_*2];
__device__ float g_tw  [T_*2];
__device__ int   g_cnt [NE];
__device__ int   g_rows[NE*T_];
__device__ int   g_slot[T_*2];
__device__ float g_yb  [(size_t)NE*T_*D_];
__device__ float g_aux [1];
__device__ float g_xm  [D_];
__device__ float g_mp  [16*D_];
__device__ bf16  g_ah  [(size_t)T_*D_];
__device__ bf16  g_al  [(size_t)T_*D_];
__device__ bf16  g_qkvh[(size_t)T_*QKV_];
__device__ bf16  g_qkvl[(size_t)T_*QKV_];
__device__ float g_ub  [(size_t)NE*T_*F_];
__device__ bf16  g_hbh [(size_t)NE*T_*F_];   // also reused as P hi
__device__ bf16  g_hbl [(size_t)NE*T_*F_];   // also reused as P lo
// pre-converted weights (hi/lo bf16)
__device__ bf16  c_qkvh[(size_t)NL*D_*QKV_], c_qkvl[(size_t)NL*D_*QKV_];
__device__ bf16  c_woh [(size_t)NL*D_*D_],   c_wol [(size_t)NL*D_*D_];
__device__ bf16  c_w1h [(size_t)NL*NE*D_*F_], c_w1l[(size_t)NL*NE*D_*F_];
__device__ bf16  c_w3h [(size_t)NL*NE*D_*F_], c_w3l[(size_t)NL*NE*D_*F_];
__device__ bf16  c_w2h [(size_t)NL*NE*F_*D_], c_w2l[(size_t)NL*NE*F_*D_];
__device__ bf16  c_lmh [(size_t)D_*NV],      c_lml[(size_t)D_*NV];

// ---------------- asm helpers ----------------
__device__ __forceinline__ uint32_t smem_u32(const void* p) {
    uint32_t a;
    asm("{ .reg .u64 t; cvta.to.shared.u64 t, %1; cvt.u32.u64 %0, t; }" : "=r"(a) : "l"(p));
    return a;
}
__device__ __forceinline__ void cpa(uint32_t d, const void* s) {
    asm volatile("cp.async.cg.shared.global [%0], [%1], 16;" :: "r"(d), "l"(s));
}
__device__ __forceinline__ void cp_commit() { asm volatile("cp.async.commit_group;" ::: "memory"); }
__device__ __forceinline__ void cp_wait1()  { asm volatile("cp.async.wait_group 1;" ::: "memory"); }
__device__ __forceinline__ void cp_wait0()  { asm volatile("cp.async.wait_group 0;" ::: "memory"); }
__device__ __forceinline__ void ldsm4(uint32_t (&r)[4], uint32_t a) {
    asm volatile("ldmatrix.sync.aligned.m8n8.x4.shared.b16 {%0,%1,%2,%3}, [%4];"
        : "=r"(r[0]), "=r"(r[1]), "=r"(r[2]), "=r"(r[3]) : "r"(a));
}
__device__ __forceinline__ void ldsm4t(uint32_t (&r)[4], uint32_t a) {
    asm volatile("ldmatrix.sync.aligned.m8n8.x4.trans.shared.b16 {%0,%1,%2,%3}, [%4];"
        : "=r"(r[0]), "=r"(r[1]), "=r"(r[2]), "=r"(r[3]) : "r"(a));
}
__device__ __forceinline__ void ldsm2t(uint32_t (&r)[2], uint32_t a) {
    asm volatile("ldmatrix.sync.aligned.m8n8.x2.trans.shared.b16 {%0,%1}, [%2];"
        : "=r"(r[0]), "=r"(r[1]) : "r"(a));
}
__device__ __forceinline__ void ldsm2(uint32_t (&r)[2], uint32_t a) {
    asm volatile("ldmatrix.sync.aligned.m8n8.x2.shared.b16 {%0,%1}, [%2];"
        : "=r"(r[0]), "=r"(r[1]) : "r"(a));
}
__device__ __forceinline__ void mma16816(float (&d)[4], const uint32_t (&a)[4], const uint32_t (&b)[2]) {
    asm volatile("mma.sync.aligned.m16n8k16.row.col.f32.bf16.bf16.f32 "
        "{%0,%1,%2,%3}, {%4,%5,%6,%7}, {%8,%9}, {%0,%1,%2,%3};"
        : "+f"(d[0]), "+f"(d[1]), "+f"(d[2]), "+f"(d[3])
        : "r"(a[0]), "r"(a[1]), "r"(a[2]), "r"(a[3]), "r"(b[0]), "r"(b[1]));
}

// ============== 128x256 tile GEMM (main path) ==============
// per buffer: Ah 128x80B @0 | Al @10240 | Bh 32x528B @20480 | Bl @37376
#define W_OFF_AL 10240
#define W_OFF_BH 20480
#define W_OFF_BL 37376
#define W_BUFSZ  54272
#define SMEM_W   (3*W_BUFSZ)

// modes: 0 = C=acc, 1 = C+=acc, 2 = silu(U)*acc -> split bf16 to Hh/Hl
__device__ __forceinline__ void mma_block256(
    const bf16* __restrict__ Ah, const bf16* __restrict__ Al, int lda,
    const int* __restrict__ rows, int count, int m0,
    const bf16* __restrict__ Bh, const bf16* __restrict__ Bl, int ldb, int n0,
    int K, float* __restrict__ C, int ldc, int mode,
    const float* __restrict__ U, bf16* __restrict__ Hh, bf16* __restrict__ Hl,
    char* dsm, uint32_t sb)
{
    const int tid = threadIdx.x, lane = tid & 31, wid = tid >> 5;
    const int wm = (wid & 1) * 64, wn = (wid >> 1) * 64;
    const int ar = tid >> 1, akc = (tid & 1) * 16;
    const int gm = m0 + ar;
    const bool av = gm < count;
    const bf16 *pAh = nullptr, *pAl = nullptr;
    if (av) {
        size_t rr = (size_t)(rows ? rows[gm] : gm) * lda + akc;
        pAh = Ah + rr; pAl = Al + rr;
    }
    const uint32_t ao = (uint32_t)ar * 80 + (uint32_t)akc * 2;

    if (!av) {
        uint4 z = make_uint4(0,0,0,0);
        #pragma unroll
        for (int s = 0; s < 3; s++) {
            char* bb = dsm + s * W_BUFSZ;
            *(uint4*)(bb + ao) = z;              *(uint4*)(bb + ao + 16) = z;
            *(uint4*)(bb + W_OFF_AL + ao) = z;   *(uint4*)(bb + W_OFF_AL + ao + 16) = z;
        }
    }

    float acc[4][8][4];
    #pragma unroll
    for (int a = 0; a < 4; a++)
        #pragma unroll
        for (int b = 0; b < 8; b++)
            #pragma unroll
            for (int c = 0; c < 4; c++) acc[a][b][c] = 0.f;

    auto ISSUE = [&](int k0, uint32_t sbuf) {
        if (av) {
            cpa(sbuf + ao,                 pAh + k0);
            cpa(sbuf + ao + 16,            pAh + k0 + 8);
            cpa(sbuf + W_OFF_AL + ao,      pAl + k0);
            cpa(sbuf + W_OFF_AL + ao + 16, pAl + k0 + 8);
        }
        #pragma unroll
        for (int j = 0; j < 4; j++) {
            int u = tid + j * 256;
            int row = u >> 5, c16 = u & 31;
            uint32_t doff = (uint32_t)row * 528 + (uint32_t)c16 * 16;
            const bf16* sh = Bh + (size_t)(k0 + row) * ldb + n0 + c16 * 8;
            const bf16* sl = Bl + (size_t)(k0 + row) * ldb + n0 + c16 * 8;
            cpa(sbuf + W_OFF_BH + doff, sh);
            cpa(sbuf + W_OFF_BL + doff, sl);
        }
    };

    auto COMPUTE = [&](uint32_t boff) {
        uint32_t abase = sb + boff + (uint32_t)(wm + (lane & 15)) * 80 + ((lane >> 4) * 16);
        uint32_t klocal = (uint32_t)((lane & 7) + ((lane >> 3) & 1) * 8);
        uint32_t bcol = (uint32_t)(wn + ((lane >> 4) & 1) * 8);
        #pragma unroll
        for (int ks = 0; ks < 2; ks++) {
            uint32_t ah4[4][4], al4[4][4];
            #pragma unroll
            for (int mt = 0; mt < 4; mt++) {
                uint32_t aa = abase + mt * (16 * 80) + ks * 32;
                ldsm4(ah4[mt], aa);
                ldsm4(al4[mt], aa + W_OFF_AL);
            }
            uint32_t bh[4][4], bl[4][4];
            uint32_t bkb = sb + boff + W_OFF_BH + (klocal + ks * 16) * 528 + bcol * 2;
            #pragma unroll
            for (int ng = 0; ng < 4; ng++) {
                uint32_t ba = bkb + ng * 32;   // 16 cols * 2B
                ldsm4t(bh[ng], ba);
                ldsm4t(bl[ng], ba + (W_OFF_BL - W_OFF_BH));
            }
            #pragma unroll
            for (int mt = 0; mt < 4; mt++)
                #pragma unroll
                for (int nt = 0; nt < 8; nt++) {
                    const int ng = nt >> 1, hf = (nt & 1) * 2;
                    uint32_t bhf[2] = { bh[ng][hf], bh[ng][hf + 1] };
                    uint32_t blf[2] = { bl[ng][hf], bl[ng][hf + 1] };
                    mma16816(acc[mt][nt], ah4[mt], bhf);
                    mma16816(acc[mt][nt], ah4[mt], blf);
                    mma16816(acc[mt][nt], al4[mt], bhf);
                }
        }
    };

    const int NC = K >> 5;
    ISSUE(0, sb); cp_commit();
    if (NC > 1) { ISSUE(32, sb + W_BUFSZ); cp_commit(); }
    for (int c = 0; c < NC; c++) {
        if (c == NC - 1) cp_wait0(); else cp_wait1();
        __syncthreads();
        COMPUTE((uint32_t)(c % 3) * W_BUFSZ);
        if (c + 2 < NC) { ISSUE((c + 2) << 5, sb + (uint32_t)((c + 2) % 3) * W_BUFSZ); cp_commit(); }
    }

    #pragma unroll
    for (int mt = 0; mt < 4; mt++) {
        int r0 = m0 + wm + mt * 16 + (lane >> 2);
        #pragma unroll
        for (int nt = 0; nt < 8; nt++) {
            int cc = n0 + wn + nt * 8 + (lane & 3) * 2;
            float* d = acc[mt][nt];
            #pragma unroll
            for (int hrow = 0; hrow < 2; hrow++) {
                int r = r0 + hrow * 8;
                if (r >= count) continue;
                float d0 = d[hrow*2], d1 = d[hrow*2 + 1];
                size_t o = (size_t)r * ldc + cc;
                if (mode == 0) {
                    *(float2*)(C + o) = make_float2(d0, d1);
                } else if (mode == 1) {
                    float2 p = *(const float2*)(C + o);
                    *(float2*)(C + o) = make_float2(p.x + d0, p.y + d1);
                } else {
                    float2 u = *(const float2*)(U + o);
                    float h0 = (u.x / (1.f + expf(-u.x))) * d0;
                    float h1 = (u.y / (1.f + expf(-u.y))) * d1;
                    bf162 hh = __floats2bfloat162_rn(h0, h1);
                    bf162 ll = __floats2bfloat162_rn(h0 - __low2float(hh), h1 - __high2float(hh));
                    *(bf162*)(Hh + o) = hh;
                    *(bf162*)(Hl + o) = ll;
                }
            }
        }
    }
}

// dense GEMM: grid (M/128, N/256)
__global__ __launch_bounds__(256, 1) void k_mma256(
    const bf16* __restrict__ Ah, const bf16* __restrict__ Al,
    const bf16* __restrict__ Bh, const bf16* __restrict__ Bl,
    float* __restrict__ C, int K, int ldb, int ldc, int mode)
{
    extern __shared__ __align__(16) char dsm[];
    mma_block256(Ah, Al, K, nullptr, 1 << 30, blockIdx.x * 128,
                 Bh, Bl, ldb, blockIdx.y * 256,
                 K, C, ldc, mode, nullptr, nullptr, nullptr, dsm, smem_u32(dsm));
}

// MoE: which 0 = X W1 -> g_ub; 1 = X W3 fused silu -> hidden split; 2 = H W2 -> g_yb
__global__ __launch_bounds__(256, 1) void k_moe_mma(
    const bf16* __restrict__ Wh, const bf16* __restrict__ Wl, int which)
{
    int e = blockIdx.z;
    int count = g_cnt[e];
    int m0 = blockIdx.x * 128;
    if (m0 >= count) return;
    int n0 = blockIdx.y * 256;
    extern __shared__ __align__(16) char dsm[];
    uint32_t sb = smem_u32(dsm);
    if (which == 0) {
        mma_block256(g_ah, g_al, D_, g_rows + e * T_, count, m0,
                     Wh + (size_t)e * D_ * F_, Wl + (size_t)e * D_ * F_, F_, n0,
                     D_, g_ub + (size_t)e * T_ * F_, F_, 0, nullptr, nullptr, nullptr, dsm, sb);
    } else if (which == 1) {
        mma_block256(g_ah, g_al, D_, g_rows + e * T_, count, m0,
                     Wh + (size_t)e * D_ * F_, Wl + (size_t)e * D_ * F_, F_, n0,
                     D_, nullptr, F_, 2, g_ub + (size_t)e * T_ * F_,
                     g_hbh + (size_t)e * T_ * F_, g_hbl + (size_t)e * T_ * F_, dsm, sb);
    } else {
        mma_block256(g_hbh + (size_t)e * T_ * F_, g_hbl + (size_t)e * T_ * F_, F_, nullptr, count, m0,
                     Wh + (size_t)e * F_ * D_, Wl + (size_t)e * F_ * D_, D_, n0,
                     F_, g_yb + (size_t)e * T_ * D_, D_, 0, nullptr, nullptr, nullptr, dsm, sb);
    }
}

// ============== 128x128 tile path (k_avm only, nlim=64) ==============
#define OFF_AL 10240
#define OFF_BH 20480
#define OFF_BL 29184
#define BUFSZ  37888
#define SMEM_MMA128 (3*BUFSZ)

__device__ __forceinline__ void mma_block128(
    const bf16* __restrict__ Ah, const bf16* __restrict__ Al, int lda,
    int count, int m0,
    const bf16* __restrict__ Bh, const bf16* __restrict__ Bl, int ldb, int n0, int nlim,
    int K, float* __restrict__ C, int ldc,
    char* dsm, uint32_t sb)
{
    const int tid = threadIdx.x, lane = tid & 31, wid = tid >> 5;
    const int wm = (wid & 1) * 64, wn = (wid >> 1) * 32;
    const int ar = tid >> 1, akc = (tid & 1) * 16;
    const int bkr = tid >> 3, bn16 = (tid & 7) * 16;
    const int gm = m0 + ar;
    const bool av = gm < count;
    const bf16 *pAh = nullptr, *pAl = nullptr;
    if (av) {
        size_t rr = (size_t)gm * lda + akc;
        pAh = Ah + rr; pAl = Al + rr;
    }
    const int bcol = (nlim < 128) ? (bn16 & (nlim - 1)) : bn16;
    const bf16* pBh = Bh + (size_t)bkr * ldb + n0 + bcol;
    const bf16* pBl = Bl + (size_t)bkr * ldb + n0 + bcol;
    const uint32_t ao = (uint32_t)ar * 80 + (uint32_t)akc * 2;
    const uint32_t bo = (uint32_t)OFF_BH + (uint32_t)bkr * 272 + (uint32_t)bn16 * 2;

    if (!av) {
        uint4 z = make_uint4(0,0,0,0);
        #pragma unroll
        for (int s = 0; s < 3; s++) {
            char* bb = dsm + s * BUFSZ;
            *(uint4*)(bb + ao) = z;            *(uint4*)(bb + ao + 16) = z;
            *(uint4*)(bb + OFF_AL + ao) = z;   *(uint4*)(bb + OFF_AL + ao + 16) = z;
        }
    }

    float acc[4][4][4];
    #pragma unroll
    for (int a = 0; a < 4; a++)
        #pragma unroll
        for (int b = 0; b < 4; b++)
            #pragma unroll
            for (int c = 0; c < 4; c++) acc[a][b][c] = 0.f;

    auto ISSUE = [&](int k0, uint32_t sbuf) {
        if (av) {
            cpa(sbuf + ao,               pAh + k0);
            cpa(sbuf + ao + 16,          pAh + k0 + 8);
            cpa(sbuf + OFF_AL + ao,      pAl + k0);
            cpa(sbuf + OFF_AL + ao + 16, pAl + k0 + 8);
        }
        const bf16* b = pBh + (size_t)k0 * ldb;
        cpa(sbuf + bo,      b);
        cpa(sbuf + bo + 16, b + 8);
        b = pBl + (size_t)k0 * ldb;
        cpa(sbuf + (OFF_BL - OFF_BH) + bo,      b);
        cpa(sbuf + (OFF_BL - OFF_BH) + bo + 16, b + 8);
    };

    auto COMPUTE = [&](uint32_t boff) {
        uint32_t abase = sb + boff + (uint32_t)(wm + (lane & 15)) * 80 + ((lane >> 4) * 8) * 2;
        uint32_t bbase = sb + boff + OFF_BH
                       + (uint32_t)((lane & 7) + ((lane >> 3) & 1) * 8) * 272
                       + (uint32_t)wn * 2;
        #pragma unroll
        for (int ks = 0; ks < 2; ks++) {
            uint32_t ah4[4][4], al4[4][4], bh2[4][2], bl2[4][2];
            #pragma unroll
            for (int mt = 0; mt < 4; mt++) {
                uint32_t aa = abase + mt * (16 * 80) + ks * 32;
                ldsm4(ah4[mt], aa);
                ldsm4(al4[mt], aa + OFF_AL);
            }
            #pragma unroll
            for (int nt = 0; nt < 4; nt++) {
                uint32_t ba = bbase + ks * (16 * 272) + nt * 16;
                ldsm2t(bh2[nt], ba);
                ldsm2t(bl2[nt], ba + (OFF_BL - OFF_BH));
            }
            #pragma unroll
            for (int mt = 0; mt < 4; mt++)
                #pragma unroll
                for (int nt = 0; nt < 4; nt++) {
                    mma16816(acc[mt][nt], ah4[mt], bh2[nt]);
                    mma16816(acc[mt][nt], ah4[mt], bl2[nt]);
                    mma16816(acc[mt][nt], al4[mt], bh2[nt]);
                }
        }
    };

    const int NC = K >> 5;
    ISSUE(0, sb); cp_commit();
    if (NC > 1) { ISSUE(32, sb + BUFSZ); cp_commit(); }
    for (int c = 0; c < NC; c++) {
        if (c == NC - 1) cp_wait0(); else cp_wait1();
        __syncthreads();
        COMPUTE((uint32_t)(c % 3) * BUFSZ);
        if (c + 2 < NC) { ISSUE((c + 2) << 5, sb + (uint32_t)((c + 2) % 3) * BUFSZ); cp_commit(); }
    }

    #pragma unroll
    for (int mt = 0; mt < 4; mt++) {
        int r0 = m0 + wm + mt * 16 + (lane >> 2);
        #pragma unroll
        for (int nt = 0; nt < 4; nt++) {
            int ln = wn + nt * 8 + (lane & 3) * 2;
            if (ln >= nlim) continue;
            int cc = n0 + ln;
            float* d = acc[mt][nt];
            #pragma unroll
            for (int hrow = 0; hrow < 2; hrow++) {
                int r = r0 + hrow * 8;
                if (r >= count) continue;
                *(float2*)(C + (size_t)r * ldc + cc) = make_float2(d[hrow*2], d[hrow*2 + 1]);
            }
        }
    }
}

// O = P V: grid (4, 1, 64); P split lives in g_hbh/g_hbl; K trimmed by causality
__global__ __launch_bounds__(256, 1) void k_avm()
{
    int b = blockIdx.z, chunk = b >> 4, head = b & 15, kvh = head >> 2;
    int m0 = blockIdx.x * 128;
    extern __shared__ __align__(16) char dsm[];
    mma_block128(g_hbh + (size_t)b * CH * CH, g_hbl + (size_t)b * CH * CH, CH, CH, m0,
                 g_qkvh + (size_t)chunk * CH * QKV_ + 1280 + kvh * 64,
                 g_qkvl + (size_t)chunk * CH * QKV_ + 1280 + kvh * 64, QKV_, 0, 64,
                 m0 + 128, g_attn + (size_t)chunk * CH * D_ + head * 64, D_, dsm, smem_u32(dsm));
}

// ---------------- scores S = Q K^T: grid (4, 4, 64); skips n0>m0 tiles ----------------
#define QK_AL 10240
#define QK_KH 20480
#define QK_KL 30720
#define QK_BUF 40960
#define SMEM_QK (2*QK_BUF)

__global__ __launch_bounds__(256, 1) void k_qk()
{
    if (blockIdx.y > blockIdx.x) return;
    extern __shared__ __align__(16) char dsm[];
    uint32_t sb = smem_u32(dsm);
    int b = blockIdx.z, chunk = b >> 4, head = b & 15, kvh = head >> 2;
    int m0 = blockIdx.x * 128, n0 = blockIdx.y * 128;
    int tid = threadIdx.x, lane = tid & 31, wid = tid >> 5;
    int wm = (wid & 1) * 64, wn = (wid >> 1) * 32;
    int ar = tid >> 1, akc = (tid & 1) * 16;
    const bf16* pQh = g_qkvh + (size_t)(chunk*CH + m0 + ar) * QKV_ + head * 64 + akc;
    const bf16* pQl = g_qkvl + (size_t)(chunk*CH + m0 + ar) * QKV_ + head * 64 + akc;
    const bf16* pKh = g_qkvh + (size_t)(chunk*CH + n0 + ar) * QKV_ + 1024 + kvh * 64 + akc;
    const bf16* pKl = g_qkvl + (size_t)(chunk*CH + n0 + ar) * QKV_ + 1024 + kvh * 64 + akc;
    const uint32_t ao = (uint32_t)ar * 80 + (uint32_t)akc * 2;

    float acc[4][4][4];
    #pragma unroll
    for (int a = 0; a < 4; a++)
        #pragma unroll
        for (int bb = 0; bb < 4; bb++)
            #pragma unroll
            for (int c = 0; c < 4; c++) acc[a][bb][c] = 0.f;

    auto ISSUE = [&](int k0, uint32_t sbuf) {
        cpa(sbuf + ao,               pQh + k0); cpa(sbuf + ao + 16,           pQh + k0 + 8);
        cpa(sbuf + QK_AL + ao,       pQl + k0); cpa(sbuf + QK_AL + ao + 16,   pQl + k0 + 8);
        cpa(sbuf + QK_KH + ao,       pKh + k0); cpa(sbuf + QK_KH + ao + 16,   pKh + k0 + 8);
        cpa(sbuf + QK_KL + ao,       pKl + k0); cpa(sbuf + QK_KL + ao + 16,   pKl + k0 + 8);
    };
    auto COMPUTE = [&](uint32_t boff) {
        uint32_t abase = sb + boff + (uint32_t)(wm + (lane & 15)) * 80 + ((lane >> 4) * 8) * 2;
        #pragma unroll
        for (int ks = 0; ks < 2; ks++) {
            uint32_t ah4[4][4], al4[4][4], bh2[4][2], bl2[4][2];
            #pragma unroll
            for (int mt = 0; mt < 4; mt++) {
                uint32_t aa = abase + mt * (16 * 80) + ks * 32;
                ldsm4(ah4[mt], aa);
                ldsm4(al4[mt], aa + QK_AL);
            }
            #pragma unroll
            for (int nt = 0; nt < 4; nt++) {
                uint32_t ba = sb + boff + QK_KH
                            + (uint32_t)(wn + nt * 8 + (lane & 7)) * 80
                            + ks * 32 + ((lane >> 3) & 1) * 16;
                ldsm2(bh2[nt], ba);
                ldsm2(bl2[nt], ba + (QK_KL - QK_KH));
            }
            #pragma unroll
            for (int mt = 0; mt < 4; mt++)
                #pragma unroll
                for (int nt = 0; nt < 4; nt++) {
                    mma16816(acc[mt][nt], ah4[mt], bh2[nt]);
                    mma16816(acc[mt][nt], ah4[mt], bl2[nt]);
                    mma16816(acc[mt][nt], al4[mt], bh2[nt]);
                }
        }
    };

    ISSUE(0, sb); cp_commit();
    ISSUE(32, sb + QK_BUF); cp_commit();
    cp_wait1(); __syncthreads(); COMPUTE(0);
    cp_wait0(); __syncthreads(); COMPUTE(QK_BUF);

    float* S = g_sc + (size_t)b * CH * CH;
    #pragma unroll
    for (int mt = 0; mt < 4; mt++) {
        int r0 = wm + mt * 16 + (lane >> 2);
        #pragma unroll
        for (int nt = 0; nt < 4; nt++) {
            int c0 = wn + nt * 8 + (lane & 3) * 2;
            float* d = acc[mt][nt];
            #pragma unroll
            for (int hrow = 0; hrow < 2; hrow++) {
                int qg = m0 + r0 + hrow * 8;
                int kg = n0 + c0;
                float v0 = d[hrow*2] * 0.125f, v1 = d[hrow*2 + 1] * 0.125f;
                if (kg > qg)     v0 = -1e30f;
                if (kg + 1 > qg) v1 = -1e30f;
                *(float2*)(S + (size_t)qg * CH + kg) = make_float2(v0, v1);
            }
        }
    }
}

// ---- split helpers ----
__device__ __forceinline__ void split8_body(const float* __restrict__ x,
    bf16* __restrict__ hh, bf16* __restrict__ ll, size_t i) {
    const float4* xv = (const float4*)x;
    float4 a = xv[2*i], b = xv[2*i+1];
    bf162 h0 = __floats2bfloat162_rn(a.x, a.y);
    bf162 h1 = __floats2bfloat162_rn(a.z, a.w);
    bf162 h2 = __floats2bfloat162_rn(b.x, b.y);
    bf162 h3 = __floats2bfloat162_rn(b.z, b.w);
    bf162 l0 = __floats2bfloat162_rn(a.x - __low2float(h0), a.y - __high2float(h0));
    bf162 l1 = __floats2bfloat162_rn(a.z - __low2float(h1), a.w - __high2float(h1));
    bf162 l2 = __floats2bfloat162_rn(b.x - __low2float(h2), b.y - __high2float(h2));
    bf162 l3 = __floats2bfloat162_rn(b.z - __low2float(h3), b.w - __high2float(h3));
    ((uint4*)hh)[i] = make_uint4(*(uint32_t*)&h0, *(uint32_t*)&h1, *(uint32_t*)&h2, *(uint32_t*)&h3);
    ((uint4*)ll)[i] = make_uint4(*(uint32_t*)&l0, *(uint32_t*)&l1, *(uint32_t*)&l2, *(uint32_t*)&l3);
}
__global__ void k_split8(const float* __restrict__ x, bf16* __restrict__ hh, bf16* __restrict__ ll) {
    split8_body(x, hh, ll, (size_t)blockIdx.x * 256 + threadIdx.x);
}

// qkv weight segments: grid (1024, 6)
__global__ void k_convqkv(const float* __restrict__ wq, const float* __restrict__ wk,
                          const float* __restrict__ wv) {
    int seg = blockIdx.y, l = seg / 3, which = seg - l * 3;
    const float* src; int N; size_t doff;
    if (which == 0)      { src = wq + (size_t)l*D_*1024; N = 1024; doff = (size_t)l*D_*QKV_; }
    else if (which == 1) { src = wk + (size_t)l*D_*256;  N = 256;  doff = (size_t)l*D_*QKV_ + 1024; }
    else                 { src = wv + (size_t)l*D_*256;  N = 256;  doff = (size_t)l*D_*QKV_ + 1280; }
    size_t i = (size_t)blockIdx.x * 256 + threadIdx.x;
    size_t e = i * 4;
    if (e >= (size_t)D_ * N) return;
    int r = (int)(e / N), c = (int)(e % N);
    float4 v = *(const float4*)(src + e);
    size_t o = doff + (size_t)r * QKV_ + c;
    bf162 h0 = __floats2bfloat162_rn(v.x, v.y);
    bf162 l0 = __floats2bfloat162_rn(v.x - __low2float(h0), v.y - __high2float(h0));
    bf162 h1 = __floats2bfloat162_rn(v.z, v.w);
    bf162 l1 = __floats2bfloat162_rn(v.z - __low2float(h1), v.w - __high2float(h1));
    *(bf162*)(c_qkvh+o) = h0; *(bf162*)(c_qkvh+o+2) = h1;
    *(bf162*)(c_qkvl+o) = l0; *(bf162*)(c_qkvl+o+2) = l1;
}

// wo/w1/w3/w2/lm: grid-stride, streaming loads/stores, 16 floats/thread
__global__ void k_convw5(const float* __restrict__ wo, const float* __restrict__ w1,
                         const float* __restrict__ w3, const float* __restrict__ w2,
                         const float* __restrict__ lm) {
    int y = blockIdx.y;
    const float* src; bf16 *dh, *dl; size_t n;
    if (y == 0)      { src = wo; dh = c_woh; dl = c_wol; n = (size_t)NL*D_*D_; }
    else if (y == 1) { src = w1; dh = c_w1h; dl = c_w1l; n = (size_t)NL*NE*D_*F_; }
    else if (y == 2) { src = w3; dh = c_w3h; dl = c_w3l; n = (size_t)NL*NE*D_*F_; }
    else if (y == 3) { src = w2; dh = c_w2h; dl = c_w2l; n = (size_t)NL*NE*F_*D_; }
    else             { src = lm; dh = c_lmh; dl = c_lml; n = (size_t)D_*NV; }
    size_t nchunks = n >> 4;   // 16 floats per chunk
    size_t stride = (size_t)gridDim.x * 256;
    const float4* xv = (const float4*)src;
    for (size_t i = (size_t)blockIdx.x * 256 + threadIdx.x; i < nchunks; i += stride) {
        float4 a = __ldcs(xv + 4*i);
        float4 b = __ldcs(xv + 4*i + 1);
        float4 c = __ldcs(xv + 4*i + 2);
        float4 d = __ldcs(xv + 4*i + 3);
        bf162 h0 = __floats2bfloat162_rn(a.x, a.y), h1 = __floats2bfloat162_rn(a.z, a.w);
        bf162 h2 = __floats2bfloat162_rn(b.x, b.y), h3 = __floats2bfloat162_rn(b.z, b.w);
        bf162 h4 = __floats2bfloat162_rn(c.x, c.y), h5 = __floats2bfloat162_rn(c.z, c.w);
        bf162 h6 = __floats2bfloat162_rn(d.x, d.y), h7 = __floats2bfloat162_rn(d.z, d.w);
        bf162 l0 = __floats2bfloat162_rn(a.x - __low2float(h0), a.y - __high2float(h0));
        bf162 l1 = __floats2bfloat162_rn(a.z - __low2float(h1), a.w - __high2float(h1));
        bf162 l2 = __floats2bfloat162_rn(b.x - __low2float(h2), b.y - __high2float(h2));
        bf162 l3 = __floats2bfloat162_rn(b.z - __low2float(h3), b.w - __high2float(h3));
        bf162 l4 = __floats2bfloat162_rn(c.x - __low2float(h4), c.y - __high2float(h4));
        bf162 l5 = __floats2bfloat162_rn(c.z - __low2float(h5), c.w - __high2float(h5));
        bf162 l6 = __floats2bfloat162_rn(d.x - __low2float(h6), d.y - __high2float(h6));
        bf162 l7 = __floats2bfloat162_rn(d.z - __low2float(h7), d.w - __high2float(h7));
        __stcs((uint4*)dh + 2*i,     make_uint4(*(uint32_t*)&h0, *(uint32_t*)&h1, *(uint32_t*)&h2, *(uint32_t*)&h3));
        __stcs((uint4*)dh + 2*i + 1, make_uint4(*(uint32_t*)&h4, *(uint32_t*)&h5, *(uint32_t*)&h6, *(uint32_t*)&h7));
        __stcs((uint4*)dl + 2*i,     make_uint4(*(uint32_t*)&l0, *(uint32_t*)&l1, *(uint32_t*)&l2, *(uint32_t*)&l3));
        __stcs((uint4*)dl + 2*i + 1, make_uint4(*(uint32_t*)&l4, *(uint32_t*)&l5, *(uint32_t*)&l6, *(uint32_t*)&l7));
    }
}

// ---------------- fused rms + split ----------------
__global__ void k_rmssplit(const float* __restrict__ x, const float* __restrict__ w,
                           float* __restrict__ out, bf16* __restrict__ hh, bf16* __restrict__ ll) {
    int t = blockIdx.x, tid = threadIdx.x;
    __shared__ float sh[256];
    float4 v = ((const float4*)(x + (size_t)t*D_))[tid];
    float s = v.x*v.x + v.y*v.y + v.z*v.z + v.w*v.w;
    sh[tid] = s; __syncthreads();
    for (int o = 128; o > 0; o >>= 1) { if (tid < o) sh[tid] += sh[tid+o]; __syncthreads(); }
    float scale = rsqrtf(sh[0] / (float)D_ + 1e-6f);
    float4 wv = ((const float4*)w)[tid];
    float4 o;
    o.x = wv.x * v.x * scale; o.y = wv.y * v.y * scale;
    o.z = wv.z * v.z * scale; o.w = wv.w * v.w * scale;
    ((float4*)(out + (size_t)t*D_))[tid] = o;
    bf162 h0 = __floats2bfloat162_rn(o.x, o.y);
    bf162 h1 = __floats2bfloat162_rn(o.z, o.w);
    bf162 l0 = __floats2bfloat162_rn(o.x - __low2float(h0), o.y - __high2float(h0));
    bf162 l1 = __floats2bfloat162_rn(o.z - __low2float(h1), o.w - __high2float(h1));
    ((uint2*)(hh + (size_t)t*D_))[tid] = make_uint2(*(uint32_t*)&h0, *(uint32_t*)&h1);
    ((uint2*)(ll + (size_t)t*D_))[tid] = make_uint2(*(uint32_t*)&l0, *(uint32_t*)&l1);
}

// ---------------- fused rope + qkv split: grid T_, 192 threads ----------------
__global__ void k_ropesplit() {
    int t = blockIdx.x, tid = threadIdx.x;
    int c0 = tid * 8;
    float p = (float)(t & (CH-1));
    const float* base = g_qkv + (size_t)t * QKV_;
    float4 a = *(const float4*)(base + c0);
    float4 b = *(const float4*)(base + c0 + 4);
    float vv[8] = {a.x, a.y, a.z, a.w, b.x, b.y, b.z, b.w};
    if (c0 < 1280) {   // rope region (q: <1024, k: 1024..1279); 8-col chunk never straddles
        #pragma unroll
        for (int j = 0; j < 4; j++) {
            int c = c0 + 2*j;
            int i = (c & 63) >> 1;
            float ang = p * powf(1000000.0f, -(float)i/32.0f);
            float cs = cosf(ang), sn = sinf(ang);
            float x1 = vv[2*j], x2 = vv[2*j+1];
            vv[2*j]   = x1*cs - x2*sn;
            vv[2*j+1] = x1*sn + x2*cs;
        }
    }
    bf162 h[4], l[4];
    #pragma unroll
    for (int j = 0; j < 4; j++) {
        h[j] = __floats2bfloat162_rn(vv[2*j], vv[2*j+1]);
        l[j] = __floats2bfloat162_rn(vv[2*j] - __low2float(h[j]), vv[2*j+1] - __high2float(h[j]));
    }
    size_t o = ((size_t)t * QKV_ + c0) >> 3;
    ((uint4*)g_qkvh)[o] = make_uint4(*(uint32_t*)&h[0], *(uint32_t*)&h[1], *(uint32_t*)&h[2], *(uint32_t*)&h[3]);
    ((uint4*)g_qkvl)[o] = make_uint4(*(uint32_t*)&l[0], *(uint32_t*)&l[1], *(uint32_t*)&l[2], *(uint32_t*)&l[3]);
}

// ---------------- misc kernels ----------------
__global__ void k_embed(const int* __restrict__ ids, const float* __restrict__ ew) {
    int t = blockIdx.x;
    if (t == 0 && threadIdx.x == 0) g_aux[0] = 0.f;
    size_t r = (size_t)ids[t] * D_;
    for (int d = threadIdx.x; d < D_; d += blockDim.x) g_h[(size_t)t*D_ + d] = ew[r + d];
}
// warp-per-row softmax: reads fp32 S, writes P as bf16 hi/lo; grid 4096 x 256
__global__ void k_softmax() {
    int tid = threadIdx.x, lane = tid & 31, w = tid >> 5;
    int row = blockIdx.x * 8 + w;
    int q = row & (CH-1);
    const float* r = g_sc + (size_t)row * CH;
    float x[16];
    float mx = -1e30f;
    #pragma unroll
    for (int j = 0; j < 4; j++) {
        int c = j * 128 + lane * 4;
        float4 v = *(const float4*)(r + c);
        x[4*j]   = (c   <= q) ? v.x : -1e30f;
        x[4*j+1] = (c+1 <= q) ? v.y : -1e30f;
        x[4*j+2] = (c+2 <= q) ? v.z : -1e30f;
        x[4*j+3] = (c+3 <= q) ? v.w : -1e30f;
        mx = fmaxf(mx, fmaxf(fmaxf(x[4*j], x[4*j+1]), fmaxf(x[4*j+2], x[4*j+3])));
    }
    #pragma unroll
    for (int o = 16; o > 0; o >>= 1) mx = fmaxf(mx, __shfl_xor_sync(0xffffffffu, mx, o));
    float sum = 0.f;
    #pragma unroll
    for (int j = 0; j < 16; j++) { x[j] = (x[j] > -1e29f) ? expf(x[j] - mx) : 0.f; sum += x[j]; }
    #pragma unroll
    for (int o = 16; o > 0; o >>= 1) sum += __shfl_xor_sync(0xffffffffu, sum, o);
    float inv = 1.f / sum;
    #pragma unroll
    for (int j = 0; j < 4; j++) {
        int c = j * 128 + lane * 4;
        float p0 = x[4*j]*inv, p1 = x[4*j+1]*inv, p2 = x[4*j+2]*inv, p3 = x[4*j+3]*inv;
        bf162 h0 = __floats2bfloat162_rn(p0, p1);
        bf162 h1 = __floats2bfloat162_rn(p2, p3);
        bf162 l0 = __floats2bfloat162_rn(p0 - __low2float(h0), p1 - __high2float(h0));
        bf162 l1 = __floats2bfloat162_rn(p2 - __low2float(h1), p3 - __high2float(h1));
        size_t o = ((size_t)row * CH + c) >> 2;
        ((uint2*)g_hbh)[o] = make_uint2(*(uint32_t*)&h0, *(uint32_t*)&h1);
        ((uint2*)g_hbl)[o] = make_uint2(*(uint32_t*)&l0, *(uint32_t*)&l1);
    }
}
__global__ void k_router(const float* __restrict__ rw) {
    int tid = threadIdx.x, lane = tid & 31, w = tid >> 5;
    int t = blockIdx.x*8 + w;
    const float* xr = g_xn + (size_t)t*D_;
    float acc[NE] = {};
    for (int dd = 0; dd < 32; dd++) {
        int d = dd*32 + lane;
        float x = xr[d];
        const float* rr = rw + (size_t)d*NE;
        #pragma unroll
        for (int e = 0; e < NE; e++) acc[e] += x * rr[e];
    }
    #pragma unroll
    for (int e = 0; e < NE; e++)
        for (int o = 16; o > 0; o >>= 1) acc[e] += __shfl_down_sync(0xffffffffu, acc[e], o);
    if (lane == 0) {
        float m = acc[0];
        #pragma unroll
        for (int e = 1; e < NE; e++) m = fmaxf(m, acc[e]);
        float p[NE], s = 0.f;
        #pragma unroll
        for (int e = 0; e < NE; e++) { p[e] = expf(acc[e]-m); s += p[e]; }
        float inv = 1.f/s;
        #pragma unroll
        for (int e = 0; e < NE; e++) { p[e] *= inv; g_probs[(size_t)t*NE + e] = p[e]; }
        int i0 = 0;
        #pragma unroll
        for (int e = 1; e < NE; e++) if (p[e] > p[i0]) i0 = e;
        int i1 = (i0 == 0) ? 1 : 0;
        #pragma unroll
        for (int e = 0; e < NE; e++) if (e != i0 && p[e] > p[i1]) i1 = e;
        float ws = p[i0] + p[i1];
        g_ti[2*t] = i0; g_ti[2*t+1] = i1;
        g_tw[2*t] = p[i0]/ws; g_tw[2*t+1] = p[i1]/ws;
    }
}
// single-block aux accumulation; also zeroes g_cnt for k_bucket
__global__ void k_aux() {
    int tid = threadIdx.x;
    if (tid < NE) g_cnt[tid] = 0;
    __shared__ float sh[256];
    __shared__ float totp[NE], totc[NE];
    float ps[NE] = {}, cs[NE] = {};
    for (int t = tid; t < T_; t += 256) {
        cs[g_ti[2*t]] += 1.f;
        #pragma unroll
        for (int e = 0; e < NE; e++) ps[e] += g_probs[(size_t)t*NE + e];
    }
    for (int e = 0; e < NE; e++) {
        sh[tid] = ps[e]; __syncthreads();
        for (int o = 128; o > 0; o >>= 1) { if (tid < o) sh[tid] += sh[tid+o]; __syncthreads(); }
        if (tid == 0) totp[e] = sh[0];
        __syncthreads();
        sh[tid] = cs[e]; __syncthreads();
        for (int o = 128; o > 0; o >>= 1) { if (tid < o) sh[tid] += sh[tid+o]; __syncthreads(); }
        if (tid == 0) totc[e] = sh[0];
        __syncthreads();
    }
    if (tid == 0) {
        float a = 0.f;
        for (int e = 0; e < NE; e++) a += (totc[e]/(float)T_) * (totp[e]/(float)T_);
        g_aux[0] += (float)NE * a;
    }
}
__global__ void k_bucket() {
    int t = blockIdx.x*256 + threadIdx.x;
    if (t >= T_) return;
    for (int j = 0; j < 2; j++) {
        int e = g_ti[2*t + j];
        int pos = atomicAdd(&g_cnt[e], 1);
        g_rows[e*T_ + pos] = t;
        g_slot[2*t + j] = e*T_ + pos;
    }
}
__global__ void k_combine() {
    int t = blockIdx.x, tid = threadIdx.x;
    int s0 = g_slot[2*t], s1 = g_slot[2*t+1];
    float w0 = g_tw[2*t], w1 = g_tw[2*t+1];
    const float* y0 = g_yb + (size_t)s0*D_;
    const float* y1 = g_yb + (size_t)s1*D_;
    float* hr = g_h + (size_t)t*D_;
    for (int d = tid; d < D_; d += 256) hr[d] += w0*y0[d] + w1*y1[d];
}
__global__ void k_task(const float* __restrict__ tw, const float* __restrict__ tb, float* __restrict__ out) {
    int c = blockIdx.x, tid = threadIdx.x;
    __shared__ float sh[256];
    float s = 0.f;
    for (int d = tid; d < D_; d += 256) s += g_xn[d] * tw[(size_t)d*16 + c];
    sh[tid] = s; __syncthreads();
    for (int o = 128; o > 0; o >>= 1) { if (tid < o) sh[tid] += sh[tid+o]; __syncthreads(); }
    if (tid == 0) out[OUT_TASK + c] = sh[0] + tb[c];
}
__global__ void k_mean1() {
    int b = blockIdx.x, tid = threadIdx.x;
    const float* x = g_xn + (size_t)b*128*D_ + tid*4;
    float4 a = make_float4(0.f,0.f,0.f,0.f);
    for (int r = 0; r < 128; r++) {
        float4 v = *(const float4*)(x + (size_t)r*D_);
        a.x += v.x; a.y += v.y; a.z += v.z; a.w += v.w;
    }
    *(float4*)(g_mp + b*D_ + tid*4) = a;
}
__global__ void k_mean2() {
    int d = blockIdx.x*256 + threadIdx.x;
    float s = 0.f;
    for (int b = 0; b < 16; b++) s += g_mp[b*D_ + d];
    g_xm[d] = s / (float)T_;
}
__global__ void k_eval(const float* __restrict__ ew, const float* __restrict__ eb, float* __restrict__ out) {
    int c = blockIdx.x, tid = threadIdx.x;
    __shared__ float sh[256];
    float s = 0.f;
    for (int d = tid; d < D_; d += 256) s += g_xm[d] * ew[(size_t)d*8 + c];
    sh[tid] = s; __syncthreads();
    for (int o = 128; o > 0; o >>= 1) { if (tid < o) sh[tid] += sh[tid+o]; __syncthreads(); }
    if (tid == 0) out[OUT_EVAL + c] = sh[0] + eb[c];
}
__global__ void k_auxw(float* __restrict__ out) { out[OUT_AUX] = g_aux[0]; }

// ---------------- launch ----------------
extern "C" void kernel_launch(void* const* d_in, const int* in_sizes, int n_in,
                              void* d_out, int out_size) {
    const int*   ids     = (const int*)  d_in[0];
    const float* embed_W = (const float*)d_in[1];
    const float* n1      = (const float*)d_in[2];
    const float* n2      = (const float*)d_in[3];
    const float* wq      = (const float*)d_in[4];
    const float* wk      = (const float*)d_in[5];
    const float* wv      = (const float*)d_in[6];
    const float* wo      = (const float*)d_in[7];
    const float* rw      = (const float*)d_in[8];
    const float* w1      = (const float*)d_in[9];
    const float* w3      = (const float*)d_in[10];
    const float* w2      = (const float*)d_in[11];
    const float* normf   = (const float*)d_in[12];
    const float* lm      = (const float*)d_in[13];
    const float* tw      = (const float*)d_in[14];
    const float* tb      = (const float*)d_in[15];
    const float* ew      = (const float*)d_in[16];
    const float* eb      = (const float*)d_in[17];
    float* out = (float*)d_out;

    float *p_h, *p_xn, *p_qkv, *p_attn;
    bf16 *p_ah, *p_al;
    bf16 *p_cqh, *p_cql, *p_cwoh, *p_cwol, *p_c1h, *p_c1l, *p_c3h, *p_c3l, *p_c2h, *p_c2l, *p_clh, *p_cll;
    cudaGetSymbolAddress((void**)&p_h,    g_h);
    cudaGetSymbolAddress((void**)&p_xn,   g_xn);
    cudaGetSymbolAddress((void**)&p_qkv,  g_qkv);
    cudaGetSymbolAddress((void**)&p_attn, g_attn);
    cudaGetSymbolAddress((void**)&p_ah,   g_ah);
    cudaGetSymbolAddress((void**)&p_al,   g_al);
    cudaGetSymbolAddress((void**)&p_cqh,  c_qkvh);
    cudaGetSymbolAddress((void**)&p_cql,  c_qkvl);
    cudaGetSymbolAddress((void**)&p_cwoh, c_woh);
    cudaGetSymbolAddress((void**)&p_cwol, c_wol);
    cudaGetSymbolAddress((void**)&p_c1h,  c_w1h);
    cudaGetSymbolAddress((void**)&p_c1l,  c_w1l);
    cudaGetSymbolAddress((void**)&p_c3h,  c_w3h);
    cudaGetSymbolAddress((void**)&p_c3l,  c_w3l);
    cudaGetSymbolAddress((void**)&p_c2h,  c_w2h);
    cudaGetSymbolAddress((void**)&p_c2l,  c_w2l);
    cudaGetSymbolAddress((void**)&p_clh,  c_lmh);
    cudaGetSymbolAddress((void**)&p_cll,  c_lml);

    cudaFuncSetAttribute(k_mma256,  cudaFuncAttributeMaxDynamicSharedMemorySize, SMEM_W);
    cudaFuncSetAttribute(k_moe_mma, cudaFuncAttributeMaxDynamicSharedMemorySize, SMEM_W);
    cudaFuncSetAttribute(k_avm,     cudaFuncAttributeMaxDynamicSharedMemorySize, SMEM_MMA128);
    cudaFuncSetAttribute(k_qk,      cudaFuncAttributeMaxDynamicSharedMemorySize, SMEM_QK);

    k_embed<<<T_, 256>>>(ids, embed_W);
    k_convqkv<<<dim3(1024, 6), 256>>>(wq, wk, wv);
    k_convw5<<<dim3(8192, 5), 256>>>(wo, w1, w3, w2, lm);

    for (int l = 0; l < NL; l++) {
        // attention
        k_rmssplit<<<T_, 256>>>(p_h, n1 + (size_t)l*D_, p_xn, p_ah, p_al);
        k_mma256<<<dim3(16, 6), 256, SMEM_W>>>(p_ah, p_al,
            p_cqh + (size_t)l*D_*QKV_, p_cql + (size_t)l*D_*QKV_, p_qkv, D_, QKV_, QKV_, 0);
        k_ropesplit<<<T_, 192>>>();
        k_qk<<<dim3(4, 4, 64), 256, SMEM_QK>>>();
        k_softmax<<<NCK*NH*CH/8, 256>>>();
        k_avm<<<dim3(4, 1, 64), 256, SMEM_MMA128>>>();
        k_split8<<<1024, 256>>>(p_attn, p_ah, p_al);
        k_mma256<<<dim3(16, 4), 256, SMEM_W>>>(p_ah, p_al,
            p_cwoh + (size_t)l*D_*D_, p_cwol + (size_t)l*D_*D_, p_h, D_, D_, D_, 1);

        // MoE
        k_rmssplit<<<T_, 256>>>(p_h, n2 + (size_t)l*D_, p_xn, p_ah, p_al);
        k_router<<<T_/8, 256>>>(rw + (size_t)l*D_*NE);
        k_aux<<<1, 256>>>();
        k_bucket<<<T_/256, 256>>>();
        k_moe_mma<<<dim3(16, 8, NE), 256, SMEM_W>>>(p_c1h + (size_t)l*NE*D_*F_, p_c1l + (size_t)l*NE*D_*F_, 0);
        k_moe_mma<<<dim3(16, 8, NE), 256, SMEM_W>>>(p_c3h + (size_t)l*NE*D_*F_, p_c3l + (size_t)l*NE*D_*F_, 1);
        k_moe_mma<<<dim3(16, 4, NE), 256, SMEM_W>>>(p_c2h + (size_t)l*NE*F_*D_, p_c2l + (size_t)l*NE*F_*D_, 2);
        k_combine<<<T_, 256>>>();
    }

    // final norm + heads
    k_rmssplit<<<T_, 256>>>(p_h, normf, p_xn, p_ah, p_al);
    k_mma256<<<dim3(16, NV/256), 256, SMEM_W>>>(p_ah, p_al, p_clh, p_cll, out, D_, NV, NV, 0);
    k_task<<<16, 256>>>(tw, tb, out);
    k_mean1<<<16, 256>>>();
    k_mean2<<<4, 256>>>();
    k_eval<<<8, 256>>>(ew, eb, out);
    k_auxw<<<1, 1>>>(out);
}